// round 4
// baseline (speedup 1.0000x reference)
#include <cuda_runtime.h>
#include <cstdint>
#include <math.h>

#define T_STEPS 64
#define BATCH   64
#define HID     1024
#define VOC     32000
#define M2      128
#define TB      4096

typedef unsigned long long ull;

// ---------------- device scratch ----------------
__device__ float g_xpre[(size_t)TB * 3 * HID];   // layer-0 input projections (+b{r,f,h}0)
__device__ float g_h1hist[(size_t)TB * HID];     // h[1] per step (decoder input)
__device__ float g_ha[M2 * HID];                 // h ping
__device__ float g_hb[M2 * HID];                 // h pong
__device__ float g_rh[M2 * HID];                 // r * h
__device__ float g_f[M2 * HID];                  // f gate
__device__ float g_WUr1[HID * HID];              // Wr1 + Ur1
__device__ float g_WUf1[HID * HID];              // Wf1 + Uf1
__device__ float g_brc[HID], g_bfc[HID], g_bhc[HID];
__device__ unsigned g_bar, g_bar2;               // grid barrier counters (self-resetting)

__device__ __forceinline__ float sigm(float x) { return 1.0f / (1.0f + expf(-x)); }

// -------- packed f32x2 primitives --------
__device__ __forceinline__ ull pk2(float x) {
    ull r; asm("mov.b64 %0, {%1, %1};" : "=l"(r) : "f"(x)); return r;
}
__device__ __forceinline__ void fm2(ull& d, ull a, ull b) {
    asm("fma.rn.f32x2 %0, %1, %2, %3;" : "=l"(d) : "l"(a), "l"(b), "l"(d));
}
__device__ __forceinline__ float up2sum(ull v) {
    float lo, hi; asm("mov.b64 {%0, %1}, %2;" : "=f"(lo), "=f"(hi) : "l"(v));
    return lo + hi;
}
__device__ __forceinline__ float2 up2(ull v) {
    float2 f; asm("mov.b64 {%0, %1}, %2;" : "=f"(f.x), "=f"(f.y) : "l"(v)); return f;
}

// ================= persistent recurrence kernel =================
// grid = 128 CTAs (all co-resident), 256 threads.
// CTA -> ms = cta&1 (m half: rows ms*64..+64), ns = cta>>1 (0..63).
// Phases per step:
//  p0: N=32 cols of [r|f] (2048): W = Ur0|Uf0, A = g_ha  -> g_rh (r*ha) / g_f
//  p1: N=16 cols (1024):          W = Uh0,     A = g_rh  -> g_hb = ha + f*(hw-ha)
//  p2: N=32 cols of [r|f]:        W = WUr1|WUf1, A = g_hb -> g_rh (r*hb) / g_f
//  p3: N=16 cols: acc = Wh1@hb + Uh1@rh -> g_ha = hb + f*(hw-hb); stash h1hist

#define REC_CTAS 128
#define BKR 64
#define LDA 68   // padded row (aligned for LDS.128, conflict-free for N=16 two-group reads)

__device__ __forceinline__ void gbar(unsigned nbar) {
    __threadfence();
    __syncthreads();
    if (threadIdx.x == 0) {
        atomicAdd(&g_bar, 1u);
        const unsigned tgt = (unsigned)REC_CTAS * nbar;
        while (*(volatile unsigned*)&g_bar < tgt) __nanosleep(64);
    }
    __syncthreads();
}

// GEMM: acc[i] (k-paired f32x2 partials) += A[m0+tm*TM+i][k] * W[n][k], k=0..1023
// A staged m-major in smem (broadcast reads), W streamed to registers.
template<int N>
__device__ __forceinline__ void pgemm(const float* __restrict__ Ab,  // + m0*HID
                                      const float* __restrict__ Wb,  // + nn0*HID
                                      ull* __restrict__ acc, float* __restrict__ As)
{
    constexpr int TM = N / 4;            // 8 (N=32) or 4 (N=16)
    const int tid = threadIdx.x;
    const int n = tid % N, tm = tid / N;
    const int sm_ = (tid >> 4);          // stage: m = (tid+256r)>>4
    const int sk4 = (tid & 15);          //        k4 = (tid+256r)&15

    float4 st[4];
    auto fetch = [&](int kt) {
        #pragma unroll
        for (int r = 0; r < 4; r++) {
            int m = sm_ + 16 * r;
            st[r] = __ldcg((const float4*)(Ab + (size_t)m * HID + kt + sk4 * 4));
        }
    };
    auto put = [&](int buf) {
        float* B = As + buf * (64 * LDA);
        #pragma unroll
        for (int r = 0; r < 4; r++) {
            int m = sm_ + 16 * r;
            *(float4*)(B + m * LDA + sk4 * 4) = st[r];
        }
    };

    fetch(0); put(0); __syncthreads();

    const float* Wrow = Wb + (size_t)n * HID;
    for (int kt = 0; kt < HID; kt += BKR) {
        const int buf = (kt >> 6) & 1;
        if (kt + BKR < HID) fetch(kt + BKR);

        float4 wv[BKR / 4];
        #pragma unroll
        for (int q = 0; q < BKR / 4; q++)
            wv[q] = __ldg((const float4*)(Wrow + kt + q * 4));

        const float* ap = As + buf * (64 * LDA) + tm * TM * LDA;
        #pragma unroll
        for (int q = 0; q < BKR / 4; q++) {
            ull w0 = ((const ull*)&wv[q])[0];
            ull w1 = ((const ull*)&wv[q])[1];
            #pragma unroll
            for (int i = 0; i < TM; i++) {
                float4 a = *(const float4*)(ap + i * LDA + q * 4);
                fm2(acc[i], ((const ull*)&a)[0], w0);
                fm2(acc[i], ((const ull*)&a)[1], w1);
            }
        }
        if (kt + BKR < HID) { put(buf ^ 1); }
        __syncthreads();
    }
}

__global__ __launch_bounds__(256)
void k_rec(const float* __restrict__ Ur0, const float* __restrict__ Uf0,
           const float* __restrict__ Uh0,
           const float* __restrict__ Wh1, const float* __restrict__ Uh1,
           const float* __restrict__ bur0, const float* __restrict__ buf0,
           const float* __restrict__ buh0)
{
    __shared__ __align__(16) float As[2 * 64 * LDA];

    const int cta = blockIdx.x;
    const int ms = cta & 1, ns = cta >> 1;
    const int m0 = ms * 64;
    const int tid = threadIdx.x;

    unsigned nbar = 0;

    for (int t = 0; t < T_STEPS; t++) {
        // ---------- phase 0 ----------
        {
            constexpr int N = 32, TM = 8;
            const int n0g = ns * N;                 // 0..2047
            const int seg = n0g >> 10, nn0 = n0g & 1023;
            const float* W = seg ? Uf0 : Ur0;
            ull acc[TM] = {};
            pgemm<N>(g_ha + (size_t)m0 * HID, W + (size_t)nn0 * HID, acc, As);
            const int n = tid % N, tm = tid / N;
            const int nn = nn0 + n;
            const float bs = __ldg((seg ? buf0 : bur0) + nn);
            #pragma unroll
            for (int i = 0; i < TM; i++) {
                const int m = m0 + tm * TM + i, b = m & (BATCH - 1);
                const float xadd = __ldg(g_xpre + ((size_t)t * BATCH + b) * (3 * HID) + n0g + n);
                const float g = sigm(up2sum(acc[i]) + bs + xadd);
                const int idx = m * HID + nn;
                if (seg == 0) g_rh[idx] = g * __ldcg(g_ha + idx);
                else          g_f[idx]  = g;
            }
        }
        gbar(++nbar);
        // ---------- phase 1 ----------
        {
            constexpr int N = 16, TM = 4;
            const int nn0 = ns * N;                 // 0..1023
            ull acc[TM] = {};
            pgemm<N>(g_rh + (size_t)m0 * HID, Uh0 + (size_t)nn0 * HID, acc, As);
            const int n = tid % N, tm = tid / N;
            const int nn = nn0 + n;
            const float bs = __ldg(buh0 + nn);
            #pragma unroll
            for (int i = 0; i < TM; i++) {
                const int m = m0 + tm * TM + i, b = m & (BATCH - 1);
                const float xadd = __ldg(g_xpre + ((size_t)t * BATCH + b) * (3 * HID) + 2 * HID + nn);
                const float hw = tanhf(up2sum(acc[i]) + bs + xadd);
                const int idx = m * HID + nn;
                const float h = __ldcg(g_ha + idx), f = __ldcg(g_f + idx);
                g_hb[idx] = h + f * (hw - h);
            }
        }
        gbar(++nbar);
        // ---------- phase 2 ----------
        {
            constexpr int N = 32, TM = 8;
            const int n0g = ns * N;
            const int seg = n0g >> 10, nn0 = n0g & 1023;
            const float* W = seg ? g_WUf1 : g_WUr1;
            ull acc[TM] = {};
            pgemm<N>(g_hb + (size_t)m0 * HID, W + (size_t)nn0 * HID, acc, As);
            const int n = tid % N, tm = tid / N;
            const int nn = nn0 + n;
            const float bs = seg ? g_bfc[nn] : g_brc[nn];
            #pragma unroll
            for (int i = 0; i < TM; i++) {
                const int m = m0 + tm * TM + i;
                const float g = sigm(up2sum(acc[i]) + bs);
                const int idx = m * HID + nn;
                if (seg == 0) g_rh[idx] = g * __ldcg(g_hb + idx);
                else          g_f[idx]  = g;
            }
        }
        gbar(++nbar);
        // ---------- phase 3 ----------
        {
            constexpr int N = 16, TM = 4;
            const int nn0 = ns * N;
            ull acc[TM] = {};
            pgemm<N>(g_hb + (size_t)m0 * HID, Wh1 + (size_t)nn0 * HID, acc, As);
            __syncthreads();
            pgemm<N>(g_rh + (size_t)m0 * HID, Uh1 + (size_t)nn0 * HID, acc, As);
            const int n = tid % N, tm = tid / N;
            const int nn = nn0 + n;
            const float bs = g_bhc[nn];
            #pragma unroll
            for (int i = 0; i < TM; i++) {
                const int m = m0 + tm * TM + i;
                const float hw = tanhf(up2sum(acc[i]) + bs);
                const int idx = m * HID + nn;
                const float h = __ldcg(g_hb + idx), f = __ldcg(g_f + idx);
                const float nh = h + f * (hw - h);
                g_ha[idx] = nh;
                if (m >= BATCH)
                    g_h1hist[((size_t)t * BATCH + (m - BATCH)) * HID + nn] = nh;
            }
        }
        if (t != T_STEPS - 1) gbar(++nbar);
    }

    // drain + reset barrier counters for the next graph replay
    __threadfence();
    __syncthreads();
    if (tid == 0) atomicAdd(&g_bar2, 1u);
    if (cta == 0 && tid == 0) {
        while (*(volatile unsigned*)&g_bar2 < (unsigned)REC_CTAS) __nanosleep(64);
        g_bar = 0; g_bar2 = 0;
        __threadfence();
    }
}

// ---------------- setup kernels ----------------
__global__ void k_hinit(const float* __restrict__ hidden) {
    int i = blockIdx.x * blockDim.x + threadIdx.x;
    if (i < M2 * HID) g_ha[i] = hidden[i];
}
__global__ void k_hout(float* __restrict__ out) {
    int i = blockIdx.x * blockDim.x + threadIdx.x;
    if (i < M2 * HID) out[i] = g_ha[i];
}
__global__ void k_addw(const float* __restrict__ Wr1, const float* __restrict__ Ur1,
                       const float* __restrict__ Wf1, const float* __restrict__ Uf1,
                       const float* __restrict__ br1, const float* __restrict__ bur1,
                       const float* __restrict__ bf1, const float* __restrict__ buf1,
                       const float* __restrict__ bh1, const float* __restrict__ buh1) {
    int i = blockIdx.x * blockDim.x + threadIdx.x;
    if (i < HID * HID) {
        g_WUr1[i] = Wr1[i] + Ur1[i];
        g_WUf1[i] = Wf1[i] + Uf1[i];
    }
    if (i < HID) {
        g_brc[i] = br1[i] + bur1[i];
        g_bfc[i] = bf1[i] + buf1[i];
        g_bhc[i] = bh1[i] + buh1[i];
    }
}

// ---------------- f32x2 GEMM core for pre/dec (N-paired accumulators) ----------------
template<int BM, int BN, int BK, int TM, int TN2, int NT, class AF>
__device__ __forceinline__ void gcore(AF arow, const float* __restrict__ Wb,
                                      int Klen, int ldw,
                                      ull (&acc)[TM][TN2], float* __restrict__ sm)
{
    const int tid = threadIdx.x;
    constexpr int KV  = BK / 4;
    constexpr int AIT = BM * BK / 4 / NT;
    constexpr int WIT = BN * BK / 4 / NT;

    float4 ar[AIT], wr[WIT];
    auto fetch = [&](int kt) {
        #pragma unroll
        for (int r = 0; r < AIT; r++) {
            int idx = r * NT + tid; int m = idx / KV, kk = (idx % KV) * 4;
            ar[r] = *(const float4*)(arow(m) + kt + kk);
        }
        #pragma unroll
        for (int r = 0; r < WIT; r++) {
            int idx = r * NT + tid; int n = idx / KV, kk = (idx % KV) * 4;
            wr[r] = *(const float4*)(Wb + (size_t)n * ldw + kt + kk);
        }
    };
    auto stos = [&](int buf) {
        float* Asm = sm + buf * BK * BM;
        float* Wsm = sm + 2 * BK * BM + buf * BK * BN;
        #pragma unroll
        for (int r = 0; r < AIT; r++) {
            int idx = r * NT + tid; int m = idx / KV, kk = (idx % KV) * 4;
            Asm[(kk+0)*BM+m]=ar[r].x; Asm[(kk+1)*BM+m]=ar[r].y;
            Asm[(kk+2)*BM+m]=ar[r].z; Asm[(kk+3)*BM+m]=ar[r].w;
        }
        #pragma unroll
        for (int r = 0; r < WIT; r++) {
            int idx = r * NT + tid; int n = idx / KV, kk = (idx % KV) * 4;
            Wsm[(kk+0)*BN+n]=wr[r].x; Wsm[(kk+1)*BN+n]=wr[r].y;
            Wsm[(kk+2)*BN+n]=wr[r].z; Wsm[(kk+3)*BN+n]=wr[r].w;
        }
    };

    constexpr int NG = BN / (2 * TN2);
    const int tn = tid % NG, tm = tid / NG;

    fetch(0); stos(0); __syncthreads();

    for (int kt = 0; kt < Klen; kt += BK) {
        const int buf = (kt / BK) & 1;
        if (kt + BK < Klen) fetch(kt + BK);
        const float* Asm = sm + buf * BK * BM + tm * TM;
        const float* Wsm = sm + 2 * BK * BM + buf * BK * BN + tn * (2 * TN2);
        #pragma unroll
        for (int k = 0; k < BK; k++) {
            float av[TM];
            #pragma unroll
            for (int q = 0; q < TM/4; q++)
                *(float4*)(av + 4*q) = *(const float4*)(Asm + k * BM + 4*q);
            ull wv[TN2];
            #pragma unroll
            for (int q = 0; q < TN2/2; q++) {
                ulonglong2 t2 = *(const ulonglong2*)(Wsm + k * BN + 4*q);
                wv[2*q] = t2.x; wv[2*q+1] = t2.y;
            }
            #pragma unroll
            for (int i = 0; i < TM; i++) {
                ull a2 = pk2(av[i]);
                #pragma unroll
                for (int j = 0; j < TN2; j++) fm2(acc[i][j], wv[j], a2);
            }
        }
        if (kt + BK < Klen) stos(buf ^ 1);
        __syncthreads();
    }
}

// ---------------- precompute: xpre = gather(emb) @ [Wr0|Wf0|Wh0].T + bias ----------------
__global__ __launch_bounds__(256)
void k_pre(const int* __restrict__ tokens, const float* __restrict__ emb,
           const float* __restrict__ W0, const float* __restrict__ W1, const float* __restrict__ W2,
           const float* __restrict__ b0, const float* __restrict__ b1, const float* __restrict__ b2)
{
    constexpr int BM = 128, BN = 128, BK = 16, TM = 8, TN2 = 4, NT = 256;
    __shared__ __align__(16) float sm[2*BK*BM + 2*BK*BN];
    __shared__ int stok[BM];
    const int m0 = blockIdx.y * BM, n0 = blockIdx.x * BN;
    const int seg = n0 >> 10, nn0 = n0 & 1023;
    const float* W    = (seg == 0) ? W0 : (seg == 1) ? W1 : W2;
    const float* bias = (seg == 0) ? b0 : (seg == 1) ? b1 : b2;

    if (threadIdx.x < BM) stok[threadIdx.x] = tokens[m0 + threadIdx.x];
    __syncthreads();

    ull acc[TM][TN2] = {};
    auto arow = [&](int m) { return emb + (size_t)stok[m] * HID; };
    gcore<BM,BN,BK,TM,TN2,NT>(arow, W + (size_t)nn0 * HID, HID, HID, acc, sm);

    constexpr int NG = BN / (2*TN2);
    const int tn = threadIdx.x % NG, tm = threadIdx.x / NG;
    #pragma unroll
    for (int i = 0; i < TM; i++) {
        const int m = m0 + tm*TM + i;
        const int nl = tn * (2*TN2);
        float* dst = g_xpre + (size_t)m * (3*HID) + n0 + nl;
        #pragma unroll
        for (int q = 0; q < TN2/2; q++) {
            union { ull u[2]; float4 f; } cv;
            cv.u[0] = acc[i][2*q]; cv.u[1] = acc[i][2*q+1];
            float4 bb = *(const float4*)(bias + nn0 + nl + 4*q);
            cv.f.x += bb.x; cv.f.y += bb.y; cv.f.z += bb.z; cv.f.w += bb.w;
            ((float4*)dst)[q] = cv.f;
        }
    }
}

// ---------------- decoder: logits = h1hist @ Wdec.T + bdec ----------------
__global__ __launch_bounds__(128)
void k_dec(const float* __restrict__ Wdec, const float* __restrict__ bdec,
           float* __restrict__ out)
{
    constexpr int BM = 128, BN = 128, BK = 16, TM = 8, TN2 = 8, NT = 128;
    __shared__ __align__(16) float sm[2*BK*BM + 2*BK*BN];
    const int m0 = blockIdx.y * BM, n0 = blockIdx.x * BN;

    ull acc[TM][TN2] = {};
    auto arow = [&](int m) { return g_h1hist + (size_t)(m0 + m) * HID; };
    gcore<BM,BN,BK,TM,TN2,NT>(arow, Wdec + (size_t)n0 * HID, HID, HID, acc, sm);

    constexpr int NG = BN / (2*TN2);   // 8
    const int tn = threadIdx.x % NG, tm = threadIdx.x / NG;
    #pragma unroll
    for (int i = 0; i < TM; i++) {
        const int m = m0 + tm*TM + i;
        const int n = n0 + tn * (2*TN2);
        float* dst = out + (size_t)m * VOC + n;
        #pragma unroll
        for (int q = 0; q < TN2/2; q++) {
            union { ull u[2]; float4 f; } cv;
            cv.u[0] = acc[i][2*q]; cv.u[1] = acc[i][2*q+1];
            float4 bb = *(const float4*)(bdec + n + 4*q);
            cv.f.x += bb.x; cv.f.y += bb.y; cv.f.z += bb.z; cv.f.w += bb.w;
            ((float4*)dst)[q] = cv.f;
        }
    }
}

// ---------------- launch ----------------
extern "C" void kernel_launch(void* const* d_in, const int* in_sizes, int n_in,
                              void* d_out, int out_size)
{
    const int*   tokens = (const int*)  d_in[0];
    const float* hidden = (const float*)d_in[1];
    const float* emb    = (const float*)d_in[2];
    const float* Wr     = (const float*)d_in[3];
    const float* br     = (const float*)d_in[4];
    const float* Wf     = (const float*)d_in[5];
    const float* bf     = (const float*)d_in[6];
    const float* Wh     = (const float*)d_in[7];
    const float* bh     = (const float*)d_in[8];
    const float* Ur     = (const float*)d_in[9];
    const float* bur    = (const float*)d_in[10];
    const float* Ufw    = (const float*)d_in[11];
    const float* bufw   = (const float*)d_in[12];
    const float* Uh     = (const float*)d_in[13];
    const float* buh    = (const float*)d_in[14];
    const float* Wdec   = (const float*)d_in[15];
    const float* bdec   = (const float*)d_in[16];
    float* out = (float*)d_out;

    const size_t HH = (size_t)HID * HID;

    k_hinit<<<(M2*HID + 1023) / 1024, 1024>>>(hidden);
    k_addw<<<(HID*HID + 255) / 256, 256>>>(Wr + HH, Ur + HH, Wf + HH, Ufw + HH,
                                           br + HID, bur + HID, bf + HID, bufw + HID,
                                           bh + HID, buh + HID);
    k_pre<<<dim3(3*HID/128, TB/128), 256>>>(tokens, emb, Wr, Wf, Wh, br, bf, bh);

    k_rec<<<REC_CTAS, 256>>>(Ur, Ufw, Uh, Wh + HH, Uh + HH, bur, bufw, buh);

    k_dec<<<dim3(VOC/128, TB/128), 128>>>(Wdec, bdec, out);

    const long long logits_elems = (long long)TB * VOC;
    if ((long long)out_size >= logits_elems + (long long)M2 * HID)
        k_hout<<<(M2*HID + 1023) / 1024, 1024>>>(out + logits_elems);
}

// round 5
// speedup vs baseline: 1.0002x; 1.0002x over previous
#include <cuda_runtime.h>
#include <cstdint>
#include <math.h>

#define T_STEPS 64
#define BATCH   64
#define HID     1024
#define VOC     32000
#define M2      128
#define TB      4096

typedef unsigned long long ull;

// ---------------- device scratch ----------------
__device__ float g_xpre[(size_t)TB * 3 * HID];   // layer-0 input projections (+b{r,f,h}0)
__device__ float g_h1hist[(size_t)TB * HID];     // h[1] per step (decoder input)
__device__ float g_ha[M2 * HID];                 // h ping
__device__ float g_hb[M2 * HID];                 // h pong
__device__ float g_rh[M2 * HID];                 // r * h
__device__ float g_f[M2 * HID];                  // f gate
__device__ float g_WUr1[HID * HID];              // Wr1 + Ur1
__device__ float g_WUf1[HID * HID];              // Wf1 + Uf1
__device__ float g_brc[HID], g_bfc[HID], g_bhc[HID];
__device__ unsigned g_bar, g_bar2;               // grid barrier counters (self-resetting)

__device__ __forceinline__ float sigm(float x) { return 1.0f / (1.0f + expf(-x)); }

// -------- packed f32x2 primitives --------
__device__ __forceinline__ ull pk2(float x) {
    ull r; asm("mov.b64 %0, {%1, %1};" : "=l"(r) : "f"(x)); return r;
}
__device__ __forceinline__ void fm2(ull& d, ull a, ull b) {
    asm("fma.rn.f32x2 %0, %1, %2, %3;" : "=l"(d) : "l"(a), "l"(b), "l"(d));
}
__device__ __forceinline__ float up2sum(ull v) {
    float lo, hi; asm("mov.b64 {%0, %1}, %2;" : "=f"(lo), "=f"(hi) : "l"(v));
    return lo + hi;
}
__device__ __forceinline__ float2 up2(ull v) {
    float2 f; asm("mov.b64 {%0, %1}, %2;" : "=f"(f.x), "=f"(f.y) : "l"(v)); return f;
}

// ================= persistent recurrence kernel =================
// grid = 128 CTAs (all co-resident), 256 threads.
// CTA -> ms = cta&1 (m half: rows ms*64..+64), ns = cta>>1 (0..63).
// Phases per step:
//  p0: N=32 cols of [r|f] (2048): W = Ur0|Uf0, A = g_ha  -> g_rh (r*ha) / g_f
//  p1: N=16 cols (1024):          W = Uh0,     A = g_rh  -> g_hb = ha + f*(hw-ha)
//  p2: N=32 cols of [r|f]:        W = WUr1|WUf1, A = g_hb -> g_rh (r*hb) / g_f
//  p3: N=16 cols: acc = Wh1@hb + Uh1@rh -> g_ha = hb + f*(hw-hb); stash h1hist

#define REC_CTAS 128
#define BKR 64
#define LDA 68   // padded row (aligned for LDS.128, conflict-free for N=16 two-group reads)

__device__ __forceinline__ void gbar(unsigned nbar) {
    __threadfence();
    __syncthreads();
    if (threadIdx.x == 0) {
        atomicAdd(&g_bar, 1u);
        const unsigned tgt = (unsigned)REC_CTAS * nbar;
        while (*(volatile unsigned*)&g_bar < tgt) __nanosleep(64);
    }
    __syncthreads();
}

// GEMM: acc[i] (k-paired f32x2 partials) += A[m0+tm*TM+i][k] * W[n][k], k=0..1023
// A staged m-major in smem (broadcast reads), W streamed to registers.
template<int N>
__device__ __forceinline__ void pgemm(const float* __restrict__ Ab,  // + m0*HID
                                      const float* __restrict__ Wb,  // + nn0*HID
                                      ull* __restrict__ acc, float* __restrict__ As)
{
    constexpr int TM = N / 4;            // 8 (N=32) or 4 (N=16)
    const int tid = threadIdx.x;
    const int n = tid % N, tm = tid / N;
    const int sm_ = (tid >> 4);          // stage: m = (tid+256r)>>4
    const int sk4 = (tid & 15);          //        k4 = (tid+256r)&15

    float4 st[4];
    auto fetch = [&](int kt) {
        #pragma unroll
        for (int r = 0; r < 4; r++) {
            int m = sm_ + 16 * r;
            st[r] = __ldcg((const float4*)(Ab + (size_t)m * HID + kt + sk4 * 4));
        }
    };
    auto put = [&](int buf) {
        float* B = As + buf * (64 * LDA);
        #pragma unroll
        for (int r = 0; r < 4; r++) {
            int m = sm_ + 16 * r;
            *(float4*)(B + m * LDA + sk4 * 4) = st[r];
        }
    };

    fetch(0); put(0); __syncthreads();

    const float* Wrow = Wb + (size_t)n * HID;
    for (int kt = 0; kt < HID; kt += BKR) {
        const int buf = (kt >> 6) & 1;
        if (kt + BKR < HID) fetch(kt + BKR);

        float4 wv[BKR / 4];
        #pragma unroll
        for (int q = 0; q < BKR / 4; q++)
            wv[q] = __ldg((const float4*)(Wrow + kt + q * 4));

        const float* ap = As + buf * (64 * LDA) + tm * TM * LDA;
        #pragma unroll
        for (int q = 0; q < BKR / 4; q++) {
            ull w0 = ((const ull*)&wv[q])[0];
            ull w1 = ((const ull*)&wv[q])[1];
            #pragma unroll
            for (int i = 0; i < TM; i++) {
                float4 a = *(const float4*)(ap + i * LDA + q * 4);
                fm2(acc[i], ((const ull*)&a)[0], w0);
                fm2(acc[i], ((const ull*)&a)[1], w1);
            }
        }
        if (kt + BKR < HID) { put(buf ^ 1); }
        __syncthreads();
    }
}

__global__ __launch_bounds__(256)
void k_rec(const float* __restrict__ Ur0, const float* __restrict__ Uf0,
           const float* __restrict__ Uh0,
           const float* __restrict__ Wh1, const float* __restrict__ Uh1,
           const float* __restrict__ bur0, const float* __restrict__ buf0,
           const float* __restrict__ buh0)
{
    __shared__ __align__(16) float As[2 * 64 * LDA];

    const int cta = blockIdx.x;
    const int ms = cta & 1, ns = cta >> 1;
    const int m0 = ms * 64;
    const int tid = threadIdx.x;

    unsigned nbar = 0;

    for (int t = 0; t < T_STEPS; t++) {
        // ---------- phase 0 ----------
        {
            constexpr int N = 32, TM = 8;
            const int n0g = ns * N;                 // 0..2047
            const int seg = n0g >> 10, nn0 = n0g & 1023;
            const float* W = seg ? Uf0 : Ur0;
            ull acc[TM] = {};
            pgemm<N>(g_ha + (size_t)m0 * HID, W + (size_t)nn0 * HID, acc, As);
            const int n = tid % N, tm = tid / N;
            const int nn = nn0 + n;
            const float bs = __ldg((seg ? buf0 : bur0) + nn);
            #pragma unroll
            for (int i = 0; i < TM; i++) {
                const int m = m0 + tm * TM + i, b = m & (BATCH - 1);
                const float xadd = __ldg(g_xpre + ((size_t)t * BATCH + b) * (3 * HID) + n0g + n);
                const float g = sigm(up2sum(acc[i]) + bs + xadd);
                const int idx = m * HID + nn;
                if (seg == 0) g_rh[idx] = g * __ldcg(g_ha + idx);
                else          g_f[idx]  = g;
            }
        }
        gbar(++nbar);
        // ---------- phase 1 ----------
        {
            constexpr int N = 16, TM = 4;
            const int nn0 = ns * N;                 // 0..1023
            ull acc[TM] = {};
            pgemm<N>(g_rh + (size_t)m0 * HID, Uh0 + (size_t)nn0 * HID, acc, As);
            const int n = tid % N, tm = tid / N;
            const int nn = nn0 + n;
            const float bs = __ldg(buh0 + nn);
            #pragma unroll
            for (int i = 0; i < TM; i++) {
                const int m = m0 + tm * TM + i, b = m & (BATCH - 1);
                const float xadd = __ldg(g_xpre + ((size_t)t * BATCH + b) * (3 * HID) + 2 * HID + nn);
                const float hw = tanhf(up2sum(acc[i]) + bs + xadd);
                const int idx = m * HID + nn;
                const float h = __ldcg(g_ha + idx), f = __ldcg(g_f + idx);
                g_hb[idx] = h + f * (hw - h);
            }
        }
        gbar(++nbar);
        // ---------- phase 2 ----------
        {
            constexpr int N = 32, TM = 8;
            const int n0g = ns * N;
            const int seg = n0g >> 10, nn0 = n0g & 1023;
            const float* W = seg ? g_WUf1 : g_WUr1;
            ull acc[TM] = {};
            pgemm<N>(g_hb + (size_t)m0 * HID, W + (size_t)nn0 * HID, acc, As);
            const int n = tid % N, tm = tid / N;
            const int nn = nn0 + n;
            const float bs = seg ? g_bfc[nn] : g_brc[nn];
            #pragma unroll
            for (int i = 0; i < TM; i++) {
                const int m = m0 + tm * TM + i;
                const float g = sigm(up2sum(acc[i]) + bs);
                const int idx = m * HID + nn;
                if (seg == 0) g_rh[idx] = g * __ldcg(g_hb + idx);
                else          g_f[idx]  = g;
            }
        }
        gbar(++nbar);
        // ---------- phase 3 ----------
        {
            constexpr int N = 16, TM = 4;
            const int nn0 = ns * N;
            ull acc[TM] = {};
            pgemm<N>(g_hb + (size_t)m0 * HID, Wh1 + (size_t)nn0 * HID, acc, As);
            __syncthreads();
            pgemm<N>(g_rh + (size_t)m0 * HID, Uh1 + (size_t)nn0 * HID, acc, As);
            const int n = tid % N, tm = tid / N;
            const int nn = nn0 + n;
            const float bs = g_bhc[nn];
            #pragma unroll
            for (int i = 0; i < TM; i++) {
                const int m = m0 + tm * TM + i;
                const float hw = tanhf(up2sum(acc[i]) + bs);
                const int idx = m * HID + nn;
                const float h = __ldcg(g_hb + idx), f = __ldcg(g_f + idx);
                const float nh = h + f * (hw - h);
                g_ha[idx] = nh;
                if (m >= BATCH)
                    g_h1hist[((size_t)t * BATCH + (m - BATCH)) * HID + nn] = nh;
            }
        }
        if (t != T_STEPS - 1) gbar(++nbar);
    }

    // drain + reset barrier counters for the next graph replay
    __threadfence();
    __syncthreads();
    if (tid == 0) atomicAdd(&g_bar2, 1u);
    if (cta == 0 && tid == 0) {
        while (*(volatile unsigned*)&g_bar2 < (unsigned)REC_CTAS) __nanosleep(64);
        g_bar = 0; g_bar2 = 0;
        __threadfence();
    }
}

// ---------------- setup kernels ----------------
__global__ void k_hinit(const float* __restrict__ hidden) {
    int i = blockIdx.x * blockDim.x + threadIdx.x;
    if (i < M2 * HID) g_ha[i] = hidden[i];
}
__global__ void k_hout(float* __restrict__ out) {
    int i = blockIdx.x * blockDim.x + threadIdx.x;
    if (i < M2 * HID) out[i] = g_ha[i];
}
__global__ void k_addw(const float* __restrict__ Wr1, const float* __restrict__ Ur1,
                       const float* __restrict__ Wf1, const float* __restrict__ Uf1,
                       const float* __restrict__ br1, const float* __restrict__ bur1,
                       const float* __restrict__ bf1, const float* __restrict__ buf1,
                       const float* __restrict__ bh1, const float* __restrict__ buh1) {
    int i = blockIdx.x * blockDim.x + threadIdx.x;
    if (i < HID * HID) {
        g_WUr1[i] = Wr1[i] + Ur1[i];
        g_WUf1[i] = Wf1[i] + Uf1[i];
    }
    if (i < HID) {
        g_brc[i] = br1[i] + bur1[i];
        g_bfc[i] = bf1[i] + buf1[i];
        g_bhc[i] = bh1[i] + buh1[i];
    }
}

// ---------------- f32x2 GEMM core for pre/dec (N-paired accumulators) ----------------
template<int BM, int BN, int BK, int TM, int TN2, int NT, class AF>
__device__ __forceinline__ void gcore(AF arow, const float* __restrict__ Wb,
                                      int Klen, int ldw,
                                      ull (&acc)[TM][TN2], float* __restrict__ sm)
{
    const int tid = threadIdx.x;
    constexpr int KV  = BK / 4;
    constexpr int AIT = BM * BK / 4 / NT;
    constexpr int WIT = BN * BK / 4 / NT;

    float4 ar[AIT], wr[WIT];
    auto fetch = [&](int kt) {
        #pragma unroll
        for (int r = 0; r < AIT; r++) {
            int idx = r * NT + tid; int m = idx / KV, kk = (idx % KV) * 4;
            ar[r] = *(const float4*)(arow(m) + kt + kk);
        }
        #pragma unroll
        for (int r = 0; r < WIT; r++) {
            int idx = r * NT + tid; int n = idx / KV, kk = (idx % KV) * 4;
            wr[r] = *(const float4*)(Wb + (size_t)n * ldw + kt + kk);
        }
    };
    auto stos = [&](int buf) {
        float* Asm = sm + buf * BK * BM;
        float* Wsm = sm + 2 * BK * BM + buf * BK * BN;
        #pragma unroll
        for (int r = 0; r < AIT; r++) {
            int idx = r * NT + tid; int m = idx / KV, kk = (idx % KV) * 4;
            Asm[(kk+0)*BM+m]=ar[r].x; Asm[(kk+1)*BM+m]=ar[r].y;
            Asm[(kk+2)*BM+m]=ar[r].z; Asm[(kk+3)*BM+m]=ar[r].w;
        }
        #pragma unroll
        for (int r = 0; r < WIT; r++) {
            int idx = r * NT + tid; int n = idx / KV, kk = (idx % KV) * 4;
            Wsm[(kk+0)*BN+n]=wr[r].x; Wsm[(kk+1)*BN+n]=wr[r].y;
            Wsm[(kk+2)*BN+n]=wr[r].z; Wsm[(kk+3)*BN+n]=wr[r].w;
        }
    };

    constexpr int NG = BN / (2 * TN2);
    const int tn = tid % NG, tm = tid / NG;

    fetch(0); stos(0); __syncthreads();

    for (int kt = 0; kt < Klen; kt += BK) {
        const int buf = (kt / BK) & 1;
        if (kt + BK < Klen) fetch(kt + BK);
        const float* Asm = sm + buf * BK * BM + tm * TM;
        const float* Wsm = sm + 2 * BK * BM + buf * BK * BN + tn * (2 * TN2);
        #pragma unroll
        for (int k = 0; k < BK; k++) {
            float av[TM];
            #pragma unroll
            for (int q = 0; q < TM/4; q++)
                *(float4*)(av + 4*q) = *(const float4*)(Asm + k * BM + 4*q);
            ull wv[TN2];
            #pragma unroll
            for (int q = 0; q < TN2/2; q++) {
                ulonglong2 t2 = *(const ulonglong2*)(Wsm + k * BN + 4*q);
                wv[2*q] = t2.x; wv[2*q+1] = t2.y;
            }
            #pragma unroll
            for (int i = 0; i < TM; i++) {
                ull a2 = pk2(av[i]);
                #pragma unroll
                for (int j = 0; j < TN2; j++) fm2(acc[i][j], wv[j], a2);
            }
        }
        if (kt + BK < Klen) stos(buf ^ 1);
        __syncthreads();
    }
}

// ---------------- precompute: xpre = gather(emb) @ [Wr0|Wf0|Wh0].T + bias ----------------
__global__ __launch_bounds__(256)
void k_pre(const int* __restrict__ tokens, const float* __restrict__ emb,
           const float* __restrict__ W0, const float* __restrict__ W1, const float* __restrict__ W2,
           const float* __restrict__ b0, const float* __restrict__ b1, const float* __restrict__ b2)
{
    constexpr int BM = 128, BN = 128, BK = 16, TM = 8, TN2 = 4, NT = 256;
    __shared__ __align__(16) float sm[2*BK*BM + 2*BK*BN];
    __shared__ int stok[BM];
    const int m0 = blockIdx.y * BM, n0 = blockIdx.x * BN;
    const int seg = n0 >> 10, nn0 = n0 & 1023;
    const float* W    = (seg == 0) ? W0 : (seg == 1) ? W1 : W2;
    const float* bias = (seg == 0) ? b0 : (seg == 1) ? b1 : b2;

    if (threadIdx.x < BM) stok[threadIdx.x] = tokens[m0 + threadIdx.x];
    __syncthreads();

    ull acc[TM][TN2] = {};
    auto arow = [&](int m) { return emb + (size_t)stok[m] * HID; };
    gcore<BM,BN,BK,TM,TN2,NT>(arow, W + (size_t)nn0 * HID, HID, HID, acc, sm);

    constexpr int NG = BN / (2*TN2);
    const int tn = threadIdx.x % NG, tm = threadIdx.x / NG;
    #pragma unroll
    for (int i = 0; i < TM; i++) {
        const int m = m0 + tm*TM + i;
        const int nl = tn * (2*TN2);
        float* dst = g_xpre + (size_t)m * (3*HID) + n0 + nl;
        #pragma unroll
        for (int q = 0; q < TN2/2; q++) {
            union { ull u[2]; float4 f; } cv;
            cv.u[0] = acc[i][2*q]; cv.u[1] = acc[i][2*q+1];
            float4 bb = *(const float4*)(bias + nn0 + nl + 4*q);
            cv.f.x += bb.x; cv.f.y += bb.y; cv.f.z += bb.z; cv.f.w += bb.w;
            ((float4*)dst)[q] = cv.f;
        }
    }
}

// ---------------- decoder: logits = h1hist @ Wdec.T + bdec ----------------
__global__ __launch_bounds__(128)
void k_dec(const float* __restrict__ Wdec, const float* __restrict__ bdec,
           float* __restrict__ out)
{
    constexpr int BM = 128, BN = 128, BK = 16, TM = 8, TN2 = 8, NT = 128;
    __shared__ __align__(16) float sm[2*BK*BM + 2*BK*BN];
    const int m0 = blockIdx.y * BM, n0 = blockIdx.x * BN;

    ull acc[TM][TN2] = {};
    auto arow = [&](int m) { return g_h1hist + (size_t)(m0 + m) * HID; };
    gcore<BM,BN,BK,TM,TN2,NT>(arow, Wdec + (size_t)n0 * HID, HID, HID, acc, sm);

    constexpr int NG = BN / (2*TN2);   // 8
    const int tn = threadIdx.x % NG, tm = threadIdx.x / NG;
    #pragma unroll
    for (int i = 0; i < TM; i++) {
        const int m = m0 + tm*TM + i;
        const int n = n0 + tn * (2*TN2);
        float* dst = out + (size_t)m * VOC + n;
        #pragma unroll
        for (int q = 0; q < TN2/2; q++) {
            union { ull u[2]; float4 f; } cv;
            cv.u[0] = acc[i][2*q]; cv.u[1] = acc[i][2*q+1];
            float4 bb = *(const float4*)(bdec + n + 4*q);
            cv.f.x += bb.x; cv.f.y += bb.y; cv.f.z += bb.z; cv.f.w += bb.w;
            ((float4*)dst)[q] = cv.f;
        }
    }
}

// ---------------- launch ----------------
extern "C" void kernel_launch(void* const* d_in, const int* in_sizes, int n_in,
                              void* d_out, int out_size)
{
    const int*   tokens = (const int*)  d_in[0];
    const float* hidden = (const float*)d_in[1];
    const float* emb    = (const float*)d_in[2];
    const float* Wr     = (const float*)d_in[3];
    const float* br     = (const float*)d_in[4];
    const float* Wf     = (const float*)d_in[5];
    const float* bf     = (const float*)d_in[6];
    const float* Wh     = (const float*)d_in[7];
    const float* bh     = (const float*)d_in[8];
    const float* Ur     = (const float*)d_in[9];
    const float* bur    = (const float*)d_in[10];
    const float* Ufw    = (const float*)d_in[11];
    const float* bufw   = (const float*)d_in[12];
    const float* Uh     = (const float*)d_in[13];
    const float* buh    = (const float*)d_in[14];
    const float* Wdec   = (const float*)d_in[15];
    const float* bdec   = (const float*)d_in[16];
    float* out = (float*)d_out;

    const size_t HH = (size_t)HID * HID;

    k_hinit<<<(M2*HID + 1023) / 1024, 1024>>>(hidden);
    k_addw<<<(HID*HID + 255) / 256, 256>>>(Wr + HH, Ur + HH, Wf + HH, Ufw + HH,
                                           br + HID, bur + HID, bf + HID, bufw + HID,
                                           bh + HID, buh + HID);
    k_pre<<<dim3(3*HID/128, TB/128), 256>>>(tokens, emb, Wr, Wf, Wh, br, bf, bh);

    k_rec<<<REC_CTAS, 256>>>(Ur, Ufw, Uh, Wh + HH, Uh + HH, bur, bufw, buh);

    k_dec<<<dim3(VOC/128, TB/128), 128>>>(Wdec, bdec, out);

    const long long logits_elems = (long long)TB * VOC;
    if ((long long)out_size >= logits_elems + (long long)M2 * HID)
        k_hout<<<(M2*HID + 1023) / 1024, 1024>>>(out + logits_elems);
}

// round 6
// speedup vs baseline: 2.3596x; 2.3591x over previous
#include <cuda_runtime.h>
#include <cstdint>
#include <math.h>

#define T_STEPS 64
#define BATCH   64
#define HID     1024
#define VOC     32000
#define M2      128
#define TB      4096

typedef unsigned long long ull;

// ---------------- device scratch ----------------
__device__ float g_xpre[(size_t)TB * 3 * HID];   // layer-0 input projections (+b{r,f,h}0)
__device__ float g_h1hist[(size_t)TB * HID];     // h[1] per step (decoder input)
__device__ float g_ha[M2 * HID];                 // h ping
__device__ float g_hb[M2 * HID];                 // h pong
__device__ float g_rh[M2 * HID];                 // r * h
__device__ float g_f[M2 * HID];                  // f gate
__device__ float g_WUr1[HID * HID];              // Wr1 + Ur1
__device__ float g_WUf1[HID * HID];              // Wf1 + Uf1
__device__ float g_brc[HID], g_bfc[HID], g_bhc[HID];
__device__ float g_part[2 * 1024 * 1024];        // split-K partials (8MB)
__device__ unsigned g_bar, g_bar2;               // grid barrier counters (self-resetting)

__device__ __forceinline__ float sigm(float x) { return 1.0f / (1.0f + expf(-x)); }

// -------- packed f32x2 primitives --------
__device__ __forceinline__ ull pk2(float x) {
    ull r; asm("mov.b64 %0, {%1, %1};" : "=l"(r) : "f"(x)); return r;
}
__device__ __forceinline__ void fm2(ull& d, ull a, ull b) {
    asm("fma.rn.f32x2 %0, %1, %2, %3;" : "=l"(d) : "l"(a), "l"(b), "l"(d));
}
__device__ __forceinline__ float up2sum(ull v) {
    float lo, hi; asm("mov.b64 {%0, %1}, %2;" : "=f"(lo), "=f"(hi) : "l"(v));
    return lo + hi;
}

// ================= K-paired f32x2 GEMM core =================
// Tile: M=128 x N=128, 256 threads, TM=8 x TN=8 per thread.
// acc[i][j] = k-paired partial of C[tm*8+i][tn+16j]; horizontal-sum at the end.
// A rows at Ab + m*HID (already offset to k-slice start); W rows at Wb + n*HID.
// Smem: double-buffered, rows k-contiguous with LDK pad. No splat movs needed:
// both fm2 operands are 8B k-pairs straight out of LDS.128.
#define BKT 16
#define LDK 20
#define SMF (2 * 2 * 128 * LDK)   // 10240 floats = 40KB

__device__ __forceinline__ void gkp(const float* __restrict__ Ab,
                                    const float* __restrict__ Wb,
                                    int klen, ull (&acc)[8][8],
                                    float* __restrict__ sm)
{
    const int tid = threadIdx.x;
    const int lr = tid >> 2;              // loader row 0..63 (and +64)
    const int lk = (tid & 3) * 4;         // loader k4 offset
    const int tn = tid & 15, tm = tid >> 4;

    float4 a0, a1, w0, w1;
    auto fetch = [&](int kt) {
        a0 = __ldcg((const float4*)(Ab + (size_t)lr        * HID + kt + lk));
        a1 = __ldcg((const float4*)(Ab + (size_t)(lr + 64) * HID + kt + lk));
        w0 = __ldg ((const float4*)(Wb + (size_t)lr        * HID + kt + lk));
        w1 = __ldg ((const float4*)(Wb + (size_t)(lr + 64) * HID + kt + lk));
    };
    auto put = [&](int buf) {
        float* As = sm + buf * (2 * 128 * LDK);
        float* Ws = As + 128 * LDK;
        *(float4*)(As + lr * LDK + lk) = a0;
        *(float4*)(As + (lr + 64) * LDK + lk) = a1;
        *(float4*)(Ws + lr * LDK + lk) = w0;
        *(float4*)(Ws + (lr + 64) * LDK + lk) = w1;
    };

    fetch(0); put(0); __syncthreads();
    const int nt = klen / BKT;
    for (int kt = 0; kt < nt; kt++) {
        if (kt + 1 < nt) fetch((kt + 1) * BKT);
        const float* As = sm + (kt & 1) * (2 * 128 * LDK) + tm * 8 * LDK;
        const float* Ws = sm + (kt & 1) * (2 * 128 * LDK) + 128 * LDK + tn * LDK;
        #pragma unroll
        for (int g = 0; g < BKT / 4; g++) {
            ull a[16];
            #pragma unroll
            for (int i = 0; i < 8; i++) {
                float4 v = *(const float4*)(As + i * LDK + g * 4);
                a[2*i]   = ((const ull*)&v)[0];
                a[2*i+1] = ((const ull*)&v)[1];
            }
            #pragma unroll
            for (int j = 0; j < 8; j++) {
                float4 v = *(const float4*)(Ws + j * 16 * LDK + g * 4);
                ull wlo = ((const ull*)&v)[0], whi = ((const ull*)&v)[1];
                #pragma unroll
                for (int i = 0; i < 8; i++) {
                    fm2(acc[i][j], a[2*i],   wlo);
                    fm2(acc[i][j], a[2*i+1], whi);
                }
            }
        }
        if (kt + 1 < nt) put((kt + 1) & 1);
        __syncthreads();
    }
}

// ================= persistent recurrence kernel =================
#define REC_CTAS 128

__device__ __forceinline__ void gbar(unsigned nbar) {
    __threadfence();
    __syncthreads();
    if (threadIdx.x == 0) {
        atomicAdd(&g_bar, 1u);
        const unsigned tgt = (unsigned)REC_CTAS * nbar;
        while (*(volatile unsigned*)&g_bar < tgt) __nanosleep(32);
    }
    __syncthreads();
}

__device__ __forceinline__ void stpart(ull (&acc)[8][8], int ks, int ntile, int Ntot) {
    const int tn = threadIdx.x & 15, tm = threadIdx.x >> 4;
    #pragma unroll
    for (int i = 0; i < 8; i++) {
        const int m = tm * 8 + i;
        float* row = g_part + ((size_t)ks * M2 + m) * Ntot + ntile * 128;
        #pragma unroll
        for (int j = 0; j < 8; j++)
            row[tn + 16 * j] = up2sum(acc[i][j]);
    }
}

__global__ __launch_bounds__(256)
void k_rec(const float* __restrict__ Ur0, const float* __restrict__ Uf0,
           const float* __restrict__ Uh0,
           const float* __restrict__ Wh1, const float* __restrict__ Uh1,
           const float* __restrict__ bur0, const float* __restrict__ buf0,
           const float* __restrict__ buh0)
{
    __shared__ __align__(16) float sm[SMF];
    const int cta = blockIdx.x, tid = threadIdx.x;
    unsigned nbar = 0;

    for (int t = 0; t < T_STEPS; t++) {
        // ---------- p0 GEMM: [r|f]0 = h @ [Ur0|Uf0].T (split-K 8) ----------
        {
            const int ntile = cta & 15, ks = cta >> 4, koff = ks * 128;
            const float* W = ((ntile < 8) ? Ur0 : Uf0) + (size_t)((ntile & 7) * 128) * HID;
            ull acc[8][8] = {};
            gkp(g_ha + koff, W + koff, 128, acc, sm);
            stpart(acc, ks, ntile, 2048);
        }
        gbar(++nbar);
        // ---------- p0 reduce + sigmoid ----------
        {
            const int m = tid >> 1, b = m & (BATCH - 1);
            const int n = cta * 16 + (tid & 1) * 8;
            float4 s0 = {0,0,0,0}, s1 = {0,0,0,0};
            #pragma unroll
            for (int ks = 0; ks < 8; ks++) {
                const float* p = g_part + ((size_t)ks * M2 + m) * 2048 + n;
                float4 v0 = __ldcg((const float4*)p), v1 = __ldcg((const float4*)(p + 4));
                s0.x += v0.x; s0.y += v0.y; s0.z += v0.z; s0.w += v0.w;
                s1.x += v1.x; s1.y += v1.y; s1.z += v1.z; s1.w += v1.w;
            }
            const int seg = n >> 10, nn = n & 1023;
            const float* bias = seg ? buf0 : bur0;
            float v[8] = {s0.x, s0.y, s0.z, s0.w, s1.x, s1.y, s1.z, s1.w};
            #pragma unroll
            for (int c = 0; c < 8; c++) {
                const float xadd = __ldg(g_xpre + ((size_t)t * BATCH + b) * (3 * HID) + n + c);
                const float g = sigm(v[c] + __ldg(bias + nn + c) + xadd);
                const int idx = m * HID + nn + c;
                if (seg == 0) g_rh[idx] = g * __ldcg(g_ha + idx);
                else          g_f[idx]  = g;
            }
        }
        gbar(++nbar);
        // ---------- p1 GEMM: hw0 = rh @ Uh0.T (split-K 16) ----------
        {
            const int ntile = cta & 7, ks = cta >> 3, koff = ks * 64;
            ull acc[8][8] = {};
            gkp(g_rh + koff, Uh0 + (size_t)(ntile * 128) * HID + koff, 64, acc, sm);
            stpart(acc, ks, ntile, 1024);
        }
        gbar(++nbar);
        // ---------- p1 reduce + tanh + h update ----------
        {
            const int m = tid >> 1, b = m & (BATCH - 1);
            const int n = cta * 8 + (tid & 1) * 4;
            float4 s = {0,0,0,0};
            #pragma unroll
            for (int ks = 0; ks < 16; ks++) {
                float4 v = __ldcg((const float4*)(g_part + ((size_t)ks * M2 + m) * 1024 + n));
                s.x += v.x; s.y += v.y; s.z += v.z; s.w += v.w;
            }
            float v[4] = {s.x, s.y, s.z, s.w};
            #pragma unroll
            for (int c = 0; c < 4; c++) {
                const float xadd = __ldg(g_xpre + ((size_t)t * BATCH + b) * (3 * HID) + 2 * HID + n + c);
                const float hw = tanhf(v[c] + __ldg(buh0 + n + c) + xadd);
                const int idx = m * HID + n + c;
                const float h = __ldcg(g_ha + idx), f = __ldcg(g_f + idx);
                g_hb[idx] = h + f * (hw - h);
            }
        }
        gbar(++nbar);
        // ---------- p2 GEMM: [r|f]1 = hb @ [WUr1|WUf1].T (split-K 8) ----------
        {
            const int ntile = cta & 15, ks = cta >> 4, koff = ks * 128;
            const float* W = ((ntile < 8) ? g_WUr1 : g_WUf1) + (size_t)((ntile & 7) * 128) * HID;
            ull acc[8][8] = {};
            gkp(g_hb + koff, W + koff, 128, acc, sm);
            stpart(acc, ks, ntile, 2048);
        }
        gbar(++nbar);
        // ---------- p2 reduce + sigmoid ----------
        {
            const int m = tid >> 1;
            const int n = cta * 16 + (tid & 1) * 8;
            float4 s0 = {0,0,0,0}, s1 = {0,0,0,0};
            #pragma unroll
            for (int ks = 0; ks < 8; ks++) {
                const float* p = g_part + ((size_t)ks * M2 + m) * 2048 + n;
                float4 v0 = __ldcg((const float4*)p), v1 = __ldcg((const float4*)(p + 4));
                s0.x += v0.x; s0.y += v0.y; s0.z += v0.z; s0.w += v0.w;
                s1.x += v1.x; s1.y += v1.y; s1.z += v1.z; s1.w += v1.w;
            }
            const int seg = n >> 10, nn = n & 1023;
            float v[8] = {s0.x, s0.y, s0.z, s0.w, s1.x, s1.y, s1.z, s1.w};
            #pragma unroll
            for (int c = 0; c < 8; c++) {
                const int idx = m * HID + nn + c;
                if (seg == 0) {
                    const float r = sigm(v[c] + g_brc[nn + c]);
                    g_rh[idx] = r * __ldcg(g_hb + idx);
                } else {
                    g_f[idx] = sigm(v[c] + g_bfc[nn + c]);
                }
            }
        }
        gbar(++nbar);
        // ---------- p3 GEMM: hw1 = hb @ Wh1.T + rh @ Uh1.T (virtual K=2048, split 16) ----------
        {
            const int ntile = cta & 7, ks = cta >> 3;
            ull acc[8][8] = {};
            if (ks < 8) {
                const int koff = ks * 128;
                gkp(g_hb + koff, Wh1 + (size_t)(ntile * 128) * HID + koff, 128, acc, sm);
            } else {
                const int koff = (ks - 8) * 128;
                gkp(g_rh + koff, Uh1 + (size_t)(ntile * 128) * HID + koff, 128, acc, sm);
            }
            stpart(acc, ks, ntile, 1024);
        }
        gbar(++nbar);
        // ---------- p3 reduce + tanh + h update + h1hist ----------
        {
            const int m = tid >> 1;
            const int n = cta * 8 + (tid & 1) * 4;
            float4 s = {0,0,0,0};
            #pragma unroll
            for (int ks = 0; ks < 16; ks++) {
                float4 v = __ldcg((const float4*)(g_part + ((size_t)ks * M2 + m) * 1024 + n));
                s.x += v.x; s.y += v.y; s.z += v.z; s.w += v.w;
            }
            float v[4] = {s.x, s.y, s.z, s.w};
            #pragma unroll
            for (int c = 0; c < 4; c++) {
                const float hw = tanhf(v[c] + g_bhc[n + c]);
                const int idx = m * HID + n + c;
                const float h = __ldcg(g_hb + idx), f = __ldcg(g_f + idx);
                const float nh = h + f * (hw - h);
                g_ha[idx] = nh;
                if (m >= BATCH)
                    g_h1hist[((size_t)t * BATCH + (m - BATCH)) * HID + n + c] = nh;
            }
        }
        if (t != T_STEPS - 1) gbar(++nbar);
    }

    // drain + reset barrier counters for the next graph replay
    __threadfence();
    __syncthreads();
    if (tid == 0) atomicAdd(&g_bar2, 1u);
    if (cta == 0 && tid == 0) {
        while (*(volatile unsigned*)&g_bar2 < (unsigned)REC_CTAS) __nanosleep(32);
        g_bar = 0; g_bar2 = 0;
        __threadfence();
    }
}

// ---------------- setup kernels ----------------
__global__ void k_hinit(const float* __restrict__ hidden) {
    int i = blockIdx.x * blockDim.x + threadIdx.x;
    if (i < M2 * HID) g_ha[i] = hidden[i];
}
__global__ void k_hout(float* __restrict__ out) {
    int i = blockIdx.x * blockDim.x + threadIdx.x;
    if (i < M2 * HID) out[i] = g_ha[i];
}
__global__ void k_addw(const float* __restrict__ Wr1, const float* __restrict__ Ur1,
                       const float* __restrict__ Wf1, const float* __restrict__ Uf1,
                       const float* __restrict__ br1, const float* __restrict__ bur1,
                       const float* __restrict__ bf1, const float* __restrict__ buf1,
                       const float* __restrict__ bh1, const float* __restrict__ buh1) {
    int i = blockIdx.x * blockDim.x + threadIdx.x;
    if (i < HID * HID) {
        g_WUr1[i] = Wr1[i] + Ur1[i];
        g_WUf1[i] = Wf1[i] + Uf1[i];
    }
    if (i < HID) {
        g_brc[i] = br1[i] + bur1[i];
        g_bfc[i] = bf1[i] + buf1[i];
        g_bhc[i] = bh1[i] + buh1[i];
    }
}

// ---------------- decoder: logits = h1hist @ Wdec.T + bdec (K-paired core) ----------------
__global__ __launch_bounds__(256)
void k_dec(const float* __restrict__ Wdec, const float* __restrict__ bdec,
           float* __restrict__ out)
{
    __shared__ __align__(16) float sm[SMF];
    const int n0 = blockIdx.x * 128, m0 = blockIdx.y * 128;

    ull acc[8][8] = {};
    gkp(g_h1hist + (size_t)m0 * HID, Wdec + (size_t)n0 * HID, HID, acc, sm);

    const int tn = threadIdx.x & 15, tm = threadIdx.x >> 4;
    #pragma unroll
    for (int i = 0; i < 8; i++) {
        const int m = m0 + tm * 8 + i;
        #pragma unroll
        for (int j = 0; j < 8; j++) {
            const int n = n0 + tn + 16 * j;
            out[(size_t)m * VOC + n] = up2sum(acc[i][j]) + __ldg(bdec + n);
        }
    }
}

// ---------------- precompute: xpre = gather(emb) @ [Wr0|Wf0|Wh0].T + bias ----------------
// (N-paired gcore retained from round 5 — this kernel is ~2% of runtime)
template<int BM, int BN, int BK, int TM, int TN2, int NT, class AF>
__device__ __forceinline__ void gcore(AF arow, const float* __restrict__ Wb,
                                      int Klen, int ldw,
                                      ull (&acc)[TM][TN2], float* __restrict__ sm)
{
    const int tid = threadIdx.x;
    constexpr int KV  = BK / 4;
    constexpr int AIT = BM * BK / 4 / NT;
    constexpr int WIT = BN * BK / 4 / NT;

    float4 ar[AIT], wr[WIT];
    auto fetch = [&](int kt) {
        #pragma unroll
        for (int r = 0; r < AIT; r++) {
            int idx = r * NT + tid; int m = idx / KV, kk = (idx % KV) * 4;
            ar[r] = *(const float4*)(arow(m) + kt + kk);
        }
        #pragma unroll
        for (int r = 0; r < WIT; r++) {
            int idx = r * NT + tid; int n = idx / KV, kk = (idx % KV) * 4;
            wr[r] = *(const float4*)(Wb + (size_t)n * ldw + kt + kk);
        }
    };
    auto stos = [&](int buf) {
        float* Asm = sm + buf * BK * BM;
        float* Wsm = sm + 2 * BK * BM + buf * BK * BN;
        #pragma unroll
        for (int r = 0; r < AIT; r++) {
            int idx = r * NT + tid; int m = idx / KV, kk = (idx % KV) * 4;
            Asm[(kk+0)*BM+m]=ar[r].x; Asm[(kk+1)*BM+m]=ar[r].y;
            Asm[(kk+2)*BM+m]=ar[r].z; Asm[(kk+3)*BM+m]=ar[r].w;
        }
        #pragma unroll
        for (int r = 0; r < WIT; r++) {
            int idx = r * NT + tid; int n = idx / KV, kk = (idx % KV) * 4;
            Wsm[(kk+0)*BN+n]=wr[r].x; Wsm[(kk+1)*BN+n]=wr[r].y;
            Wsm[(kk+2)*BN+n]=wr[r].z; Wsm[(kk+3)*BN+n]=wr[r].w;
        }
    };

    constexpr int NG = BN / (2 * TN2);
    const int tn = tid % NG, tm = tid / NG;

    fetch(0); stos(0); __syncthreads();

    for (int kt = 0; kt < Klen; kt += BK) {
        const int buf = (kt / BK) & 1;
        if (kt + BK < Klen) fetch(kt + BK);
        const float* Asm = sm + buf * BK * BM + tm * TM;
        const float* Wsm = sm + 2 * BK * BM + buf * BK * BN + tn * (2 * TN2);
        #pragma unroll
        for (int k = 0; k < BK; k++) {
            float av[TM];
            #pragma unroll
            for (int q = 0; q < TM/4; q++)
                *(float4*)(av + 4*q) = *(const float4*)(Asm + k * BM + 4*q);
            ull wv[TN2];
            #pragma unroll
            for (int q = 0; q < TN2/2; q++) {
                ulonglong2 t2 = *(const ulonglong2*)(Wsm + k * BN + 4*q);
                wv[2*q] = t2.x; wv[2*q+1] = t2.y;
            }
            #pragma unroll
            for (int i = 0; i < TM; i++) {
                ull a2 = pk2(av[i]);
                #pragma unroll
                for (int j = 0; j < TN2; j++) fm2(acc[i][j], wv[j], a2);
            }
        }
        if (kt + BK < Klen) stos(buf ^ 1);
        __syncthreads();
    }
}

__global__ __launch_bounds__(256)
void k_pre(const int* __restrict__ tokens, const float* __restrict__ emb,
           const float* __restrict__ W0, const float* __restrict__ W1, const float* __restrict__ W2,
           const float* __restrict__ b0, const float* __restrict__ b1, const float* __restrict__ b2)
{
    constexpr int BM = 128, BN = 128, BK = 16, TM = 8, TN2 = 4, NT = 256;
    __shared__ __align__(16) float sm[2*BK*BM + 2*BK*BN];
    __shared__ int stok[BM];
    const int m0 = blockIdx.y * BM, n0 = blockIdx.x * BN;
    const int seg = n0 >> 10, nn0 = n0 & 1023;
    const float* W    = (seg == 0) ? W0 : (seg == 1) ? W1 : W2;
    const float* bias = (seg == 0) ? b0 : (seg == 1) ? b1 : b2;

    if (threadIdx.x < BM) stok[threadIdx.x] = tokens[m0 + threadIdx.x];
    __syncthreads();

    ull acc[TM][TN2] = {};
    auto arow = [&](int m) { return emb + (size_t)stok[m] * HID; };
    gcore<BM,BN,BK,TM,TN2,NT>(arow, W + (size_t)nn0 * HID, HID, HID, acc, sm);

    constexpr int NG = BN / (2*TN2);
    const int tn = threadIdx.x % NG, tm = threadIdx.x / NG;
    #pragma unroll
    for (int i = 0; i < TM; i++) {
        const int m = m0 + tm*TM + i;
        const int nl = tn * (2*TN2);
        float* dst = g_xpre + (size_t)m * (3*HID) + n0 + nl;
        #pragma unroll
        for (int q = 0; q < TN2/2; q++) {
            union { ull u[2]; float4 f; } cv;
            cv.u[0] = acc[i][2*q]; cv.u[1] = acc[i][2*q+1];
            float4 bb = *(const float4*)(bias + nn0 + nl + 4*q);
            cv.f.x += bb.x; cv.f.y += bb.y; cv.f.z += bb.z; cv.f.w += bb.w;
            ((float4*)dst)[q] = cv.f;
        }
    }
}

// ---------------- launch ----------------
extern "C" void kernel_launch(void* const* d_in, const int* in_sizes, int n_in,
                              void* d_out, int out_size)
{
    const int*   tokens = (const int*)  d_in[0];
    const float* hidden = (const float*)d_in[1];
    const float* emb    = (const float*)d_in[2];
    const float* Wr     = (const float*)d_in[3];
    const float* br     = (const float*)d_in[4];
    const float* Wf     = (const float*)d_in[5];
    const float* bf     = (const float*)d_in[6];
    const float* Wh     = (const float*)d_in[7];
    const float* bh     = (const float*)d_in[8];
    const float* Ur     = (const float*)d_in[9];
    const float* bur    = (const float*)d_in[10];
    const float* Ufw    = (const float*)d_in[11];
    const float* bufw   = (const float*)d_in[12];
    const float* Uh     = (const float*)d_in[13];
    const float* buh    = (const float*)d_in[14];
    const float* Wdec   = (const float*)d_in[15];
    const float* bdec   = (const float*)d_in[16];
    float* out = (float*)d_out;

    const size_t HH = (size_t)HID * HID;

    k_hinit<<<(M2*HID + 1023) / 1024, 1024>>>(hidden);
    k_addw<<<(HID*HID + 255) / 256, 256>>>(Wr + HH, Ur + HH, Wf + HH, Ufw + HH,
                                           br + HID, bur + HID, bf + HID, bufw + HID,
                                           bh + HID, buh + HID);
    k_pre<<<dim3(3*HID/128, TB/128), 256>>>(tokens, emb, Wr, Wf, Wh, br, bf, bh);

    k_rec<<<REC_CTAS, 256>>>(Ur, Ufw, Uh, Wh + HH, Uh + HH, bur, bufw, buh);

    k_dec<<<dim3(VOC/128, TB/128), 256>>>(Wdec, bdec, out);

    const long long logits_elems = (long long)TB * VOC;
    if ((long long)out_size >= logits_elems + (long long)M2 * HID)
        k_hout<<<(M2*HID + 1023) / 1024, 1024>>>(out + logits_elems);
}

// round 8
// speedup vs baseline: 3.4482x; 1.4614x over previous
#include <cuda_runtime.h>
#include <cuda_bf16.h>
#include <cstdint>
#include <math.h>

#define T_STEPS 64
#define BATCH   64
#define HID     1024
#define VOC     32000
#define M2      128
#define TB      4096

typedef unsigned long long ull;

// ---------------- device scratch ----------------
__device__ float g_xpre[(size_t)TB * 3 * HID];   // layer-0 input projections (+b{r,f,h}0)
__device__ float g_ha[M2 * HID];                 // h ping
__device__ float g_hb[M2 * HID];                 // h pong
__device__ float g_rh[M2 * HID];                 // r * h
__device__ float g_f[M2 * HID];                  // f gate
__device__ float g_WUr1[HID * HID];              // Wr1 + Ur1
__device__ float g_WUf1[HID * HID];              // Wf1 + Uf1
__device__ float g_brc[HID], g_bfc[HID], g_bhc[HID];
__device__ float g_part[2 * 1024 * 1024];        // split-K partials (8MB)
__device__ unsigned g_bar, g_bar2;               // grid barrier counters (self-resetting)
// bf16 split operands for the tensor-core decoder
__device__ __align__(16) __nv_bfloat16 g_h1H[(size_t)TB * HID];
__device__ __align__(16) __nv_bfloat16 g_h1L[(size_t)TB * HID];
__device__ __align__(16) __nv_bfloat16 g_WdH[(size_t)VOC * HID];
__device__ __align__(16) __nv_bfloat16 g_WdL[(size_t)VOC * HID];

__device__ __forceinline__ float sigm(float x) { return 1.0f / (1.0f + expf(-x)); }

// -------- packed f32x2 primitives --------
__device__ __forceinline__ ull pk2(float x) {
    ull r; asm("mov.b64 %0, {%1, %1};" : "=l"(r) : "f"(x)); return r;
}
__device__ __forceinline__ void fm2(ull& d, ull a, ull b) {
    asm("fma.rn.f32x2 %0, %1, %2, %3;" : "=l"(d) : "l"(a), "l"(b), "l"(d));
}
__device__ __forceinline__ float up2sum(ull v) {
    float lo, hi; asm("mov.b64 {%0, %1}, %2;" : "=f"(lo), "=f"(hi) : "l"(v));
    return lo + hi;
}

// ================= K-paired f32x2 GEMM core (recurrence) =================
#define BKT 16
#define LDK 20
#define SMF (2 * 2 * 128 * LDK)

__device__ __forceinline__ void gkp(const float* __restrict__ Ab,
                                    const float* __restrict__ Wb,
                                    int klen, ull (&acc)[8][8],
                                    float* __restrict__ sm)
{
    const int tid = threadIdx.x;
    const int lr = tid >> 2;
    const int lk = (tid & 3) * 4;
    const int tn = tid & 15, tm = tid >> 4;

    float4 a0, a1, w0, w1;
    auto fetch = [&](int kt) {
        a0 = __ldcg((const float4*)(Ab + (size_t)lr        * HID + kt + lk));
        a1 = __ldcg((const float4*)(Ab + (size_t)(lr + 64) * HID + kt + lk));
        w0 = __ldg ((const float4*)(Wb + (size_t)lr        * HID + kt + lk));
        w1 = __ldg ((const float4*)(Wb + (size_t)(lr + 64) * HID + kt + lk));
    };
    auto put = [&](int buf) {
        float* As = sm + buf * (2 * 128 * LDK);
        float* Ws = As + 128 * LDK;
        *(float4*)(As + lr * LDK + lk) = a0;
        *(float4*)(As + (lr + 64) * LDK + lk) = a1;
        *(float4*)(Ws + lr * LDK + lk) = w0;
        *(float4*)(Ws + (lr + 64) * LDK + lk) = w1;
    };

    fetch(0); put(0); __syncthreads();
    const int nt = klen / BKT;
    for (int kt = 0; kt < nt; kt++) {
        if (kt + 1 < nt) fetch((kt + 1) * BKT);
        const float* As = sm + (kt & 1) * (2 * 128 * LDK) + tm * 8 * LDK;
        const float* Ws = sm + (kt & 1) * (2 * 128 * LDK) + 128 * LDK + tn * LDK;
        #pragma unroll
        for (int g = 0; g < BKT / 4; g++) {
            ull a[16];
            #pragma unroll
            for (int i = 0; i < 8; i++) {
                float4 v = *(const float4*)(As + i * LDK + g * 4);
                a[2*i]   = ((const ull*)&v)[0];
                a[2*i+1] = ((const ull*)&v)[1];
            }
            #pragma unroll
            for (int j = 0; j < 8; j++) {
                float4 v = *(const float4*)(Ws + j * 16 * LDK + g * 4);
                ull wlo = ((const ull*)&v)[0], whi = ((const ull*)&v)[1];
                #pragma unroll
                for (int i = 0; i < 8; i++) {
                    fm2(acc[i][j], a[2*i],   wlo);
                    fm2(acc[i][j], a[2*i+1], whi);
                }
            }
        }
        if (kt + 1 < nt) put((kt + 1) & 1);
        __syncthreads();
    }
}

// ================= persistent recurrence kernel =================
#define REC_CTAS 128

__device__ __forceinline__ void gbar(unsigned nbar) {
    __threadfence();
    __syncthreads();
    if (threadIdx.x == 0) {
        atomicAdd(&g_bar, 1u);
        const unsigned tgt = (unsigned)REC_CTAS * nbar;
        while (*(volatile unsigned*)&g_bar < tgt) __nanosleep(32);
    }
    __syncthreads();
}

__device__ __forceinline__ void stpart(ull (&acc)[8][8], int ks, int ntile, int Ntot) {
    const int tn = threadIdx.x & 15, tm = threadIdx.x >> 4;
    #pragma unroll
    for (int i = 0; i < 8; i++) {
        const int m = tm * 8 + i;
        float* row = g_part + ((size_t)ks * M2 + m) * Ntot + ntile * 128;
        #pragma unroll
        for (int j = 0; j < 8; j++)
            row[tn + 16 * j] = up2sum(acc[i][j]);
    }
}

__global__ __launch_bounds__(256)
void k_rec(const float* __restrict__ Ur0, const float* __restrict__ Uf0,
           const float* __restrict__ Uh0,
           const float* __restrict__ Wh1, const float* __restrict__ Uh1,
           const float* __restrict__ bur0, const float* __restrict__ buf0,
           const float* __restrict__ buh0)
{
    __shared__ __align__(16) float sm[SMF];
    const int cta = blockIdx.x, tid = threadIdx.x;
    unsigned nbar = 0;

    for (int t = 0; t < T_STEPS; t++) {
        // ---------- p0 GEMM: [r|f]0 = h @ [Ur0|Uf0].T (split-K 8) ----------
        {
            const int ntile = cta & 15, ks = cta >> 4, koff = ks * 128;
            const float* W = ((ntile < 8) ? Ur0 : Uf0) + (size_t)((ntile & 7) * 128) * HID;
            ull acc[8][8] = {};
            gkp(g_ha + koff, W + koff, 128, acc, sm);
            stpart(acc, ks, ntile, 2048);
        }
        gbar(++nbar);
        // ---------- p0 reduce + sigmoid ----------
        {
            const int m = tid >> 1, b = m & (BATCH - 1);
            const int n = cta * 16 + (tid & 1) * 8;
            float4 s0 = {0,0,0,0}, s1 = {0,0,0,0};
            #pragma unroll
            for (int ks = 0; ks < 8; ks++) {
                const float* p = g_part + ((size_t)ks * M2 + m) * 2048 + n;
                float4 v0 = __ldcg((const float4*)p), v1 = __ldcg((const float4*)(p + 4));
                s0.x += v0.x; s0.y += v0.y; s0.z += v0.z; s0.w += v0.w;
                s1.x += v1.x; s1.y += v1.y; s1.z += v1.z; s1.w += v1.w;
            }
            const int seg = n >> 10, nn = n & 1023;
            const float* bias = seg ? buf0 : bur0;
            float v[8] = {s0.x, s0.y, s0.z, s0.w, s1.x, s1.y, s1.z, s1.w};
            #pragma unroll
            for (int c = 0; c < 8; c++) {
                const float xadd = __ldg(g_xpre + ((size_t)t * BATCH + b) * (3 * HID) + n + c);
                const float g = sigm(v[c] + __ldg(bias + nn + c) + xadd);
                const int idx = m * HID + nn + c;
                if (seg == 0) g_rh[idx] = g * __ldcg(g_ha + idx);
                else          g_f[idx]  = g;
            }
        }
        gbar(++nbar);
        // ---------- p1 GEMM: hw0 = rh @ Uh0.T (split-K 16) ----------
        {
            const int ntile = cta & 7, ks = cta >> 3, koff = ks * 64;
            ull acc[8][8] = {};
            gkp(g_rh + koff, Uh0 + (size_t)(ntile * 128) * HID + koff, 64, acc, sm);
            stpart(acc, ks, ntile, 1024);
        }
        gbar(++nbar);
        // ---------- p1 reduce + tanh + h update ----------
        {
            const int m = tid >> 1, b = m & (BATCH - 1);
            const int n = cta * 8 + (tid & 1) * 4;
            float4 s = {0,0,0,0};
            #pragma unroll
            for (int ks = 0; ks < 16; ks++) {
                float4 v = __ldcg((const float4*)(g_part + ((size_t)ks * M2 + m) * 1024 + n));
                s.x += v.x; s.y += v.y; s.z += v.z; s.w += v.w;
            }
            float v[4] = {s.x, s.y, s.z, s.w};
            #pragma unroll
            for (int c = 0; c < 4; c++) {
                const float xadd = __ldg(g_xpre + ((size_t)t * BATCH + b) * (3 * HID) + 2 * HID + n + c);
                const float hw = tanhf(v[c] + __ldg(buh0 + n + c) + xadd);
                const int idx = m * HID + n + c;
                const float h = __ldcg(g_ha + idx), f = __ldcg(g_f + idx);
                g_hb[idx] = h + f * (hw - h);
            }
        }
        gbar(++nbar);
        // ---------- p2 GEMM: [r|f]1 = hb @ [WUr1|WUf1].T (split-K 8) ----------
        {
            const int ntile = cta & 15, ks = cta >> 4, koff = ks * 128;
            const float* W = ((ntile < 8) ? g_WUr1 : g_WUf1) + (size_t)((ntile & 7) * 128) * HID;
            ull acc[8][8] = {};
            gkp(g_hb + koff, W + koff, 128, acc, sm);
            stpart(acc, ks, ntile, 2048);
        }
        gbar(++nbar);
        // ---------- p2 reduce + sigmoid ----------
        {
            const int m = tid >> 1;
            const int n = cta * 16 + (tid & 1) * 8;
            float4 s0 = {0,0,0,0}, s1 = {0,0,0,0};
            #pragma unroll
            for (int ks = 0; ks < 8; ks++) {
                const float* p = g_part + ((size_t)ks * M2 + m) * 2048 + n;
                float4 v0 = __ldcg((const float4*)p), v1 = __ldcg((const float4*)(p + 4));
                s0.x += v0.x; s0.y += v0.y; s0.z += v0.z; s0.w += v0.w;
                s1.x += v1.x; s1.y += v1.y; s1.z += v1.z; s1.w += v1.w;
            }
            const int seg = n >> 10, nn = n & 1023;
            float v[8] = {s0.x, s0.y, s0.z, s0.w, s1.x, s1.y, s1.z, s1.w};
            #pragma unroll
            for (int c = 0; c < 8; c++) {
                const int idx = m * HID + nn + c;
                if (seg == 0) {
                    const float r = sigm(v[c] + g_brc[nn + c]);
                    g_rh[idx] = r * __ldcg(g_hb + idx);
                } else {
                    g_f[idx] = sigm(v[c] + g_bfc[nn + c]);
                }
            }
        }
        gbar(++nbar);
        // ---------- p3 GEMM: hw1 = hb @ Wh1.T + rh @ Uh1.T (virtual K=2048, split 16) ----------
        {
            const int ntile = cta & 7, ks = cta >> 3;
            ull acc[8][8] = {};
            if (ks < 8) {
                const int koff = ks * 128;
                gkp(g_hb + koff, Wh1 + (size_t)(ntile * 128) * HID + koff, 128, acc, sm);
            } else {
                const int koff = (ks - 8) * 128;
                gkp(g_rh + koff, Uh1 + (size_t)(ntile * 128) * HID + koff, 128, acc, sm);
            }
            stpart(acc, ks, ntile, 1024);
        }
        gbar(++nbar);
        // ---------- p3 reduce + tanh + h update + h1 bf16 hi/lo stash ----------
        {
            const int m = tid >> 1;
            const int n = cta * 8 + (tid & 1) * 4;
            float4 s = {0,0,0,0};
            #pragma unroll
            for (int ks = 0; ks < 16; ks++) {
                float4 v = __ldcg((const float4*)(g_part + ((size_t)ks * M2 + m) * 1024 + n));
                s.x += v.x; s.y += v.y; s.z += v.z; s.w += v.w;
            }
            float v[4] = {s.x, s.y, s.z, s.w};
            #pragma unroll
            for (int c = 0; c < 4; c++) {
                const float hw = tanhf(v[c] + g_bhc[n + c]);
                const int idx = m * HID + n + c;
                const float h = __ldcg(g_hb + idx), f = __ldcg(g_f + idx);
                const float nh = h + f * (hw - h);
                g_ha[idx] = nh;
                if (m >= BATCH) {
                    const size_t o = ((size_t)t * BATCH + (m - BATCH)) * HID + n + c;
                    const __nv_bfloat16 hh = __float2bfloat16(nh);
                    g_h1H[o] = hh;
                    g_h1L[o] = __float2bfloat16(nh - __bfloat162float(hh));
                }
            }
        }
        if (t != T_STEPS - 1) gbar(++nbar);
    }

    __threadfence();
    __syncthreads();
    if (tid == 0) atomicAdd(&g_bar2, 1u);
    if (cta == 0 && tid == 0) {
        while (*(volatile unsigned*)&g_bar2 < (unsigned)REC_CTAS) __nanosleep(32);
        g_bar = 0; g_bar2 = 0;
        __threadfence();
    }
}

// ---------------- setup kernels ----------------
__global__ void k_hinit(const float* __restrict__ hidden) {
    int i = blockIdx.x * blockDim.x + threadIdx.x;
    if (i < M2 * HID) g_ha[i] = hidden[i];
}
__global__ void k_hout(float* __restrict__ out) {
    int i = blockIdx.x * blockDim.x + threadIdx.x;
    if (i < M2 * HID) out[i] = g_ha[i];
}
__global__ void k_addw(const float* __restrict__ Wr1, const float* __restrict__ Ur1,
                       const float* __restrict__ Wf1, const float* __restrict__ Uf1,
                       const float* __restrict__ br1, const float* __restrict__ bur1,
                       const float* __restrict__ bf1, const float* __restrict__ buf1,
                       const float* __restrict__ bh1, const float* __restrict__ buh1) {
    int i = blockIdx.x * blockDim.x + threadIdx.x;
    if (i < HID * HID) {
        g_WUr1[i] = Wr1[i] + Ur1[i];
        g_WUf1[i] = Wf1[i] + Uf1[i];
    }
    if (i < HID) {
        g_brc[i] = br1[i] + bur1[i];
        g_bfc[i] = bf1[i] + buf1[i];
        g_bhc[i] = bh1[i] + buh1[i];
    }
}

// ---------------- Wdec -> bf16 hi/lo split ----------------
__global__ void k_splitW(const float* __restrict__ W) {
    const size_t n4 = (size_t)VOC * HID / 4;
    for (size_t j = (size_t)blockIdx.x * blockDim.x + threadIdx.x; j < n4;
         j += (size_t)gridDim.x * blockDim.x) {
        float4 v = __ldg((const float4*)W + j);
        __nv_bfloat16 h0 = __float2bfloat16(v.x), h1 = __float2bfloat16(v.y);
        __nv_bfloat16 h2 = __float2bfloat16(v.z), h3 = __float2bfloat16(v.w);
        ushort4 hv = { __bfloat16_as_ushort(h0), __bfloat16_as_ushort(h1),
                       __bfloat16_as_ushort(h2), __bfloat16_as_ushort(h3) };
        ((ushort4*)g_WdH)[j] = hv;
        __nv_bfloat16 l0 = __float2bfloat16(v.x - __bfloat162float(h0));
        __nv_bfloat16 l1 = __float2bfloat16(v.y - __bfloat162float(h1));
        __nv_bfloat16 l2 = __float2bfloat16(v.z - __bfloat162float(h2));
        __nv_bfloat16 l3 = __float2bfloat16(v.w - __bfloat162float(h3));
        ushort4 lv = { __bfloat16_as_ushort(l0), __bfloat16_as_ushort(l1),
                       __bfloat16_as_ushort(l2), __bfloat16_as_ushort(l3) };
        ((ushort4*)g_WdL)[j] = lv;
    }
}

// ================= mma.sync bf16x3 decoder (base-target tensor cores) =================
__device__ __forceinline__ uint32_t s2u(const void* p) {
    uint32_t a;
    asm("{ .reg .u64 t; cvta.to.shared.u64 t, %1; cvt.u32.u64 %0, t; }" : "=r"(a) : "l"(p));
    return a;
}
__device__ __forceinline__ void cpa16(uint32_t dst, const void* src) {
    asm volatile("cp.async.cg.shared.global [%0], [%1], 16;" :: "r"(dst), "l"(src) : "memory");
}
#define SW128(o) ((o) ^ (((o) >> 3) & 0x70))

__device__ __forceinline__ void ldm4(uint32_t* r, uint32_t addr) {
    asm volatile("ldmatrix.sync.aligned.m8n8.x4.shared.b16 {%0,%1,%2,%3}, [%4];"
                 : "=r"(r[0]), "=r"(r[1]), "=r"(r[2]), "=r"(r[3]) : "r"(addr));
}
__device__ __forceinline__ void mma16816(float* d, const uint32_t* a, const uint32_t* b) {
    asm volatile(
        "mma.sync.aligned.m16n8k16.row.col.f32.bf16.bf16.f32 "
        "{%0,%1,%2,%3},{%4,%5,%6,%7},{%8,%9},{%0,%1,%2,%3};"
        : "+f"(d[0]), "+f"(d[1]), "+f"(d[2]), "+f"(d[3])
        : "r"(a[0]), "r"(a[1]), "r"(a[2]), "r"(a[3]), "r"(b[0]), "r"(b[1]));
}

#define DEC_SMEM (2 * 65536)

__global__ __launch_bounds__(256)
void k_dec_mma(const float* __restrict__ bdec, float* __restrict__ out)
{
    extern __shared__ __align__(128) char dsm[];
    const uint32_t sb = s2u(dsm);
    const int tid = threadIdx.x, lane = tid & 31, wid = tid >> 5;
    const int wm = wid >> 2, wn = wid & 3;          // 2 x 4 warps; warp tile 64m x 32n
    const int m0 = blockIdx.x * 128, n0 = blockIdx.y * 128;

    const __nv_bfloat16* __restrict__ Ah = g_h1H + (size_t)m0 * HID;
    const __nv_bfloat16* __restrict__ Al = g_h1L + (size_t)m0 * HID;
    const __nv_bfloat16* __restrict__ Bh = g_WdH + (size_t)n0 * HID;
    const __nv_bfloat16* __restrict__ Bl = g_WdL + (size_t)n0 * HID;

    // stage layout: Ah[16KB] Al[16KB] Bh[16KB] Bl[16KB]; 2 stages
    auto load_chunk = [&](int kc, int b) {
        const uint32_t stg = sb + b * 65536;
        const __nv_bfloat16* srcs[4] = { Ah, Al, Bh, Bl };
        #pragma unroll
        for (int arr = 0; arr < 4; arr++) {
            const uint32_t ab = stg + arr * 16384;
            #pragma unroll
            for (int i = 0; i < 4; i++) {
                const int g = tid + 256 * i;
                const int row = g >> 3, c = g & 7;
                cpa16(ab + SW128(row * 128 + c * 16),
                      srcs[arr] + (size_t)row * HID + kc * 64 + c * 8);
            }
        }
        asm volatile("cp.async.commit_group;" ::: "memory");
    };

    float acc[4][4][4] = {};   // [m-tile][n-tile][frag]

    // lane-invariant parts of ldmatrix addressing
    const int rowa = wm * 64 + (lane & 7) + ((lane >> 3) & 1) * 8;
    const int cola_sel = (lane >> 4) * 16;
    const int rowb = wn * 32 + (lane & 7) + ((lane >> 4) & 1) * 8;
    const int colb_sel = ((lane >> 3) & 1) * 16;

    load_chunk(0, 0);
    for (int kc = 0; kc < 16; kc++) {
        const int b = kc & 1;
        if (kc < 15) { load_chunk(kc + 1, b ^ 1);
                       asm volatile("cp.async.wait_group 1;" ::: "memory"); }
        else         { asm volatile("cp.async.wait_group 0;" ::: "memory"); }
        __syncthreads();

        const uint32_t stg = sb + b * 65536;
        #pragma unroll
        for (int ks = 0; ks < 4; ks++) {
            uint32_t ah[4][4], al[4][4], bhp[2][4], blp[2][4];
            const int cola = ks * 32 + cola_sel;
            #pragma unroll
            for (int mt = 0; mt < 4; mt++) {
                const uint32_t ad = stg + SW128((rowa + mt * 16) * 128 + cola);
                ldm4(ah[mt], ad);
                ldm4(al[mt], ad + 16384);
            }
            const int colb = ks * 32 + colb_sel;
            #pragma unroll
            for (int p = 0; p < 2; p++) {
                const uint32_t bd = stg + 32768 + SW128((rowb + p * 16) * 128 + colb);
                ldm4(bhp[p], bd);
                ldm4(blp[p], bd + 16384);
            }
            #pragma unroll
            for (int mt = 0; mt < 4; mt++) {
                #pragma unroll
                for (int nt = 0; nt < 4; nt++) {
                    const uint32_t* bh = &bhp[nt >> 1][(nt & 1) * 2];
                    const uint32_t* bl = &blp[nt >> 1][(nt & 1) * 2];
                    mma16816(acc[mt][nt], ah[mt], bh);
                    mma16816(acc[mt][nt], ah[mt], bl);
                    mma16816(acc[mt][nt], al[mt], bh);
                }
            }
        }
        __syncthreads();
    }

    // epilogue: direct stores, c-fragment layout m16n8
    #pragma unroll
    for (int mt = 0; mt < 4; mt++) {
        const int r = m0 + wm * 64 + mt * 16 + (lane >> 2);
        #pragma unroll
        for (int nt = 0; nt < 4; nt++) {
            const int cc = n0 + wn * 32 + nt * 8 + (lane & 3) * 2;
            const float2 bb = *(const float2*)(bdec + cc);
            float2 v0 = { acc[mt][nt][0] + bb.x, acc[mt][nt][1] + bb.y };
            float2 v1 = { acc[mt][nt][2] + bb.x, acc[mt][nt][3] + bb.y };
            *(float2*)(out + (size_t)r * VOC + cc) = v0;
            *(float2*)(out + (size_t)(r + 8) * VOC + cc) = v1;
        }
    }
}

// ---------------- precompute: xpre = gather(emb) @ [Wr0|Wf0|Wh0].T + bias ----------------
template<int BM, int BN, int BK, int TM, int TN2, int NT, class AF>
__device__ __forceinline__ void gcore(AF arow, const float* __restrict__ Wb,
                                      int Klen, int ldw,
                                      ull (&acc)[TM][TN2], float* __restrict__ sm)
{
    const int tid = threadIdx.x;
    constexpr int KV  = BK / 4;
    constexpr int AIT = BM * BK / 4 / NT;
    constexpr int WIT = BN * BK / 4 / NT;

    float4 ar[AIT], wr[WIT];
    auto fetch = [&](int kt) {
        #pragma unroll
        for (int r = 0; r < AIT; r++) {
            int idx = r * NT + tid; int m = idx / KV, kk = (idx % KV) * 4;
            ar[r] = *(const float4*)(arow(m) + kt + kk);
        }
        #pragma unroll
        for (int r = 0; r < WIT; r++) {
            int idx = r * NT + tid; int n = idx / KV, kk = (idx % KV) * 4;
            wr[r] = *(const float4*)(Wb + (size_t)n * ldw + kt + kk);
        }
    };
    auto stos = [&](int buf) {
        float* Asm = sm + buf * BK * BM;
        float* Wsm = sm + 2 * BK * BM + buf * BK * BN;
        #pragma unroll
        for (int r = 0; r < AIT; r++) {
            int idx = r * NT + tid; int m = idx / KV, kk = (idx % KV) * 4;
            Asm[(kk+0)*BM+m]=ar[r].x; Asm[(kk+1)*BM+m]=ar[r].y;
            Asm[(kk+2)*BM+m]=ar[r].z; Asm[(kk+3)*BM+m]=ar[r].w;
        }
        #pragma unroll
        for (int r = 0; r < WIT; r++) {
            int idx = r * NT + tid; int n = idx / KV, kk = (idx % KV) * 4;
            Wsm[(kk+0)*BN+n]=wr[r].x; Wsm[(kk+1)*BN+n]=wr[r].y;
            Wsm[(kk+2)*BN+n]=wr[r].z; Wsm[(kk+3)*BN+n]=wr[r].w;
        }
    };

    constexpr int NG = BN / (2 * TN2);
    const int tn = tid % NG, tm = tid / NG;

    fetch(0); stos(0); __syncthreads();

    for (int kt = 0; kt < Klen; kt += BK) {
        const int buf = (kt / BK) & 1;
        if (kt + BK < Klen) fetch(kt + BK);
        const float* Asm = sm + buf * BK * BM + tm * TM;
        const float* Wsm = sm + 2 * BK * BM + buf * BK * BN + tn * (2 * TN2);
        #pragma unroll
        for (int k = 0; k < BK; k++) {
            float av[TM];
            #pragma unroll
            for (int q = 0; q < TM/4; q++)
                *(float4*)(av + 4*q) = *(const float4*)(Asm + k * BM + 4*q);
            ull wv[TN2];
            #pragma unroll
            for (int q = 0; q < TN2/2; q++) {
                ulonglong2 t2 = *(const ulonglong2*)(Wsm + k * BN + 4*q);
                wv[2*q] = t2.x; wv[2*q+1] = t2.y;
            }
            #pragma unroll
            for (int i = 0; i < TM; i++) {
                ull a2 = pk2(av[i]);
                #pragma unroll
                for (int j = 0; j < TN2; j++) fm2(acc[i][j], wv[j], a2);
            }
        }
        if (kt + BK < Klen) stos(buf ^ 1);
        __syncthreads();
    }
}

__global__ __launch_bounds__(256)
void k_pre(const int* __restrict__ tokens, const float* __restrict__ emb,
           const float* __restrict__ W0, const float* __restrict__ W1, const float* __restrict__ W2,
           const float* __restrict__ b0, const float* __restrict__ b1, const float* __restrict__ b2)
{
    constexpr int BM = 128, BN = 128, BK = 16, TM = 8, TN2 = 4, NT = 256;
    __shared__ __align__(16) float sm[2*BK*BM + 2*BK*BN];
    __shared__ int stok[BM];
    const int m0 = blockIdx.y * BM, n0 = blockIdx.x * BN;
    const int seg = n0 >> 10, nn0 = n0 & 1023;
    const float* W    = (seg == 0) ? W0 : (seg == 1) ? W1 : W2;
    const float* bias = (seg == 0) ? b0 : (seg == 1) ? b1 : b2;

    if (threadIdx.x < BM) stok[threadIdx.x] = tokens[m0 + threadIdx.x];
    __syncthreads();

    ull acc[TM][TN2] = {};
    auto arow = [&](int m) { return emb + (size_t)stok[m] * HID; };
    gcore<BM,BN,BK,TM,TN2,NT>(arow, W + (size_t)nn0 * HID, HID, HID, acc, sm);

    constexpr int NG = BN / (2*TN2);
    const int tn = threadIdx.x % NG, tm = threadIdx.x / NG;
    #pragma unroll
    for (int i = 0; i < TM; i++) {
        const int m = m0 + tm*TM + i;
        const int nl = tn * (2*TN2);
        float* dst = g_xpre + (size_t)m * (3*HID) + n0 + nl;
        #pragma unroll
        for (int q = 0; q < TN2/2; q++) {
            union { ull u[2]; float4 f; } cv;
            cv.u[0] = acc[i][2*q]; cv.u[1] = acc[i][2*q+1];
            float4 bb = *(const float4*)(bias + nn0 + nl + 4*q);
            cv.f.x += bb.x; cv.f.y += bb.y; cv.f.z += bb.z; cv.f.w += bb.w;
            ((float4*)dst)[q] = cv.f;
        }
    }
}

// ---------------- launch ----------------
extern "C" void kernel_launch(void* const* d_in, const int* in_sizes, int n_in,
                              void* d_out, int out_size)
{
    const int*   tokens = (const int*)  d_in[0];
    const float* hidden = (const float*)d_in[1];
    const float* emb    = (const float*)d_in[2];
    const float* Wr     = (const float*)d_in[3];
    const float* br     = (const float*)d_in[4];
    const float* Wf     = (const float*)d_in[5];
    const float* bf     = (const float*)d_in[6];
    const float* Wh     = (const float*)d_in[7];
    const float* bh     = (const float*)d_in[8];
    const float* Ur     = (const float*)d_in[9];
    const float* bur    = (const float*)d_in[10];
    const float* Ufw    = (const float*)d_in[11];
    const float* bufw   = (const float*)d_in[12];
    const float* Uh     = (const float*)d_in[13];
    const float* buh    = (const float*)d_in[14];
    const float* Wdec   = (const float*)d_in[15];
    const float* bdec   = (const float*)d_in[16];
    float* out = (float*)d_out;

    const size_t HH = (size_t)HID * HID;

    cudaFuncSetAttribute(k_dec_mma, cudaFuncAttributeMaxDynamicSharedMemorySize, DEC_SMEM);

    k_hinit<<<(M2*HID + 1023) / 1024, 1024>>>(hidden);
    k_addw<<<(HID*HID + 255) / 256, 256>>>(Wr + HH, Ur + HH, Wf + HH, Ufw + HH,
                                           br + HID, bur + HID, bf + HID, bufw + HID,
                                           bh + HID, buh + HID);
    k_splitW<<<2048, 256>>>(Wdec);
    k_pre<<<dim3(3*HID/128, TB/128), 256>>>(tokens, emb, Wr, Wf, Wh, br, bf, bh);

    k_rec<<<REC_CTAS, 256>>>(Ur, Ufw, Uh, Wh + HH, Uh + HH, bur, bufw, buh);

    k_dec_mma<<<dim3(32, 250), 256, DEC_SMEM>>>(bdec, out);

    const long long logits_elems = (long long)TB * VOC;
    if ((long long)out_size >= logits_elems + (long long)M2 * HID)
        k_hout<<<(M2*HID + 1023) / 1024, 1024>>>(out + logits_elems);
}

// round 12
// speedup vs baseline: 3.4845x; 1.0105x over previous
#include <cuda_runtime.h>
#include <cuda_bf16.h>
#include <cstdint>
#include <math.h>

#define T_STEPS 64
#define BATCH   64
#define HID     1024
#define VOC     32000
#define M2      128
#define TB      4096

typedef unsigned long long ull;

// ---------------- device scratch ----------------
__device__ float g_xpre[(size_t)TB * 3 * HID];   // layer-0 input projections (+b{r,f,h}0)
__device__ float g_ha[M2 * HID];                 // h ping
__device__ float g_hb[M2 * HID];                 // h pong
__device__ float g_rh[M2 * HID];                 // r * h
__device__ float g_f[M2 * HID];                  // f gate
__device__ float g_WUr1[HID * HID];              // Wr1 + Ur1
__device__ float g_WUf1[HID * HID];              // Wf1 + Uf1
__device__ float g_brc[HID], g_bfc[HID], g_bhc[HID];
__device__ float g_part[2 * 1024 * 1024];        // split-K partials (8MB)
__device__ unsigned g_bar, g_bar2;               // grid barrier counters (self-resetting)
// bf16 split operands for the tensor-core decoder
__device__ __align__(16) __nv_bfloat16 g_h1H[(size_t)TB * HID];
__device__ __align__(16) __nv_bfloat16 g_h1L[(size_t)TB * HID];
__device__ __align__(16) __nv_bfloat16 g_WdH[(size_t)VOC * HID];
__device__ __align__(16) __nv_bfloat16 g_WdL[(size_t)VOC * HID];

__device__ __forceinline__ float sigm(float x) { return 1.0f / (1.0f + expf(-x)); }

// -------- packed f32x2 primitives --------
__device__ __forceinline__ ull pk2(float x) {
    ull r; asm("mov.b64 %0, {%1, %1};" : "=l"(r) : "f"(x)); return r;
}
__device__ __forceinline__ void fm2(ull& d, ull a, ull b) {
    asm("fma.rn.f32x2 %0, %1, %2, %3;" : "=l"(d) : "l"(a), "l"(b), "l"(d));
}
__device__ __forceinline__ float up2sum(ull v) {
    float lo, hi; asm("mov.b64 {%0, %1}, %2;" : "=f"(lo), "=f"(hi) : "l"(v));
    return lo + hi;
}

// ================= K-paired f32x2 GEMM core (recurrence) =================
#define BKT 16
#define LDK 20
#define SMF (2 * 2 * 128 * LDK)

__device__ __forceinline__ void gkp(const float* __restrict__ Ab,
                                    const float* __restrict__ Wb,
                                    int klen, ull (&acc)[8][8],
                                    float* __restrict__ sm)
{
    const int tid = threadIdx.x;
    const int lr = tid >> 2;
    const int lk = (tid & 3) * 4;
    const int tn = tid & 15, tm = tid >> 4;

    float4 a0, a1, w0, w1;
    auto fetch = [&](int kt) {
        a0 = __ldcg((const float4*)(Ab + (size_t)lr        * HID + kt + lk));
        a1 = __ldcg((const float4*)(Ab + (size_t)(lr + 64) * HID + kt + lk));
        w0 = __ldg ((const float4*)(Wb + (size_t)lr        * HID + kt + lk));
        w1 = __ldg ((const float4*)(Wb + (size_t)(lr + 64) * HID + kt + lk));
    };
    auto put = [&](int buf) {
        float* As = sm + buf * (2 * 128 * LDK);
        float* Ws = As + 128 * LDK;
        *(float4*)(As + lr * LDK + lk) = a0;
        *(float4*)(As + (lr + 64) * LDK + lk) = a1;
        *(float4*)(Ws + lr * LDK + lk) = w0;
        *(float4*)(Ws + (lr + 64) * LDK + lk) = w1;
    };

    fetch(0); put(0); __syncthreads();
    const int nt = klen / BKT;
    for (int kt = 0; kt < nt; kt++) {
        if (kt + 1 < nt) fetch((kt + 1) * BKT);
        const float* As = sm + (kt & 1) * (2 * 128 * LDK) + tm * 8 * LDK;
        const float* Ws = sm + (kt & 1) * (2 * 128 * LDK) + 128 * LDK + tn * LDK;
        #pragma unroll
        for (int g = 0; g < BKT / 4; g++) {
            ull a[16];
            #pragma unroll
            for (int i = 0; i < 8; i++) {
                float4 v = *(const float4*)(As + i * LDK + g * 4);
                a[2*i]   = ((const ull*)&v)[0];
                a[2*i+1] = ((const ull*)&v)[1];
            }
            #pragma unroll
            for (int j = 0; j < 8; j++) {
                float4 v = *(const float4*)(Ws + j * 16 * LDK + g * 4);
                ull wlo = ((const ull*)&v)[0], whi = ((const ull*)&v)[1];
                #pragma unroll
                for (int i = 0; i < 8; i++) {
                    fm2(acc[i][j], a[2*i],   wlo);
                    fm2(acc[i][j], a[2*i+1], whi);
                }
            }
        }
        if (kt + 1 < nt) put((kt + 1) & 1);
        __syncthreads();
    }
}

// ================= persistent recurrence kernel =================
#define REC_CTAS 128

__device__ __forceinline__ void gbar(unsigned nbar) {
    __threadfence();
    __syncthreads();
    if (threadIdx.x == 0) {
        atomicAdd(&g_bar, 1u);
        const unsigned tgt = (unsigned)REC_CTAS * nbar;
        while (*(volatile unsigned*)&g_bar < tgt) __nanosleep(8);
    }
    __syncthreads();
}

__device__ __forceinline__ void stpart(ull (&acc)[8][8], int ks, int ntile, int Ntot) {
    const int tn = threadIdx.x & 15, tm = threadIdx.x >> 4;
    #pragma unroll
    for (int i = 0; i < 8; i++) {
        const int m = tm * 8 + i;
        float* row = g_part + ((size_t)ks * M2 + m) * Ntot + ntile * 128;
        #pragma unroll
        for (int j = 0; j < 8; j++)
            row[tn + 16 * j] = up2sum(acc[i][j]);
    }
}

__global__ __launch_bounds__(256)
void k_rec(const float* __restrict__ Ur0, const float* __restrict__ Uf0,
           const float* __restrict__ Uh0,
           const float* __restrict__ Wh1, const float* __restrict__ Uh1,
           const float* __restrict__ bur0, const float* __restrict__ buf0,
           const float* __restrict__ buh0)
{
    __shared__ __align__(16) float sm[SMF];
    const int cta = blockIdx.x, tid = threadIdx.x;
    unsigned nbar = 0;

    for (int t = 0; t < T_STEPS; t++) {
        // ---------- p0 GEMM: [r|f]0 = h @ [Ur0|Uf0].T (split-K 8) ----------
        {
            const int ntile = cta & 15, ks = cta >> 4, koff = ks * 128;
            const float* W = ((ntile < 8) ? Ur0 : Uf0) + (size_t)((ntile & 7) * 128) * HID;
            ull acc[8][8] = {};
            gkp(g_ha + koff, W + koff, 128, acc, sm);
            stpart(acc, ks, ntile, 2048);
        }
        gbar(++nbar);
        // ---------- p0 reduce + sigmoid ----------
        {
            const int m = tid >> 1, b = m & (BATCH - 1);
            const int n = cta * 16 + (tid & 1) * 8;
            float4 s0 = {0,0,0,0}, s1 = {0,0,0,0};
            #pragma unroll
            for (int ks = 0; ks < 8; ks++) {
                const float* p = g_part + ((size_t)ks * M2 + m) * 2048 + n;
                float4 v0 = __ldcg((const float4*)p), v1 = __ldcg((const float4*)(p + 4));
                s0.x += v0.x; s0.y += v0.y; s0.z += v0.z; s0.w += v0.w;
                s1.x += v1.x; s1.y += v1.y; s1.z += v1.z; s1.w += v1.w;
            }
            const int seg = n >> 10, nn = n & 1023;
            const float* bias = seg ? buf0 : bur0;
            float v[8] = {s0.x, s0.y, s0.z, s0.w, s1.x, s1.y, s1.z, s1.w};
            #pragma unroll
            for (int c = 0; c < 8; c++) {
                const float xadd = __ldg(g_xpre + ((size_t)t * BATCH + b) * (3 * HID) + n + c);
                const float g = sigm(v[c] + __ldg(bias + nn + c) + xadd);
                const int idx = m * HID + nn + c;
                if (seg == 0) g_rh[idx] = g * __ldcg(g_ha + idx);
                else          g_f[idx]  = g;
            }
        }
        gbar(++nbar);
        // ---------- p1 GEMM: hw0 = rh @ Uh0.T (split-K 16) ----------
        {
            const int ntile = cta & 7, ks = cta >> 3, koff = ks * 64;
            ull acc[8][8] = {};
            gkp(g_rh + koff, Uh0 + (size_t)(ntile * 128) * HID + koff, 64, acc, sm);
            stpart(acc, ks, ntile, 1024);
        }
        gbar(++nbar);
        // ---------- p1 reduce + tanh + h update ----------
        {
            const int m = tid >> 1, b = m & (BATCH - 1);
            const int n = cta * 8 + (tid & 1) * 4;
            float4 s = {0,0,0,0};
            #pragma unroll
            for (int ks = 0; ks < 16; ks++) {
                float4 v = __ldcg((const float4*)(g_part + ((size_t)ks * M2 + m) * 1024 + n));
                s.x += v.x; s.y += v.y; s.z += v.z; s.w += v.w;
            }
            float v[4] = {s.x, s.y, s.z, s.w};
            #pragma unroll
            for (int c = 0; c < 4; c++) {
                const float xadd = __ldg(g_xpre + ((size_t)t * BATCH + b) * (3 * HID) + 2 * HID + n + c);
                const float hw = tanhf(v[c] + __ldg(buh0 + n + c) + xadd);
                const int idx = m * HID + n + c;
                const float h = __ldcg(g_ha + idx), f = __ldcg(g_f + idx);
                g_hb[idx] = h + f * (hw - h);
            }
        }
        gbar(++nbar);
        // ---------- p2 GEMM: [r|f]1 = hb @ [WUr1|WUf1].T (split-K 8) ----------
        {
            const int ntile = cta & 15, ks = cta >> 4, koff = ks * 128;
            const float* W = ((ntile < 8) ? g_WUr1 : g_WUf1) + (size_t)((ntile & 7) * 128) * HID;
            ull acc[8][8] = {};
            gkp(g_hb + koff, W + koff, 128, acc, sm);
            stpart(acc, ks, ntile, 2048);
        }
        gbar(++nbar);
        // ---------- p2 reduce + sigmoid ----------
        {
            const int m = tid >> 1;
            const int n = cta * 16 + (tid & 1) * 8;
            float4 s0 = {0,0,0,0}, s1 = {0,0,0,0};
            #pragma unroll
            for (int ks = 0; ks < 8; ks++) {
                const float* p = g_part + ((size_t)ks * M2 + m) * 2048 + n;
                float4 v0 = __ldcg((const float4*)p), v1 = __ldcg((const float4*)(p + 4));
                s0.x += v0.x; s0.y += v0.y; s0.z += v0.z; s0.w += v0.w;
                s1.x += v1.x; s1.y += v1.y; s1.z += v1.z; s1.w += v1.w;
            }
            const int seg = n >> 10, nn = n & 1023;
            float v[8] = {s0.x, s0.y, s0.z, s0.w, s1.x, s1.y, s1.z, s1.w};
            #pragma unroll
            for (int c = 0; c < 8; c++) {
                const int idx = m * HID + nn + c;
                if (seg == 0) {
                    const float r = sigm(v[c] + g_brc[nn + c]);
                    g_rh[idx] = r * __ldcg(g_hb + idx);
                } else {
                    g_f[idx] = sigm(v[c] + g_bfc[nn + c]);
                }
            }
        }
        gbar(++nbar);
        // ---------- p3 GEMM: hw1 = hb @ Wh1.T + rh @ Uh1.T (virtual K=2048, split 16) ----------
        {
            const int ntile = cta & 7, ks = cta >> 3;
            ull acc[8][8] = {};
            if (ks < 8) {
                const int koff = ks * 128;
                gkp(g_hb + koff, Wh1 + (size_t)(ntile * 128) * HID + koff, 128, acc, sm);
            } else {
                const int koff = (ks - 8) * 128;
                gkp(g_rh + koff, Uh1 + (size_t)(ntile * 128) * HID + koff, 128, acc, sm);
            }
            stpart(acc, ks, ntile, 1024);
        }
        gbar(++nbar);
        // ---------- p3 reduce + tanh + h update + h1 bf16 hi/lo stash ----------
        {
            const int m = tid >> 1;
            const int n = cta * 8 + (tid & 1) * 4;
            float4 s = {0,0,0,0};
            #pragma unroll
            for (int ks = 0; ks < 16; ks++) {
                float4 v = __ldcg((const float4*)(g_part + ((size_t)ks * M2 + m) * 1024 + n));
                s.x += v.x; s.y += v.y; s.z += v.z; s.w += v.w;
            }
            float v[4] = {s.x, s.y, s.z, s.w};
            #pragma unroll
            for (int c = 0; c < 4; c++) {
                const float hw = tanhf(v[c] + g_bhc[n + c]);
                const int idx = m * HID + n + c;
                const float h = __ldcg(g_hb + idx), f = __ldcg(g_f + idx);
                const float nh = h + f * (hw - h);
                g_ha[idx] = nh;
                if (m >= BATCH) {
                    const size_t o = ((size_t)t * BATCH + (m - BATCH)) * HID + n + c;
                    const __nv_bfloat16 hh = __float2bfloat16(nh);
                    g_h1H[o] = hh;
                    g_h1L[o] = __float2bfloat16(nh - __bfloat162float(hh));
                }
            }
        }
        if (t != T_STEPS - 1) gbar(++nbar);
    }

    __threadfence();
    __syncthreads();
    if (tid == 0) atomicAdd(&g_bar2, 1u);
    if (cta == 0 && tid == 0) {
        while (*(volatile unsigned*)&g_bar2 < (unsigned)REC_CTAS) __nanosleep(8);
        g_bar = 0; g_bar2 = 0;
        __threadfence();
    }
}

// ---------------- setup kernels ----------------
__global__ void k_hinit(const float* __restrict__ hidden) {
    int i = blockIdx.x * blockDim.x + threadIdx.x;
    if (i < M2 * HID) g_ha[i] = hidden[i];
}
__global__ void k_hout(float* __restrict__ out) {
    int i = blockIdx.x * blockDim.x + threadIdx.x;
    if (i < M2 * HID) out[i] = g_ha[i];
}
__global__ void k_addw(const float* __restrict__ Wr1, const float* __restrict__ Ur1,
                       const float* __restrict__ Wf1, const float* __restrict__ Uf1,
                       const float* __restrict__ br1, const float* __restrict__ bur1,
                       const float* __restrict__ bf1, const float* __restrict__ buf1,
                       const float* __restrict__ bh1, const float* __restrict__ buh1) {
    int i = blockIdx.x * blockDim.x + threadIdx.x;
    if (i < HID * HID) {
        g_WUr1[i] = Wr1[i] + Ur1[i];
        g_WUf1[i] = Wf1[i] + Uf1[i];
    }
    if (i < HID) {
        g_brc[i] = br1[i] + bur1[i];
        g_bfc[i] = bf1[i] + buf1[i];
        g_bhc[i] = bh1[i] + buh1[i];
    }
}

// ---------------- Wdec -> bf16 hi/lo split ----------------
__global__ void k_splitW(const float* __restrict__ W) {
    const size_t n4 = (size_t)VOC * HID / 4;
    for (size_t j = (size_t)blockIdx.x * blockDim.x + threadIdx.x; j < n4;
         j += (size_t)gridDim.x * blockDim.x) {
        float4 v = __ldg((const float4*)W + j);
        __nv_bfloat16 h0 = __float2bfloat16(v.x), h1 = __float2bfloat16(v.y);
        __nv_bfloat16 h2 = __float2bfloat16(v.z), h3 = __float2bfloat16(v.w);
        ushort4 hv = { __bfloat16_as_ushort(h0), __bfloat16_as_ushort(h1),
                       __bfloat16_as_ushort(h2), __bfloat16_as_ushort(h3) };
        ((ushort4*)g_WdH)[j] = hv;
        __nv_bfloat16 l0 = __float2bfloat16(v.x - __bfloat162float(h0));
        __nv_bfloat16 l1 = __float2bfloat16(v.y - __bfloat162float(h1));
        __nv_bfloat16 l2 = __float2bfloat16(v.z - __bfloat162float(h2));
        __nv_bfloat16 l3 = __float2bfloat16(v.w - __bfloat162float(h3));
        ushort4 lv = { __bfloat16_as_ushort(l0), __bfloat16_as_ushort(l1),
                       __bfloat16_as_ushort(l2), __bfloat16_as_ushort(l3) };
        ((ushort4*)g_WdL)[j] = lv;
    }
}

// ================= mma.sync bf16x3 decoder (base-target tensor cores) =================
__device__ __forceinline__ uint32_t s2u(const void* p) {
    uint32_t a;
    asm("{ .reg .u64 t; cvta.to.shared.u64 t, %1; cvt.u32.u64 %0, t; }" : "=r"(a) : "l"(p));
    return a;
}
__device__ __forceinline__ void cpa16(uint32_t dst, const void* src) {
    asm volatile("cp.async.cg.shared.global [%0], [%1], 16;" :: "r"(dst), "l"(src) : "memory");
}
#define SW128(o) ((o) ^ (((o) >> 3) & 0x70))

__device__ __forceinline__ void ldm4(uint32_t* r, uint32_t addr) {
    asm volatile("ldmatrix.sync.aligned.m8n8.x4.shared.b16 {%0,%1,%2,%3}, [%4];"
                 : "=r"(r[0]), "=r"(r[1]), "=r"(r[2]), "=r"(r[3]) : "r"(addr));
}
__device__ __forceinline__ void mma16816(float* d, const uint32_t* a, const uint32_t* b) {
    asm volatile(
        "mma.sync.aligned.m16n8k16.row.col.f32.bf16.bf16.f32 "
        "{%0,%1,%2,%3},{%4,%5,%6,%7},{%8,%9},{%0,%1,%2,%3};"
        : "+f"(d[0]), "+f"(d[1]), "+f"(d[2]), "+f"(d[3])
        : "r"(a[0]), "r"(a[1]), "r"(a[2]), "r"(a[3]), "r"(b[0]), "r"(b[1]));
}

#define DEC_SMEM (2 * 65536)

__global__ __launch_bounds__(256)
void k_dec_mma(const float* __restrict__ bdec, float* __restrict__ out)
{
    extern __shared__ __align__(128) char dsm[];
    const uint32_t sb = s2u(dsm);
    const int tid = threadIdx.x, lane = tid & 31, wid = tid >> 5;
    const int wm = wid >> 2, wn = wid & 3;          // 2 x 4 warps; warp tile 64m x 32n
    const int m0 = blockIdx.x * 128, n0 = blockIdx.y * 128;

    const __nv_bfloat16* __restrict__ Ah = g_h1H + (size_t)m0 * HID;
    const __nv_bfloat16* __restrict__ Al = g_h1L + (size_t)m0 * HID;
    const __nv_bfloat16* __restrict__ Bh = g_WdH + (size_t)n0 * HID;
    const __nv_bfloat16* __restrict__ Bl = g_WdL + (size_t)n0 * HID;

    // stage layout: Ah[16KB] Al[16KB] Bh[16KB] Bl[16KB]; 2 stages
    auto load_chunk = [&](int kc, int b) {
        const uint32_t stg = sb + b * 65536;
        const __nv_bfloat16* srcs[4] = { Ah, Al, Bh, Bl };
        #pragma unroll
        for (int arr = 0; arr < 4; arr++) {
            const uint32_t ab = stg + arr * 16384;
            #pragma unroll
            for (int i = 0; i < 4; i++) {
                const int g = tid + 256 * i;
                const int row = g >> 3, c = g & 7;
                cpa16(ab + SW128(row * 128 + c * 16),
                      srcs[arr] + (size_t)row * HID + kc * 64 + c * 8);
            }
        }
        asm volatile("cp.async.commit_group;" ::: "memory");
    };

    float acc[4][4][4] = {};   // [m-tile][n-tile][frag]

    // lane-invariant parts of ldmatrix addressing
    const int rowa = wm * 64 + (lane & 7) + ((lane >> 3) & 1) * 8;
    const int cola_sel = (lane >> 4) * 16;
    const int rowb = wn * 32 + (lane & 7) + ((lane >> 4) & 1) * 8;
    const int colb_sel = ((lane >> 3) & 1) * 16;

    load_chunk(0, 0);
    for (int kc = 0; kc < 16; kc++) {
        const int b = kc & 1;
        if (kc < 15) { load_chunk(kc + 1, b ^ 1);
                       asm volatile("cp.async.wait_group 1;" ::: "memory"); }
        else         { asm volatile("cp.async.wait_group 0;" ::: "memory"); }
        __syncthreads();

        const uint32_t stg = sb + b * 65536;
        #pragma unroll
        for (int ks = 0; ks < 4; ks++) {
            uint32_t ah[4][4], al[4][4], bhp[2][4], blp[2][4];
            const int cola = ks * 32 + cola_sel;
            #pragma unroll
            for (int mt = 0; mt < 4; mt++) {
                const uint32_t ad = stg + SW128((rowa + mt * 16) * 128 + cola);
                ldm4(ah[mt], ad);
                ldm4(al[mt], ad + 16384);
            }
            const int colb = ks * 32 + colb_sel;
            #pragma unroll
            for (int p = 0; p < 2; p++) {
                const uint32_t bd = stg + 32768 + SW128((rowb + p * 16) * 128 + colb);
                ldm4(bhp[p], bd);
                ldm4(blp[p], bd + 16384);
            }
            #pragma unroll
            for (int mt = 0; mt < 4; mt++) {
                #pragma unroll
                for (int nt = 0; nt < 4; nt++) {
                    const uint32_t* bh = &bhp[nt >> 1][(nt & 1) * 2];
                    const uint32_t* bl = &blp[nt >> 1][(nt & 1) * 2];
                    mma16816(acc[mt][nt], ah[mt], bh);
                    mma16816(acc[mt][nt], ah[mt], bl);
                    mma16816(acc[mt][nt], al[mt], bh);
                }
            }
        }
        __syncthreads();
    }

    // epilogue: direct stores, c-fragment layout m16n8
    #pragma unroll
    for (int mt = 0; mt < 4; mt++) {
        const int r = m0 + wm * 64 + mt * 16 + (lane >> 2);
        #pragma unroll
        for (int nt = 0; nt < 4; nt++) {
            const int cc = n0 + wn * 32 + nt * 8 + (lane & 3) * 2;
            const float2 bb = *(const float2*)(bdec + cc);
            float2 v0 = { acc[mt][nt][0] + bb.x, acc[mt][nt][1] + bb.y };
            float2 v1 = { acc[mt][nt][2] + bb.x, acc[mt][nt][3] + bb.y };
            *(float2*)(out + (size_t)r * VOC + cc) = v0;
            *(float2*)(out + (size_t)(r + 8) * VOC + cc) = v1;
        }
    }
}

// ---------------- precompute: xpre = gather(emb) @ [Wr0|Wf0|Wh0].T + bias ----------------
template<int BM, int BN, int BK, int TM, int TN2, int NT, class AF>
__device__ __forceinline__ void gcore(AF arow, const float* __restrict__ Wb,
                                      int Klen, int ldw,
                                      ull (&acc)[TM][TN2], float* __restrict__ sm)
{
    const int tid = threadIdx.x;
    constexpr int KV  = BK / 4;
    constexpr int AIT = BM * BK / 4 / NT;
    constexpr int WIT = BN * BK / 4 / NT;

    float4 ar[AIT], wr[WIT];
    auto fetch = [&](int kt) {
        #pragma unroll
        for (int r = 0; r < AIT; r++) {
            int idx = r * NT + tid; int m = idx / KV, kk = (idx % KV) * 4;
            ar[r] = *(const float4*)(arow(m) + kt + kk);
        }
        #pragma unroll
        for (int r = 0; r < WIT; r++) {
            int idx = r * NT + tid; int n = idx / KV, kk = (idx % KV) * 4;
            wr[r] = *(const float4*)(Wb + (size_t)n * ldw + kt + kk);
        }
    };
    auto stos = [&](int buf) {
        float* Asm = sm + buf * BK * BM;
        float* Wsm = sm + 2 * BK * BM + buf * BK * BN;
        #pragma unroll
        for (int r = 0; r < AIT; r++) {
            int idx = r * NT + tid; int m = idx / KV, kk = (idx % KV) * 4;
            Asm[(kk+0)*BM+m]=ar[r].x; Asm[(kk+1)*BM+m]=ar[r].y;
            Asm[(kk+2)*BM+m]=ar[r].z; Asm[(kk+3)*BM+m]=ar[r].w;
        }
        #pragma unroll
        for (int r = 0; r < WIT; r++) {
            int idx = r * NT + tid; int n = idx / KV, kk = (idx % KV) * 4;
            Wsm[(kk+0)*BN+n]=wr[r].x; Wsm[(kk+1)*BN+n]=wr[r].y;
            Wsm[(kk+2)*BN+n]=wr[r].z; Wsm[(kk+3)*BN+n]=wr[r].w;
        }
    };

    constexpr int NG = BN / (2 * TN2);
    const int tn = tid % NG, tm = tid / NG;

    fetch(0); stos(0); __syncthreads();

    for (int kt = 0; kt < Klen; kt += BK) {
        const int buf = (kt / BK) & 1;
        if (kt + BK < Klen) fetch(kt + BK);
        const float* Asm = sm + buf * BK * BM + tm * TM;
        const float* Wsm = sm + 2 * BK * BM + buf * BK * BN + tn * (2 * TN2);
        #pragma unroll
        for (int k = 0; k < BK; k++) {
            float av[TM];
            #pragma unroll
            for (int q = 0; q < TM/4; q++)
                *(float4*)(av + 4*q) = *(const float4*)(Asm + k * BM + 4*q);
            ull wv[TN2];
            #pragma unroll
            for (int q = 0; q < TN2/2; q++) {
                ulonglong2 t2 = *(const ulonglong2*)(Wsm + k * BN + 4*q);
                wv[2*q] = t2.x; wv[2*q+1] = t2.y;
            }
            #pragma unroll
            for (int i = 0; i < TM; i++) {
                ull a2 = pk2(av[i]);
                #pragma unroll
                for (int j = 0; j < TN2; j++) fm2(acc[i][j], wv[j], a2);
            }
        }
        if (kt + BK < Klen) stos(buf ^ 1);
        __syncthreads();
    }
}

__global__ __launch_bounds__(256, 2)
void k_pre(const int* __restrict__ tokens, const float* __restrict__ emb,
           const float* __restrict__ W0, const float* __restrict__ W1, const float* __restrict__ W2,
           const float* __restrict__ b0, const float* __restrict__ b1, const float* __restrict__ b2)
{
    constexpr int BM = 128, BN = 128, BK = 16, TM = 8, TN2 = 4, NT = 256;
    __shared__ __align__(16) float sm[2*BK*BM + 2*BK*BN];
    __shared__ int stok[BM];
    const int m0 = blockIdx.y * BM, n0 = blockIdx.x * BN;
    const int seg = n0 >> 10, nn0 = n0 & 1023;
    const float* W    = (seg == 0) ? W0 : (seg == 1) ? W1 : W2;
    const float* bias = (seg == 0) ? b0 : (seg == 1) ? b1 : b2;

    if (threadIdx.x < BM) stok[threadIdx.x] = tokens[m0 + threadIdx.x];
    __syncthreads();

    ull acc[TM][TN2] = {};
    auto arow = [&](int m) { return emb + (size_t)stok[m] * HID; };
    gcore<BM,BN,BK,TM,TN2,NT>(arow, W + (size_t)nn0 * HID, HID, HID, acc, sm);

    constexpr int NG = BN / (2*TN2);
    const int tn = threadIdx.x % NG, tm = threadIdx.x / NG;
    #pragma unroll
    for (int i = 0; i < TM; i++) {
        const int m = m0 + tm*TM + i;
        const int nl = tn * (2*TN2);
        float* dst = g_xpre + (size_t)m * (3*HID) + n0 + nl;
        #pragma unroll
        for (int q = 0; q < TN2/2; q++) {
            union { ull u[2]; float4 f; } cv;
            cv.u[0] = acc[i][2*q]; cv.u[1] = acc[i][2*q+1];
            float4 bb = *(const float4*)(bias + nn0 + nl + 4*q);
            cv.f.x += bb.x; cv.f.y += bb.y; cv.f.z += bb.z; cv.f.w += bb.w;
            ((float4*)dst)[q] = cv.f;
        }
    }
}

// ---------------- launch ----------------
extern "C" void kernel_launch(void* const* d_in, const int* in_sizes, int n_in,
                              void* d_out, int out_size)
{
    const int*   tokens = (const int*)  d_in[0];
    const float* hidden = (const float*)d_in[1];
    const float* emb    = (const float*)d_in[2];
    const float* Wr     = (const float*)d_in[3];
    const float* br     = (const float*)d_in[4];
    const float* Wf     = (const float*)d_in[5];
    const float* bf     = (const float*)d_in[6];
    const float* Wh     = (const float*)d_in[7];
    const float* bh     = (const float*)d_in[8];
    const float* Ur     = (const float*)d_in[9];
    const float* bur    = (const float*)d_in[10];
    const float* Ufw    = (const float*)d_in[11];
    const float* bufw   = (const float*)d_in[12];
    const float* Uh     = (const float*)d_in[13];
    const float* buh    = (const float*)d_in[14];
    const float* Wdec   = (const float*)d_in[15];
    const float* bdec   = (const float*)d_in[16];
    float* out = (float*)d_out;

    const size_t HH = (size_t)HID * HID;

    cudaFuncSetAttribute(k_dec_mma, cudaFuncAttributeMaxDynamicSharedMemorySize, DEC_SMEM);

    k_hinit<<<(M2*HID + 1023) / 1024, 1024>>>(hidden);
    k_addw<<<(HID*HID + 255) / 256, 256>>>(Wr + HH, Ur + HH, Wf + HH, Ufw + HH,
                                           br + HID, bur + HID, bf + HID, bufw + HID,
                                           bh + HID, buh + HID);
    k_splitW<<<2048, 256>>>(Wdec);
    k_pre<<<dim3(3*HID/128, TB/128), 256>>>(tokens, emb, Wr, Wf, Wh, br, bf, bh);

    k_rec<<<REC_CTAS, 256>>>(Ur, Ufw, Uh, Wh + HH, Uh + HH, bur, bufw, buh);

    k_dec_mma<<<dim3(32, 250), 256, DEC_SMEM>>>(bdec, out);

    const long long logits_elems = (long long)TB * VOC;
    if ((long long)out_size >= logits_elems + (long long)M2 * HID)
        k_hout<<<(M2*HID + 1023) / 1024, 1024>>>(out + logits_elems);
}

// round 13
// speedup vs baseline: 5.2009x; 1.4926x over previous
#include <cuda_runtime.h>
#include <cuda_bf16.h>
#include <cstdint>
#include <math.h>

#define T_STEPS 64
#define BATCH   64
#define HID     1024
#define VOC     32000
#define M2      128
#define TB      4096

typedef unsigned long long ull;
typedef __nv_bfloat16 bf16;

// ---------------- device scratch ----------------
__device__ float g_xpre[(size_t)TB * 3 * HID];
__device__ float g_ha[M2 * HID];                 // h ping (fp32 master)
__device__ float g_hb[M2 * HID];                 // h pong
__device__ float g_f[M2 * HID];                  // f gate
__device__ float g_brc[HID], g_bfc[HID], g_bhc[HID];
__device__ float g_part[2 * 1024 * 1024];
__device__ unsigned g_bar, g_bar2;

// bf16 hi/lo split operands
__device__ __align__(16) bf16 g_haH[M2*HID], g_haL[M2*HID];
__device__ __align__(16) bf16 g_hbH[M2*HID], g_hbL[M2*HID];
__device__ __align__(16) bf16 g_rhH[M2*HID], g_rhL[M2*HID];
__device__ __align__(16) bf16 g_h1H[(size_t)TB * HID], g_h1L[(size_t)TB * HID];
__device__ __align__(16) bf16 g_xeH[(size_t)TB * HID], g_xeL[(size_t)TB * HID];
__device__ __align__(16) bf16 g_WdH[(size_t)VOC * HID], g_WdL[(size_t)VOC * HID];
__device__ __align__(16) bf16 g_Ur0H[HID*HID], g_Ur0L[HID*HID];
__device__ __align__(16) bf16 g_Uf0H[HID*HID], g_Uf0L[HID*HID];
__device__ __align__(16) bf16 g_Uh0H[HID*HID], g_Uh0L[HID*HID];
__device__ __align__(16) bf16 g_Wh1H[HID*HID], g_Wh1L[HID*HID];
__device__ __align__(16) bf16 g_Uh1H[HID*HID], g_Uh1L[HID*HID];
__device__ __align__(16) bf16 g_WUr1H[HID*HID], g_WUr1L[HID*HID];
__device__ __align__(16) bf16 g_WUf1H[HID*HID], g_WUf1L[HID*HID];
__device__ __align__(16) bf16 g_Wr0H[HID*HID], g_Wr0L[HID*HID];
__device__ __align__(16) bf16 g_Wf0H[HID*HID], g_Wf0L[HID*HID];
__device__ __align__(16) bf16 g_Wh0H[HID*HID], g_Wh0L[HID*HID];

__device__ __forceinline__ float sigm(float x) { return 1.0f / (1.0f + expf(-x)); }
__device__ __forceinline__ void wsplit(bf16* H, bf16* L, size_t idx, float v) {
    const bf16 h = __float2bfloat16(v);
    H[idx] = h;
    L[idx] = __float2bfloat16(v - __bfloat162float(h));
}

// ================= mma.sync bf16x3 machinery =================
__device__ __forceinline__ uint32_t s2u(const void* p) {
    uint32_t a;
    asm("{ .reg .u64 t; cvta.to.shared.u64 t, %1; cvt.u32.u64 %0, t; }" : "=r"(a) : "l"(p));
    return a;
}
__device__ __forceinline__ void cpa16(uint32_t dst, const void* src) {
    asm volatile("cp.async.cg.shared.global [%0], [%1], 16;" :: "r"(dst), "l"(src) : "memory");
}
#define SW128(o) ((o) ^ (((o) >> 3) & 0x70))
#define STG 65536
#define MMA_SMEM (2 * STG)

__device__ __forceinline__ void ldm4(uint32_t* r, uint32_t addr) {
    asm volatile("ldmatrix.sync.aligned.m8n8.x4.shared.b16 {%0,%1,%2,%3}, [%4];"
                 : "=r"(r[0]), "=r"(r[1]), "=r"(r[2]), "=r"(r[3]) : "r"(addr));
}
__device__ __forceinline__ void mma16816(float* d, const uint32_t* a, const uint32_t* b) {
    asm volatile(
        "mma.sync.aligned.m16n8k16.row.col.f32.bf16.bf16.f32 "
        "{%0,%1,%2,%3},{%4,%5,%6,%7},{%8,%9},{%0,%1,%2,%3};"
        : "+f"(d[0]), "+f"(d[1]), "+f"(d[2]), "+f"(d[3])
        : "r"(a[0]), "r"(a[1]), "r"(a[2]), "r"(a[3]), "r"(b[0]), "r"(b[1]));
}

// Stage one 64-k chunk: Ah|Al|Bh|Bl, 128 rows x 64 bf16 each, SW128. blockDim=256.
__device__ __forceinline__ void ldchunk(uint32_t stg, const bf16* Ah, const bf16* Al,
                                        const bf16* Bh, const bf16* Bl)
{
    const int tid = threadIdx.x;
    const bf16* srcs[4] = { Ah, Al, Bh, Bl };
    #pragma unroll
    for (int arr = 0; arr < 4; arr++) {
        const uint32_t ab = stg + arr * 16384;
        #pragma unroll
        for (int i = 0; i < 4; i++) {
            const int g = tid + 256 * i;
            const int row = g >> 3, c = g & 7;
            cpa16(ab + SW128(row * 128 + c * 16), srcs[arr] + (size_t)row * HID + c * 8);
        }
    }
    asm volatile("cp.async.commit_group;" ::: "memory");
}

__device__ __forceinline__ void mma_stage(uint32_t stg, float (&acc)[4][4][4])
{
    const int lane = threadIdx.x & 31, wid = threadIdx.x >> 5;
    const int wm = wid >> 2, wn = wid & 3;
    const int rowa = wm * 64 + (lane & 7) + ((lane >> 3) & 1) * 8;
    const int cola_sel = (lane >> 4) * 16;
    const int rowb = wn * 32 + (lane & 7) + ((lane >> 4) & 1) * 8;
    const int colb_sel = ((lane >> 3) & 1) * 16;

    #pragma unroll
    for (int ks = 0; ks < 4; ks++) {
        uint32_t ah[4][4], al[4][4], bhp[2][4], blp[2][4];
        const int cola = ks * 32 + cola_sel;
        #pragma unroll
        for (int mt = 0; mt < 4; mt++) {
            const uint32_t ad = stg + SW128((rowa + mt * 16) * 128 + cola);
            ldm4(ah[mt], ad);
            ldm4(al[mt], ad + 16384);
        }
        const int colb = ks * 32 + colb_sel;
        #pragma unroll
        for (int p = 0; p < 2; p++) {
            const uint32_t bd = stg + 32768 + SW128((rowb + p * 16) * 128 + colb);
            ldm4(bhp[p], bd);
            ldm4(blp[p], bd + 16384);
        }
        #pragma unroll
        for (int mt = 0; mt < 4; mt++) {
            #pragma unroll
            for (int nt = 0; nt < 4; nt++) {
                const uint32_t* bh = &bhp[nt >> 1][(nt & 1) * 2];
                const uint32_t* bl = &blp[nt >> 1][(nt & 1) * 2];
                mma16816(acc[mt][nt], ah[mt], bh);
                mma16816(acc[mt][nt], ah[mt], bl);
                mma16816(acc[mt][nt], al[mt], bh);
            }
        }
    }
}

// Short-K (64 or 128) GEMM for the recurrence phases.
__device__ __forceinline__ void mma_gemm128(const bf16* Ah, const bf16* Al,
                                            const bf16* Bh, const bf16* Bl,
                                            int nchunks, float (&acc)[4][4][4], uint32_t sb)
{
    ldchunk(sb, Ah, Al, Bh, Bl);
    if (nchunks == 2) {
        ldchunk(sb + STG, Ah + 64, Al + 64, Bh + 64, Bl + 64);
        asm volatile("cp.async.wait_group 1;" ::: "memory");
        __syncthreads();
        mma_stage(sb, acc);
        asm volatile("cp.async.wait_group 0;" ::: "memory");
        __syncthreads();
        mma_stage(sb + STG, acc);
    } else {
        asm volatile("cp.async.wait_group 0;" ::: "memory");
        __syncthreads();
        mma_stage(sb, acc);
    }
    __syncthreads();
}

// Full K=1024 GEMM (pre), double-buffered.
__device__ __forceinline__ void mma_k1024(const bf16* Ah, const bf16* Al,
                                          const bf16* Bh, const bf16* Bl,
                                          float (&acc)[4][4][4], uint32_t sb)
{
    ldchunk(sb, Ah, Al, Bh, Bl);
    for (int kc = 0; kc < 16; kc++) {
        const int b = kc & 1;
        if (kc < 15) {
            const int o = (kc + 1) * 64;
            ldchunk(sb + (b ^ 1) * STG, Ah + o, Al + o, Bh + o, Bl + o);
            asm volatile("cp.async.wait_group 1;" ::: "memory");
        } else {
            asm volatile("cp.async.wait_group 0;" ::: "memory");
        }
        __syncthreads();
        mma_stage(sb + b * STG, acc);
        __syncthreads();
    }
}

// ================= persistent recurrence kernel =================
#define REC_CTAS 128

__device__ __forceinline__ void gbar(unsigned nbar) {
    __threadfence();
    __syncthreads();
    if (threadIdx.x == 0) {
        atomicAdd(&g_bar, 1u);
        const unsigned tgt = (unsigned)REC_CTAS * nbar;
        while (*(volatile unsigned*)&g_bar < tgt) __nanosleep(8);
    }
    __syncthreads();
}

__device__ __forceinline__ void stpart_mma(float (&acc)[4][4][4], int ks, int ntile, int Ntot) {
    const int lane = threadIdx.x & 31, wid = threadIdx.x >> 5;
    const int wm = wid >> 2, wn = wid & 3;
    #pragma unroll
    for (int mt = 0; mt < 4; mt++) {
        const int r = wm * 64 + mt * 16 + (lane >> 2);
        #pragma unroll
        for (int nt = 0; nt < 4; nt++) {
            const int c = ntile * 128 + wn * 32 + nt * 8 + (lane & 3) * 2;
            float* base = g_part + ((size_t)ks * M2 + r) * Ntot + c;
            *(float2*)base = make_float2(acc[mt][nt][0], acc[mt][nt][1]);
            *(float2*)(base + (size_t)8 * Ntot) = make_float2(acc[mt][nt][2], acc[mt][nt][3]);
        }
    }
}

__global__ __launch_bounds__(256)
void k_rec(const float* __restrict__ bur0, const float* __restrict__ buf0,
           const float* __restrict__ buh0)
{
    extern __shared__ __align__(128) char dsm[];
    const uint32_t sb = s2u(dsm);
    const int cta = blockIdx.x, tid = threadIdx.x;
    unsigned nbar = 0;

    for (int t = 0; t < T_STEPS; t++) {
        // ---------- p0 GEMM: [r|f]0 = ha @ [Ur0|Uf0].T (split-K 8, K=128) ----------
        {
            const int ntile = cta & 15, ks = cta >> 4, koff = ks * 128;
            const bf16* BH = (ntile < 8) ? g_Ur0H : g_Uf0H;
            const bf16* BL = (ntile < 8) ? g_Ur0L : g_Uf0L;
            const size_t wo = (size_t)((ntile & 7) * 128) * HID + koff;
            float acc[4][4][4] = {};
            mma_gemm128(g_haH + koff, g_haL + koff, BH + wo, BL + wo, 2, acc, sb);
            stpart_mma(acc, ks, ntile, 2048);
        }
        gbar(++nbar);
        // ---------- p0 reduce + sigmoid ----------
        {
            const int m = tid >> 1, b = m & (BATCH - 1);
            const int n = cta * 16 + (tid & 1) * 8;
            float4 s0 = {0,0,0,0}, s1 = {0,0,0,0};
            #pragma unroll
            for (int ks = 0; ks < 8; ks++) {
                const float* p = g_part + ((size_t)ks * M2 + m) * 2048 + n;
                float4 v0 = __ldcg((const float4*)p), v1 = __ldcg((const float4*)(p + 4));
                s0.x += v0.x; s0.y += v0.y; s0.z += v0.z; s0.w += v0.w;
                s1.x += v1.x; s1.y += v1.y; s1.z += v1.z; s1.w += v1.w;
            }
            const int seg = n >> 10, nn = n & 1023;
            const float* bias = seg ? buf0 : bur0;
            float v[8] = {s0.x, s0.y, s0.z, s0.w, s1.x, s1.y, s1.z, s1.w};
            #pragma unroll
            for (int c = 0; c < 8; c++) {
                const float xadd = __ldg(g_xpre + ((size_t)t * BATCH + b) * (3 * HID) + n + c);
                const float g = sigm(v[c] + __ldg(bias + nn + c) + xadd);
                const int idx = m * HID + nn + c;
                if (seg == 0) {
                    const float rh = g * __ldcg(g_ha + idx);
                    wsplit(g_rhH, g_rhL, idx, rh);
                } else {
                    g_f[idx] = g;
                }
            }
        }
        gbar(++nbar);
        // ---------- p1 GEMM: hw0 = rh @ Uh0.T (split-K 16, K=64) ----------
        {
            const int ntile = cta & 7, ks = cta >> 3, koff = ks * 64;
            const size_t wo = (size_t)(ntile * 128) * HID + koff;
            float acc[4][4][4] = {};
            mma_gemm128(g_rhH + koff, g_rhL + koff, g_Uh0H + wo, g_Uh0L + wo, 1, acc, sb);
            stpart_mma(acc, ks, ntile, 1024);
        }
        gbar(++nbar);
        // ---------- p1 reduce + tanh + h update ----------
        {
            const int m = tid >> 1, b = m & (BATCH - 1);
            const int n = cta * 8 + (tid & 1) * 4;
            float4 s = {0,0,0,0};
            #pragma unroll
            for (int ks = 0; ks < 16; ks++) {
                float4 v = __ldcg((const float4*)(g_part + ((size_t)ks * M2 + m) * 1024 + n));
                s.x += v.x; s.y += v.y; s.z += v.z; s.w += v.w;
            }
            float v[4] = {s.x, s.y, s.z, s.w};
            #pragma unroll
            for (int c = 0; c < 4; c++) {
                const float xadd = __ldg(g_xpre + ((size_t)t * BATCH + b) * (3 * HID) + 2 * HID + n + c);
                const float hw = tanhf(v[c] + __ldg(buh0 + n + c) + xadd);
                const int idx = m * HID + n + c;
                const float h = __ldcg(g_ha + idx), f = __ldcg(g_f + idx);
                const float nh = h + f * (hw - h);
                g_hb[idx] = nh;
                wsplit(g_hbH, g_hbL, idx, nh);
            }
        }
        gbar(++nbar);
        // ---------- p2 GEMM: [r|f]1 = hb @ [WUr1|WUf1].T (split-K 8, K=128) ----------
        {
            const int ntile = cta & 15, ks = cta >> 4, koff = ks * 128;
            const bf16* BH = (ntile < 8) ? g_WUr1H : g_WUf1H;
            const bf16* BL = (ntile < 8) ? g_WUr1L : g_WUf1L;
            const size_t wo = (size_t)((ntile & 7) * 128) * HID + koff;
            float acc[4][4][4] = {};
            mma_gemm128(g_hbH + koff, g_hbL + koff, BH + wo, BL + wo, 2, acc, sb);
            stpart_mma(acc, ks, ntile, 2048);
        }
        gbar(++nbar);
        // ---------- p2 reduce + sigmoid ----------
        {
            const int m = tid >> 1;
            const int n = cta * 16 + (tid & 1) * 8;
            float4 s0 = {0,0,0,0}, s1 = {0,0,0,0};
            #pragma unroll
            for (int ks = 0; ks < 8; ks++) {
                const float* p = g_part + ((size_t)ks * M2 + m) * 2048 + n;
                float4 v0 = __ldcg((const float4*)p), v1 = __ldcg((const float4*)(p + 4));
                s0.x += v0.x; s0.y += v0.y; s0.z += v0.z; s0.w += v0.w;
                s1.x += v1.x; s1.y += v1.y; s1.z += v1.z; s1.w += v1.w;
            }
            const int seg = n >> 10, nn = n & 1023;
            float v[8] = {s0.x, s0.y, s0.z, s0.w, s1.x, s1.y, s1.z, s1.w};
            #pragma unroll
            for (int c = 0; c < 8; c++) {
                const int idx = m * HID + nn + c;
                if (seg == 0) {
                    const float r = sigm(v[c] + g_brc[nn + c]);
                    wsplit(g_rhH, g_rhL, idx, r * __ldcg(g_hb + idx));
                } else {
                    g_f[idx] = sigm(v[c] + g_bfc[nn + c]);
                }
            }
        }
        gbar(++nbar);
        // ---------- p3 GEMM: hw1 = hb @ Wh1.T + rh @ Uh1.T (virtual K=2048, split 16) ----------
        {
            const int ntile = cta & 7, ks = cta >> 3;
            float acc[4][4][4] = {};
            if (ks < 8) {
                const int koff = ks * 128;
                const size_t wo = (size_t)(ntile * 128) * HID + koff;
                mma_gemm128(g_hbH + koff, g_hbL + koff, g_Wh1H + wo, g_Wh1L + wo, 2, acc, sb);
            } else {
                const int koff = (ks - 8) * 128;
                const size_t wo = (size_t)(ntile * 128) * HID + koff;
                mma_gemm128(g_rhH + koff, g_rhL + koff, g_Uh1H + wo, g_Uh1L + wo, 2, acc, sb);
            }
            stpart_mma(acc, ks, ntile, 1024);
        }
        gbar(++nbar);
        // ---------- p3 reduce + tanh + h update + h1 stash ----------
        {
            const int m = tid >> 1;
            const int n = cta * 8 + (tid & 1) * 4;
            float4 s = {0,0,0,0};
            #pragma unroll
            for (int ks = 0; ks < 16; ks++) {
                float4 v = __ldcg((const float4*)(g_part + ((size_t)ks * M2 + m) * 1024 + n));
                s.x += v.x; s.y += v.y; s.z += v.z; s.w += v.w;
            }
            float v[4] = {s.x, s.y, s.z, s.w};
            #pragma unroll
            for (int c = 0; c < 4; c++) {
                const float hw = tanhf(v[c] + g_bhc[n + c]);
                const int idx = m * HID + n + c;
                const float h = __ldcg(g_hb + idx), f = __ldcg(g_f + idx);
                const float nh = h + f * (hw - h);
                g_ha[idx] = nh;
                wsplit(g_haH, g_haL, idx, nh);
                if (m >= BATCH) {
                    const size_t o = ((size_t)t * BATCH + (m - BATCH)) * HID + n + c;
                    wsplit(g_h1H, g_h1L, o, nh);
                }
            }
        }
        if (t != T_STEPS - 1) gbar(++nbar);
    }

    __threadfence();
    __syncthreads();
    if (tid == 0) atomicAdd(&g_bar2, 1u);
    if (cta == 0 && tid == 0) {
        while (*(volatile unsigned*)&g_bar2 < (unsigned)REC_CTAS) __nanosleep(8);
        g_bar = 0; g_bar2 = 0;
        __threadfence();
    }
}

// ---------------- setup kernels ----------------
__global__ void k_hinit(const float* __restrict__ hidden) {
    int i = blockIdx.x * blockDim.x + threadIdx.x;
    if (i < M2 * HID) {
        const float v = hidden[i];
        g_ha[i] = v;
        wsplit(g_haH, g_haL, i, v);
    }
}
__global__ void k_hout(float* __restrict__ out) {
    int i = blockIdx.x * blockDim.x + threadIdx.x;
    if (i < M2 * HID) out[i] = g_ha[i];
}
__global__ void k_addb(const float* __restrict__ br1, const float* __restrict__ bur1,
                       const float* __restrict__ bf1, const float* __restrict__ buf1,
                       const float* __restrict__ bh1, const float* __restrict__ buh1) {
    int i = blockIdx.x * blockDim.x + threadIdx.x;
    if (i < HID) {
        g_brc[i] = br1[i] + bur1[i];
        g_bfc[i] = bf1[i] + buf1[i];
        g_bhc[i] = bh1[i] + buh1[i];
    }
}

__device__ __forceinline__ void split4(float4 v, bf16* H, bf16* L, size_t j) {
    const bf16 h0 = __float2bfloat16(v.x), h1 = __float2bfloat16(v.y);
    const bf16 h2 = __float2bfloat16(v.z), h3 = __float2bfloat16(v.w);
    ushort4 hv = { __bfloat16_as_ushort(h0), __bfloat16_as_ushort(h1),
                   __bfloat16_as_ushort(h2), __bfloat16_as_ushort(h3) };
    ((ushort4*)H)[j] = hv;
    ushort4 lv = { __bfloat16_as_ushort(__float2bfloat16(v.x - __bfloat162float(h0))),
                   __bfloat16_as_ushort(__float2bfloat16(v.y - __bfloat162float(h1))),
                   __bfloat16_as_ushort(__float2bfloat16(v.z - __bfloat162float(h2))),
                   __bfloat16_as_ushort(__float2bfloat16(v.w - __bfloat162float(h3))) };
    ((ushort4*)L)[j] = lv;
}

// FIX: destinations resolved in DEVICE code (passing __device__ arrays by name
// from host gives the host shadow address — the rounds-9/11 bug).
__device__ __forceinline__ void seldst(int which, bf16*& H, bf16*& L) {
    switch (which) {
        case 0: H = g_Ur0H;  L = g_Ur0L;  break;
        case 1: H = g_Uf0H;  L = g_Uf0L;  break;
        case 2: H = g_Uh0H;  L = g_Uh0L;  break;
        case 3: H = g_Wh1H;  L = g_Wh1L;  break;
        case 4: H = g_Uh1H;  L = g_Uh1L;  break;
        case 5: H = g_Wr0H;  L = g_Wr0L;  break;
        case 6: H = g_Wf0H;  L = g_Wf0L;  break;
        case 7: H = g_Wh0H;  L = g_Wh0L;  break;
        case 8: H = g_WUr1H; L = g_WUr1L; break;
        default:H = g_WUf1H; L = g_WUf1L; break;
    }
}

__global__ void k_splitmat(const float* __restrict__ src, const float* __restrict__ src2,
                           int which) {
    bf16 *H, *L;
    seldst(which, H, L);
    const size_t n4 = (size_t)HID * HID / 4;
    for (size_t j = (size_t)blockIdx.x * blockDim.x + threadIdx.x; j < n4;
         j += (size_t)gridDim.x * blockDim.x) {
        float4 v = __ldg((const float4*)src + j);
        if (src2) {
            float4 v2 = __ldg((const float4*)src2 + j);
            v.x += v2.x; v.y += v2.y; v.z += v2.z; v.w += v2.w;
        }
        split4(v, H, L, j);
    }
}
__global__ void k_splitW(const float* __restrict__ W) {
    const size_t n4 = (size_t)VOC * HID / 4;
    for (size_t j = (size_t)blockIdx.x * blockDim.x + threadIdx.x; j < n4;
         j += (size_t)gridDim.x * blockDim.x)
        split4(__ldg((const float4*)W + j), g_WdH, g_WdL, j);
}
__global__ void k_gather(const int* __restrict__ tokens, const float* __restrict__ emb) {
    const size_t n4 = (size_t)TB * HID / 4;
    for (size_t j = (size_t)blockIdx.x * blockDim.x + threadIdx.x; j < n4;
         j += (size_t)gridDim.x * blockDim.x) {
        const int row = (int)(j >> 8);
        const int c4  = (int)(j & 255);
        const int tok = __ldg(tokens + row);
        split4(__ldg((const float4*)(emb + (size_t)tok * HID) + c4), g_xeH, g_xeL, j);
    }
}

// ---------------- pre: xpre = xemb @ [Wr0|Wf0|Wh0].T + bias (bf16x3 mma) ----------------
__global__ __launch_bounds__(256)
void k_pre_mma(const float* __restrict__ b0, const float* __restrict__ b1,
               const float* __restrict__ b2)
{
    extern __shared__ __align__(128) char dsm[];
    const uint32_t sb = s2u(dsm);
    const int lane = threadIdx.x & 31, wid = threadIdx.x >> 5;
    const int wm = wid >> 2, wn = wid & 3;
    const int m0 = blockIdx.x * 128, n0g = blockIdx.y * 128;
    const int seg = n0g >> 10, nn0 = n0g & 1023;

    const bf16* BH = (seg == 0) ? g_Wr0H : (seg == 1) ? g_Wf0H : g_Wh0H;
    const bf16* BL = (seg == 0) ? g_Wr0L : (seg == 1) ? g_Wf0L : g_Wh0L;
    const float* bias = (seg == 0) ? b0 : (seg == 1) ? b1 : b2;

    float acc[4][4][4] = {};
    mma_k1024(g_xeH + (size_t)m0 * HID, g_xeL + (size_t)m0 * HID,
              BH + (size_t)nn0 * HID, BL + (size_t)nn0 * HID, acc, sb);

    #pragma unroll
    for (int mt = 0; mt < 4; mt++) {
        const int r = m0 + wm * 64 + mt * 16 + (lane >> 2);
        #pragma unroll
        for (int nt = 0; nt < 4; nt++) {
            const int cl = wn * 32 + nt * 8 + (lane & 3) * 2;
            const float2 bb = *(const float2*)(bias + nn0 + cl);
            float* d0 = g_xpre + (size_t)r * (3 * HID) + n0g + cl;
            *(float2*)d0 = make_float2(acc[mt][nt][0] + bb.x, acc[mt][nt][1] + bb.y);
            float* d1 = d0 + (size_t)8 * (3 * HID);
            *(float2*)d1 = make_float2(acc[mt][nt][2] + bb.x, acc[mt][nt][3] + bb.y);
        }
    }
}

// ---------------- decoder: logits = h1 @ Wdec.T + bdec (bf16x3 mma) ----------------
__global__ __launch_bounds__(256)
void k_dec_mma(const float* __restrict__ bdec, float* __restrict__ out)
{
    extern __shared__ __align__(128) char dsm[];
    const uint32_t sb = s2u(dsm);
    const int lane = threadIdx.x & 31, wid = threadIdx.x >> 5;
    const int wm = wid >> 2, wn = wid & 3;
    const int m0 = blockIdx.x * 128, n0 = blockIdx.y * 128;

    float acc[4][4][4] = {};
    mma_k1024(g_h1H + (size_t)m0 * HID, g_h1L + (size_t)m0 * HID,
              g_WdH + (size_t)n0 * HID, g_WdL + (size_t)n0 * HID, acc, sb);

    #pragma unroll
    for (int mt = 0; mt < 4; mt++) {
        const int r = m0 + wm * 64 + mt * 16 + (lane >> 2);
        #pragma unroll
        for (int nt = 0; nt < 4; nt++) {
            const int cc = n0 + wn * 32 + nt * 8 + (lane & 3) * 2;
            const float2 bb = *(const float2*)(bdec + cc);
            *(float2*)(out + (size_t)r * VOC + cc) =
                make_float2(acc[mt][nt][0] + bb.x, acc[mt][nt][1] + bb.y);
            *(float2*)(out + (size_t)(r + 8) * VOC + cc) =
                make_float2(acc[mt][nt][2] + bb.x, acc[mt][nt][3] + bb.y);
        }
    }
}

// ---------------- launch ----------------
extern "C" void kernel_launch(void* const* d_in, const int* in_sizes, int n_in,
                              void* d_out, int out_size)
{
    const int*   tokens = (const int*)  d_in[0];
    const float* hidden = (const float*)d_in[1];
    const float* emb    = (const float*)d_in[2];
    const float* Wr     = (const float*)d_in[3];
    const float* br     = (const float*)d_in[4];
    const float* Wf     = (const float*)d_in[5];
    const float* bf     = (const float*)d_in[6];
    const float* Wh     = (const float*)d_in[7];
    const float* bh     = (const float*)d_in[8];
    const float* Ur     = (const float*)d_in[9];
    const float* bur    = (const float*)d_in[10];
    const float* Ufw    = (const float*)d_in[11];
    const float* bufw   = (const float*)d_in[12];
    const float* Uh     = (const float*)d_in[13];
    const float* buh    = (const float*)d_in[14];
    const float* Wdec   = (const float*)d_in[15];
    const float* bdec   = (const float*)d_in[16];
    float* out = (float*)d_out;

    const size_t HH = (size_t)HID * HID;

    cudaFuncSetAttribute(k_rec,     cudaFuncAttributeMaxDynamicSharedMemorySize, MMA_SMEM);
    cudaFuncSetAttribute(k_pre_mma, cudaFuncAttributeMaxDynamicSharedMemorySize, MMA_SMEM);
    cudaFuncSetAttribute(k_dec_mma, cudaFuncAttributeMaxDynamicSharedMemorySize, MMA_SMEM);

    k_hinit<<<(M2*HID + 1023) / 1024, 1024>>>(hidden);
    k_addb<<<4, 256>>>(br + HID, bur + HID, bf + HID, bufw + HID, bh + HID, buh + HID);

    // weight splits (destinations selected in device code)
    k_splitmat<<<512, 256>>>(Ur,      nullptr,   0);   // Ur0
    k_splitmat<<<512, 256>>>(Ufw,     nullptr,   1);   // Uf0
    k_splitmat<<<512, 256>>>(Uh,      nullptr,   2);   // Uh0
    k_splitmat<<<512, 256>>>(Wh + HH, nullptr,   3);   // Wh1
    k_splitmat<<<512, 256>>>(Uh + HH, nullptr,   4);   // Uh1
    k_splitmat<<<512, 256>>>(Wr,      nullptr,   5);   // Wr0
    k_splitmat<<<512, 256>>>(Wf,      nullptr,   6);   // Wf0
    k_splitmat<<<512, 256>>>(Wh,      nullptr,   7);   // Wh0
    k_splitmat<<<512, 256>>>(Wr + HH, Ur + HH,   8);   // WUr1 = Wr1+Ur1
    k_splitmat<<<512, 256>>>(Wf + HH, Ufw + HH,  9);   // WUf1 = Wf1+Uf1
    k_splitW<<<2048, 256>>>(Wdec);
    k_gather<<<2048, 256>>>(tokens, emb);

    k_pre_mma<<<dim3(TB/128, 3*HID/128), 256, MMA_SMEM>>>(br, bf, bh);

    k_rec<<<REC_CTAS, 256, MMA_SMEM>>>(bur, bufw, buh);

    k_dec_mma<<<dim3(TB/128, VOC/128), 256, MMA_SMEM>>>(bdec, out);

    const long long logits_elems = (long long)TB * VOC;
    if ((long long)out_size >= logits_elems + (long long)M2 * HID)
        k_hout<<<(M2*HID + 1023) / 1024, 1024>>>(out + logits_elems);
}

// round 14
// speedup vs baseline: 5.2440x; 1.0083x over previous
#include <cuda_runtime.h>
#include <cuda_bf16.h>
#include <cstdint>
#include <math.h>

#define T_STEPS 64
#define BATCH   64
#define HID     1024
#define VOC     32000
#define M2      128
#define TB      4096

typedef unsigned long long ull;
typedef __nv_bfloat16 bf16;

// ---------------- device scratch ----------------
__device__ float g_xpre[(size_t)TB * 3 * HID];
__device__ float g_ha[M2 * HID];                 // h ping (fp32 master)
__device__ float g_hb[M2 * HID];                 // h pong
__device__ float g_f[M2 * HID];                  // f gate
__device__ float g_brc[HID], g_bfc[HID], g_bhc[HID];
__device__ float g_part[2 * 1024 * 1024];
__device__ unsigned g_bar, g_bar2;
__device__ unsigned g_cnt[64];                   // per-tile arrival counters (monotonic per launch)

// bf16 hi/lo split operands
__device__ __align__(16) bf16 g_haH[M2*HID], g_haL[M2*HID];
__device__ __align__(16) bf16 g_hbH[M2*HID], g_hbL[M2*HID];
__device__ __align__(16) bf16 g_rhH[M2*HID], g_rhL[M2*HID];
__device__ __align__(16) bf16 g_h1H[(size_t)TB * HID], g_h1L[(size_t)TB * HID];
__device__ __align__(16) bf16 g_xeH[(size_t)TB * HID], g_xeL[(size_t)TB * HID];
__device__ __align__(16) bf16 g_WdH[(size_t)VOC * HID], g_WdL[(size_t)VOC * HID];
__device__ __align__(16) bf16 g_Ur0H[HID*HID], g_Ur0L[HID*HID];
__device__ __align__(16) bf16 g_Uf0H[HID*HID], g_Uf0L[HID*HID];
__device__ __align__(16) bf16 g_Uh0H[HID*HID], g_Uh0L[HID*HID];
__device__ __align__(16) bf16 g_Wh1H[HID*HID], g_Wh1L[HID*HID];
__device__ __align__(16) bf16 g_Uh1H[HID*HID], g_Uh1L[HID*HID];
__device__ __align__(16) bf16 g_WUr1H[HID*HID], g_WUr1L[HID*HID];
__device__ __align__(16) bf16 g_WUf1H[HID*HID], g_WUf1L[HID*HID];
__device__ __align__(16) bf16 g_Wr0H[HID*HID], g_Wr0L[HID*HID];
__device__ __align__(16) bf16 g_Wf0H[HID*HID], g_Wf0L[HID*HID];
__device__ __align__(16) bf16 g_Wh0H[HID*HID], g_Wh0L[HID*HID];

__device__ __forceinline__ float sigm(float x) { return 1.0f / (1.0f + expf(-x)); }
__device__ __forceinline__ void wsplit(bf16* H, bf16* L, size_t idx, float v) {
    const bf16 h = __float2bfloat16(v);
    H[idx] = h;
    L[idx] = __float2bfloat16(v - __bfloat162float(h));
}

// ================= mma.sync bf16x3 machinery =================
__device__ __forceinline__ uint32_t s2u(const void* p) {
    uint32_t a;
    asm("{ .reg .u64 t; cvta.to.shared.u64 t, %1; cvt.u32.u64 %0, t; }" : "=r"(a) : "l"(p));
    return a;
}
__device__ __forceinline__ void cpa16(uint32_t dst, const void* src) {
    asm volatile("cp.async.cg.shared.global [%0], [%1], 16;" :: "r"(dst), "l"(src) : "memory");
}
#define SW128(o) ((o) ^ (((o) >> 3) & 0x70))
#define STG 65536
#define MMA_SMEM (2 * STG)

__device__ __forceinline__ void ldm4(uint32_t* r, uint32_t addr) {
    asm volatile("ldmatrix.sync.aligned.m8n8.x4.shared.b16 {%0,%1,%2,%3}, [%4];"
                 : "=r"(r[0]), "=r"(r[1]), "=r"(r[2]), "=r"(r[3]) : "r"(addr));
}
__device__ __forceinline__ void mma16816(float* d, const uint32_t* a, const uint32_t* b) {
    asm volatile(
        "mma.sync.aligned.m16n8k16.row.col.f32.bf16.bf16.f32 "
        "{%0,%1,%2,%3},{%4,%5,%6,%7},{%8,%9},{%0,%1,%2,%3};"
        : "+f"(d[0]), "+f"(d[1]), "+f"(d[2]), "+f"(d[3])
        : "r"(a[0]), "r"(a[1]), "r"(a[2]), "r"(a[3]), "r"(b[0]), "r"(b[1]));
}

__device__ __forceinline__ void ldchunk(uint32_t stg, const bf16* Ah, const bf16* Al,
                                        const bf16* Bh, const bf16* Bl)
{
    const int tid = threadIdx.x;
    const bf16* srcs[4] = { Ah, Al, Bh, Bl };
    #pragma unroll
    for (int arr = 0; arr < 4; arr++) {
        const uint32_t ab = stg + arr * 16384;
        #pragma unroll
        for (int i = 0; i < 4; i++) {
            const int g = tid + 256 * i;
            const int row = g >> 3, c = g & 7;
            cpa16(ab + SW128(row * 128 + c * 16), srcs[arr] + (size_t)row * HID + c * 8);
        }
    }
    asm volatile("cp.async.commit_group;" ::: "memory");
}

__device__ __forceinline__ void mma_stage(uint32_t stg, float (&acc)[4][4][4])
{
    const int lane = threadIdx.x & 31, wid = threadIdx.x >> 5;
    const int wm = wid >> 2, wn = wid & 3;
    const int rowa = wm * 64 + (lane & 7) + ((lane >> 3) & 1) * 8;
    const int cola_sel = (lane >> 4) * 16;
    const int rowb = wn * 32 + (lane & 7) + ((lane >> 4) & 1) * 8;
    const int colb_sel = ((lane >> 3) & 1) * 16;

    #pragma unroll
    for (int ks = 0; ks < 4; ks++) {
        uint32_t ah[4][4], al[4][4], bhp[2][4], blp[2][4];
        const int cola = ks * 32 + cola_sel;
        #pragma unroll
        for (int mt = 0; mt < 4; mt++) {
            const uint32_t ad = stg + SW128((rowa + mt * 16) * 128 + cola);
            ldm4(ah[mt], ad);
            ldm4(al[mt], ad + 16384);
        }
        const int colb = ks * 32 + colb_sel;
        #pragma unroll
        for (int p = 0; p < 2; p++) {
            const uint32_t bd = stg + 32768 + SW128((rowb + p * 16) * 128 + colb);
            ldm4(bhp[p], bd);
            ldm4(blp[p], bd + 16384);
        }
        #pragma unroll
        for (int mt = 0; mt < 4; mt++) {
            #pragma unroll
            for (int nt = 0; nt < 4; nt++) {
                const uint32_t* bh = &bhp[nt >> 1][(nt & 1) * 2];
                const uint32_t* bl = &blp[nt >> 1][(nt & 1) * 2];
                mma16816(acc[mt][nt], ah[mt], bh);
                mma16816(acc[mt][nt], ah[mt], bl);
                mma16816(acc[mt][nt], al[mt], bh);
            }
        }
    }
}

__device__ __forceinline__ void mma_gemm128(const bf16* Ah, const bf16* Al,
                                            const bf16* Bh, const bf16* Bl,
                                            int nchunks, float (&acc)[4][4][4], uint32_t sb)
{
    ldchunk(sb, Ah, Al, Bh, Bl);
    if (nchunks == 2) {
        ldchunk(sb + STG, Ah + 64, Al + 64, Bh + 64, Bl + 64);
        asm volatile("cp.async.wait_group 1;" ::: "memory");
        __syncthreads();
        mma_stage(sb, acc);
        asm volatile("cp.async.wait_group 0;" ::: "memory");
        __syncthreads();
        mma_stage(sb + STG, acc);
    } else {
        asm volatile("cp.async.wait_group 0;" ::: "memory");
        __syncthreads();
        mma_stage(sb, acc);
    }
    __syncthreads();
}

__device__ __forceinline__ void mma_k1024(const bf16* Ah, const bf16* Al,
                                          const bf16* Bh, const bf16* Bl,
                                          float (&acc)[4][4][4], uint32_t sb)
{
    ldchunk(sb, Ah, Al, Bh, Bl);
    for (int kc = 0; kc < 16; kc++) {
        const int b = kc & 1;
        if (kc < 15) {
            const int o = (kc + 1) * 64;
            ldchunk(sb + (b ^ 1) * STG, Ah + o, Al + o, Bh + o, Bl + o);
            asm volatile("cp.async.wait_group 1;" ::: "memory");
        } else {
            asm volatile("cp.async.wait_group 0;" ::: "memory");
        }
        __syncthreads();
        mma_stage(sb + b * STG, acc);
        __syncthreads();
    }
}

// ================= persistent recurrence kernel =================
#define REC_CTAS 128

__device__ __forceinline__ void gbar(unsigned nbar) {
    __threadfence();
    __syncthreads();
    if (threadIdx.x == 0) {
        atomicAdd(&g_bar, 1u);
        const unsigned tgt = (unsigned)REC_CTAS * nbar;
        while (*(volatile unsigned*)&g_bar < tgt) __nanosleep(8);
    }
    __syncthreads();
}

// group mini-barrier: signal my producer tile, wait for my reduce tile's group
__device__ __forceinline__ void grpbar(int sig_slot, int wait_slot, unsigned tgt) {
    __threadfence();
    __syncthreads();
    if (threadIdx.x == 0) {
        atomicAdd(&g_cnt[sig_slot], 1u);
        while (*(volatile unsigned*)&g_cnt[wait_slot] < tgt) __nanosleep(8);
    }
    __syncthreads();
}

__device__ __forceinline__ void stpart_mma(float (&acc)[4][4][4], int ks, int ntile, int Ntot) {
    const int lane = threadIdx.x & 31, wid = threadIdx.x >> 5;
    const int wm = wid >> 2, wn = wid & 3;
    #pragma unroll
    for (int mt = 0; mt < 4; mt++) {
        const int r = wm * 64 + mt * 16 + (lane >> 2);
        #pragma unroll
        for (int nt = 0; nt < 4; nt++) {
            const int c = ntile * 128 + wn * 32 + nt * 8 + (lane & 3) * 2;
            float* base = g_part + ((size_t)ks * M2 + r) * Ntot + c;
            *(float2*)base = make_float2(acc[mt][nt][0], acc[mt][nt][1]);
            *(float2*)(base + (size_t)8 * Ntot) = make_float2(acc[mt][nt][2], acc[mt][nt][3]);
        }
    }
}

__global__ __launch_bounds__(256)
void k_rec(const float* __restrict__ bur0, const float* __restrict__ buf0,
           const float* __restrict__ buh0)
{
    extern __shared__ __align__(128) char dsm[];
    const uint32_t sb = s2u(dsm);
    const int cta = blockIdx.x, tid = threadIdx.x;
    unsigned nbar = 0;

    for (int t = 0; t < T_STEPS; t++) {
        // ========== p0: [r|f]0 = ha @ [Ur0|Uf0].T (split-K 8, K=128) ==========
        {
            const int ntile = cta & 15, ks = cta >> 4, koff = ks * 128;
            const bf16* BH = (ntile < 8) ? g_Ur0H : g_Uf0H;
            const bf16* BL = (ntile < 8) ? g_Ur0L : g_Uf0L;
            const size_t wo = (size_t)((ntile & 7) * 128) * HID + koff;
            float acc[4][4][4] = {};
            mma_gemm128(g_haH + koff, g_haL + koff, BH + wo, BL + wo, 2, acc, sb);
            stpart_mma(acc, ks, ntile, 2048);
        }
        grpbar(cta & 15, cta >> 3, (unsigned)(t * 8 + 8));
        // ---- p0 reduce + sigmoid (slice n = cta*16) ----
        {
            const int m = tid >> 1, b = m & (BATCH - 1);
            const int n = cta * 16 + (tid & 1) * 8;
            float4 s0 = {0,0,0,0}, s1 = {0,0,0,0};
            #pragma unroll
            for (int ks = 0; ks < 8; ks++) {
                const float* p = g_part + ((size_t)ks * M2 + m) * 2048 + n;
                float4 v0 = __ldcg((const float4*)p), v1 = __ldcg((const float4*)(p + 4));
                s0.x += v0.x; s0.y += v0.y; s0.z += v0.z; s0.w += v0.w;
                s1.x += v1.x; s1.y += v1.y; s1.z += v1.z; s1.w += v1.w;
            }
            const int seg = n >> 10, nn = n & 1023;
            const float* bias = seg ? buf0 : bur0;
            float v[8] = {s0.x, s0.y, s0.z, s0.w, s1.x, s1.y, s1.z, s1.w};
            #pragma unroll
            for (int c = 0; c < 8; c++) {
                const float xadd = __ldg(g_xpre + ((size_t)t * BATCH + b) * (3 * HID) + n + c);
                const float g = sigm(v[c] + __ldg(bias + nn + c) + xadd);
                const int idx = m * HID + nn + c;
                if (seg == 0) {
                    const float rh = g * __ldcg(g_ha + idx);
                    wsplit(g_rhH, g_rhL, idx, rh);
                } else {
                    g_f[idx] = g;
                }
            }
        }
        gbar(++nbar);
        // ========== p1: hw0 = rh @ Uh0.T (split-K 16, K=64) ==========
        {
            const int ntile = cta & 7, ks = cta >> 3, koff = ks * 64;
            const size_t wo = (size_t)(ntile * 128) * HID + koff;
            float acc[4][4][4] = {};
            mma_gemm128(g_rhH + koff, g_rhL + koff, g_Uh0H + wo, g_Uh0L + wo, 1, acc, sb);
            stpart_mma(acc, ks, ntile, 1024);
        }
        grpbar(16 + (cta & 7), 16 + (cta >> 4), (unsigned)(t * 16 + 16));
        // ---- p1 reduce + tanh + h update (slice n = cta*8) ----
        {
            const int m = tid >> 1, b = m & (BATCH - 1);
            const int n = cta * 8 + (tid & 1) * 4;
            float4 s = {0,0,0,0};
            #pragma unroll
            for (int ks = 0; ks < 16; ks++) {
                float4 v = __ldcg((const float4*)(g_part + ((size_t)ks * M2 + m) * 1024 + n));
                s.x += v.x; s.y += v.y; s.z += v.z; s.w += v.w;
            }
            float v[4] = {s.x, s.y, s.z, s.w};
            #pragma unroll
            for (int c = 0; c < 4; c++) {
                const float xadd = __ldg(g_xpre + ((size_t)t * BATCH + b) * (3 * HID) + 2 * HID + n + c);
                const float hw = tanhf(v[c] + __ldg(buh0 + n + c) + xadd);
                const int idx = m * HID + n + c;
                const float h = __ldcg(g_ha + idx), f = __ldcg(g_f + idx);
                const float nh = h + f * (hw - h);
                g_hb[idx] = nh;
                wsplit(g_hbH, g_hbL, idx, nh);
            }
        }
        gbar(++nbar);
        // ========== p2: [r|f]1 = hb @ [WUr1|WUf1].T (split-K 8, K=128) ==========
        {
            const int ntile = cta & 15, ks = cta >> 4, koff = ks * 128;
            const bf16* BH = (ntile < 8) ? g_WUr1H : g_WUf1H;
            const bf16* BL = (ntile < 8) ? g_WUr1L : g_WUf1L;
            const size_t wo = (size_t)((ntile & 7) * 128) * HID + koff;
            float acc[4][4][4] = {};
            mma_gemm128(g_hbH + koff, g_hbL + koff, BH + wo, BL + wo, 2, acc, sb);
            stpart_mma(acc, ks, ntile, 2048);
        }
        grpbar(32 + (cta & 15), 32 + (cta >> 3), (unsigned)(t * 8 + 8));
        // ---- p2 reduce + sigmoid ----
        {
            const int m = tid >> 1;
            const int n = cta * 16 + (tid & 1) * 8;
            float4 s0 = {0,0,0,0}, s1 = {0,0,0,0};
            #pragma unroll
            for (int ks = 0; ks < 8; ks++) {
                const float* p = g_part + ((size_t)ks * M2 + m) * 2048 + n;
                float4 v0 = __ldcg((const float4*)p), v1 = __ldcg((const float4*)(p + 4));
                s0.x += v0.x; s0.y += v0.y; s0.z += v0.z; s0.w += v0.w;
                s1.x += v1.x; s1.y += v1.y; s1.z += v1.z; s1.w += v1.w;
            }
            const int seg = n >> 10, nn = n & 1023;
            float v[8] = {s0.x, s0.y, s0.z, s0.w, s1.x, s1.y, s1.z, s1.w};
            #pragma unroll
            for (int c = 0; c < 8; c++) {
                const int idx = m * HID + nn + c;
                if (seg == 0) {
                    const float r = sigm(v[c] + g_brc[nn + c]);
                    wsplit(g_rhH, g_rhL, idx, r * __ldcg(g_hb + idx));
                } else {
                    g_f[idx] = sigm(v[c] + g_bfc[nn + c]);
                }
            }
        }
        gbar(++nbar);
        // ========== p3: hw1 = hb @ Wh1.T + rh @ Uh1.T (virtual K=2048, split 16) ==========
        {
            const int ntile = cta & 7, ks = cta >> 3;
            float acc[4][4][4] = {};
            if (ks < 8) {
                const int koff = ks * 128;
                const size_t wo = (size_t)(ntile * 128) * HID + koff;
                mma_gemm128(g_hbH + koff, g_hbL + koff, g_Wh1H + wo, g_Wh1L + wo, 2, acc, sb);
            } else {
                const int koff = (ks - 8) * 128;
                const size_t wo = (size_t)(ntile * 128) * HID + koff;
                mma_gemm128(g_rhH + koff, g_rhL + koff, g_Uh1H + wo, g_Uh1L + wo, 2, acc, sb);
            }
            stpart_mma(acc, ks, ntile, 1024);
        }
        grpbar(48 + (cta & 7), 48 + (cta >> 4), (unsigned)(t * 16 + 16));
        // ---- p3 reduce + tanh + h update + h1 stash ----
        {
            const int m = tid >> 1;
            const int n = cta * 8 + (tid & 1) * 4;
            float4 s = {0,0,0,0};
            #pragma unroll
            for (int ks = 0; ks < 16; ks++) {
                float4 v = __ldcg((const float4*)(g_part + ((size_t)ks * M2 + m) * 1024 + n));
                s.x += v.x; s.y += v.y; s.z += v.z; s.w += v.w;
            }
            float v[4] = {s.x, s.y, s.z, s.w};
            #pragma unroll
            for (int c = 0; c < 4; c++) {
                const float hw = tanhf(v[c] + g_bhc[n + c]);
                const int idx = m * HID + n + c;
                const float h = __ldcg(g_hb + idx), f = __ldcg(g_f + idx);
                const float nh = h + f * (hw - h);
                g_ha[idx] = nh;
                wsplit(g_haH, g_haL, idx, nh);
                if (m >= BATCH) {
                    const size_t o = ((size_t)t * BATCH + (m - BATCH)) * HID + n + c;
                    wsplit(g_h1H, g_h1L, o, nh);
                }
            }
        }
        if (t != T_STEPS - 1) gbar(++nbar);
    }

    // drain + reset all coordination state for the next graph replay
    __threadfence();
    __syncthreads();
    if (tid == 0) atomicAdd(&g_bar2, 1u);
    if (cta == 0) {
        if (tid == 0) {
            while (*(volatile unsigned*)&g_bar2 < (unsigned)REC_CTAS) __nanosleep(8);
        }
        __syncthreads();
        if (tid < 64) g_cnt[tid] = 0;
        if (tid == 0) { g_bar = 0; g_bar2 = 0; }
        __threadfence();
    }
}

// ---------------- setup kernels ----------------
__global__ void k_hinit(const float* __restrict__ hidden) {
    int i = blockIdx.x * blockDim.x + threadIdx.x;
    if (i < M2 * HID) {
        const float v = hidden[i];
        g_ha[i] = v;
        wsplit(g_haH, g_haL, i, v);
    }
}
__global__ void k_hout(float* __restrict__ out) {
    int i = blockIdx.x * blockDim.x + threadIdx.x;
    if (i < M2 * HID) out[i] = g_ha[i];
}
__global__ void k_addb(const float* __restrict__ br1, const float* __restrict__ bur1,
                       const float* __restrict__ bf1, const float* __restrict__ buf1,
                       const float* __restrict__ bh1, const float* __restrict__ buh1) {
    int i = blockIdx.x * blockDim.x + threadIdx.x;
    if (i < HID) {
        g_brc[i] = br1[i] + bur1[i];
        g_bfc[i] = bf1[i] + buf1[i];
        g_bhc[i] = bh1[i] + buh1[i];
    }
}

__device__ __forceinline__ void split4(float4 v, bf16* H, bf16* L, size_t j) {
    const bf16 h0 = __float2bfloat16(v.x), h1 = __float2bfloat16(v.y);
    const bf16 h2 = __float2bfloat16(v.z), h3 = __float2bfloat16(v.w);
    ushort4 hv = { __bfloat16_as_ushort(h0), __bfloat16_as_ushort(h1),
                   __bfloat16_as_ushort(h2), __bfloat16_as_ushort(h3) };
    ((ushort4*)H)[j] = hv;
    ushort4 lv = { __bfloat16_as_ushort(__float2bfloat16(v.x - __bfloat162float(h0))),
                   __bfloat16_as_ushort(__float2bfloat16(v.y - __bfloat162float(h1))),
                   __bfloat16_as_ushort(__float2bfloat16(v.z - __bfloat162float(h2))),
                   __bfloat16_as_ushort(__float2bfloat16(v.w - __bfloat162float(h3))) };
    ((ushort4*)L)[j] = lv;
}

// One launch splits all 10 recurrence/pre weight matrices (grid.y selects).
// All destination globals resolved in DEVICE code.
__global__ void k_splitall(const float* __restrict__ Wr, const float* __restrict__ Wf,
                           const float* __restrict__ Wh, const float* __restrict__ Ur,
                           const float* __restrict__ Ufw, const float* __restrict__ Uh)
{
    const size_t HH = (size_t)HID * HID;
    const float *src, *src2 = nullptr;
    bf16 *H, *L;
    switch (blockIdx.y) {
        case 0: src = Ur;       H = g_Ur0H;  L = g_Ur0L;  break;
        case 1: src = Ufw;      H = g_Uf0H;  L = g_Uf0L;  break;
        case 2: src = Uh;       H = g_Uh0H;  L = g_Uh0L;  break;
        case 3: src = Wh + HH;  H = g_Wh1H;  L = g_Wh1L;  break;
        case 4: src = Uh + HH;  H = g_Uh1H;  L = g_Uh1L;  break;
        case 5: src = Wr;       H = g_Wr0H;  L = g_Wr0L;  break;
        case 6: src = Wf;       H = g_Wf0H;  L = g_Wf0L;  break;
        case 7: src = Wh;       H = g_Wh0H;  L = g_Wh0L;  break;
        case 8: src = Wr + HH;  src2 = Ur + HH;  H = g_WUr1H; L = g_WUr1L; break;
        default:src = Wf + HH;  src2 = Ufw + HH; H = g_WUf1H; L = g_WUf1L; break;
    }
    const size_t n4 = HH / 4;
    for (size_t j = (size_t)blockIdx.x * blockDim.x + threadIdx.x; j < n4;
         j += (size_t)gridDim.x * blockDim.x) {
        float4 v = __ldg((const float4*)src + j);
        if (src2) {
            float4 v2 = __ldg((const float4*)src2 + j);
            v.x += v2.x; v.y += v2.y; v.z += v2.z; v.w += v2.w;
        }
        split4(v, H, L, j);
    }
}

__global__ void k_splitW(const float* __restrict__ W) {
    const size_t n4 = (size_t)VOC * HID / 4;
    for (size_t j = (size_t)blockIdx.x * blockDim.x + threadIdx.x; j < n4;
         j += (size_t)gridDim.x * blockDim.x)
        split4(__ldg((const float4*)W + j), g_WdH, g_WdL, j);
}
__global__ void k_gather(const int* __restrict__ tokens, const float* __restrict__ emb) {
    const size_t n4 = (size_t)TB * HID / 4;
    for (size_t j = (size_t)blockIdx.x * blockDim.x + threadIdx.x; j < n4;
         j += (size_t)gridDim.x * blockDim.x) {
        const int row = (int)(j >> 8);
        const int c4  = (int)(j & 255);
        const int tok = __ldg(tokens + row);
        split4(__ldg((const float4*)(emb + (size_t)tok * HID) + c4), g_xeH, g_xeL, j);
    }
}

// ---------------- pre: xpre = xemb @ [Wr0|Wf0|Wh0].T + bias (bf16x3 mma) ----------------
__global__ __launch_bounds__(256)
void k_pre_mma(const float* __restrict__ b0, const float* __restrict__ b1,
               const float* __restrict__ b2)
{
    extern __shared__ __align__(128) char dsm[];
    const uint32_t sb = s2u(dsm);
    const int lane = threadIdx.x & 31, wid = threadIdx.x >> 5;
    const int wm = wid >> 2, wn = wid & 3;
    const int m0 = blockIdx.x * 128, n0g = blockIdx.y * 128;
    const int seg = n0g >> 10, nn0 = n0g & 1023;

    const bf16* BH = (seg == 0) ? g_Wr0H : (seg == 1) ? g_Wf0H : g_Wh0H;
    const bf16* BL = (seg == 0) ? g_Wr0L : (seg == 1) ? g_Wf0L : g_Wh0L;
    const float* bias = (seg == 0) ? b0 : (seg == 1) ? b1 : b2;

    float acc[4][4][4] = {};
    mma_k1024(g_xeH + (size_t)m0 * HID, g_xeL + (size_t)m0 * HID,
              BH + (size_t)nn0 * HID, BL + (size_t)nn0 * HID, acc, sb);

    #pragma unroll
    for (int mt = 0; mt < 4; mt++) {
        const int r = m0 + wm * 64 + mt * 16 + (lane >> 2);
        #pragma unroll
        for (int nt = 0; nt < 4; nt++) {
            const int cl = wn * 32 + nt * 8 + (lane & 3) * 2;
            const float2 bb = *(const float2*)(bias + nn0 + cl);
            float* d0 = g_xpre + (size_t)r * (3 * HID) + n0g + cl;
            *(float2*)d0 = make_float2(acc[mt][nt][0] + bb.x, acc[mt][nt][1] + bb.y);
            float* d1 = d0 + (size_t)8 * (3 * HID);
            *(float2*)d1 = make_float2(acc[mt][nt][2] + bb.x, acc[mt][nt][3] + bb.y);
        }
    }
}

// ---------------- decoder: logits = h1 @ Wdec.T + bdec (bf16x3 mma) ----------------
__global__ __launch_bounds__(256)
void k_dec_mma(const float* __restrict__ bdec, float* __restrict__ out)
{
    extern __shared__ __align__(128) char dsm[];
    const uint32_t sb = s2u(dsm);
    const int lane = threadIdx.x & 31, wid = threadIdx.x >> 5;
    const int wm = wid >> 2, wn = wid & 3;
    const int m0 = blockIdx.x * 128, n0 = blockIdx.y * 128;

    float acc[4][4][4] = {};
    mma_k1024(g_h1H + (size_t)m0 * HID, g_h1L + (size_t)m0 * HID,
              g_WdH + (size_t)n0 * HID, g_WdL + (size_t)n0 * HID, acc, sb);

    #pragma unroll
    for (int mt = 0; mt < 4; mt++) {
        const int r = m0 + wm * 64 + mt * 16 + (lane >> 2);
        #pragma unroll
        for (int nt = 0; nt < 4; nt++) {
            const int cc = n0 + wn * 32 + nt * 8 + (lane & 3) * 2;
            const float2 bb = *(const float2*)(bdec + cc);
            *(float2*)(out + (size_t)r * VOC + cc) =
                make_float2(acc[mt][nt][0] + bb.x, acc[mt][nt][1] + bb.y);
            *(float2*)(out + (size_t)(r + 8) * VOC + cc) =
                make_float2(acc[mt][nt][2] + bb.x, acc[mt][nt][3] + bb.y);
        }
    }
}

// ---------------- launch ----------------
extern "C" void kernel_launch(void* const* d_in, const int* in_sizes, int n_in,
                              void* d_out, int out_size)
{
    const int*   tokens = (const int*)  d_in[0];
    const float* hidden = (const float*)d_in[1];
    const float* emb    = (const float*)d_in[2];
    const float* Wr     = (const float*)d_in[3];
    const float* br     = (const float*)d_in[4];
    const float* Wf     = (const float*)d_in[5];
    const float* bf     = (const float*)d_in[6];
    const float* Wh     = (const float*)d_in[7];
    const float* bh     = (const float*)d_in[8];
    const float* Ur     = (const float*)d_in[9];
    const float* bur    = (const float*)d_in[10];
    const float* Ufw    = (const float*)d_in[11];
    const float* bufw   = (const float*)d_in[12];
    const float* Uh     = (const float*)d_in[13];
    const float* buh    = (const float*)d_in[14];
    const float* Wdec   = (const float*)d_in[15];
    const float* bdec   = (const float*)d_in[16];
    float* out = (float*)d_out;

    cudaFuncSetAttribute(k_rec,     cudaFuncAttributeMaxDynamicSharedMemorySize, MMA_SMEM);
    cudaFuncSetAttribute(k_pre_mma, cudaFuncAttributeMaxDynamicSharedMemorySize, MMA_SMEM);
    cudaFuncSetAttribute(k_dec_mma, cudaFuncAttributeMaxDynamicSharedMemorySize, MMA_SMEM);

    k_hinit<<<(M2*HID + 1023) / 1024, 1024>>>(hidden);
    k_addb<<<4, 256>>>(br + HID, bur + HID, bf + HID, bufw + HID, bh + HID, buh + HID);

    k_splitall<<<dim3(128, 10), 256>>>(Wr, Wf, Wh, Ur, Ufw, Uh);
    k_splitW<<<2048, 256>>>(Wdec);
    k_gather<<<2048, 256>>>(tokens, emb);

    k_pre_mma<<<dim3(TB/128, 3*HID/128), 256, MMA_SMEM>>>(br, bf, bh);

    k_rec<<<REC_CTAS, 256, MMA_SMEM>>>(bur, bufw, buh);

    k_dec_mma<<<dim3(TB/128, VOC/128), 256, MMA_SMEM>>>(bdec, out);

    const long long logits_elems = (long long)TB * VOC;
    if ((long long)out_size >= logits_elems + (long long)M2 * HID)
        k_hout<<<(M2*HID + 1023) / 1024, 1024>>>(out + logits_elems);
}

// round 15
// speedup vs baseline: 5.4272x; 1.0349x over previous
#include <cuda_runtime.h>
#include <cuda_bf16.h>
#include <cstdint>
#include <math.h>

#define T_STEPS 64
#define BATCH   64
#define HID     1024
#define VOC     32000
#define M2      128
#define TB      4096

typedef unsigned long long ull;
typedef __nv_bfloat16 bf16;

// ---------------- device scratch ----------------
__device__ float g_xpre[(size_t)TB * 3 * HID];
__device__ float g_ha[M2 * HID];                 // h ping (fp32 master)
__device__ float g_hb[M2 * HID];                 // h pong
__device__ float g_f[M2 * HID];                  // f gate
__device__ float g_brc[HID], g_bfc[HID], g_bhc[HID];
__device__ float g_part[2 * 1024 * 1024];
__device__ unsigned g_bar, g_bar2;
__device__ unsigned g_cnt[64];                   // per-tile arrival counters (monotonic per launch)

// bf16 hi/lo split operands
__device__ __align__(16) bf16 g_haH[M2*HID], g_haL[M2*HID];
__device__ __align__(16) bf16 g_hbH[M2*HID], g_hbL[M2*HID];
__device__ __align__(16) bf16 g_rhH[M2*HID], g_rhL[M2*HID];
__device__ __align__(16) bf16 g_h1H[(size_t)TB * HID], g_h1L[(size_t)TB * HID];
__device__ __align__(16) bf16 g_xeH[(size_t)TB * HID], g_xeL[(size_t)TB * HID];
__device__ __align__(16) bf16 g_WdH[(size_t)VOC * HID], g_WdL[(size_t)VOC * HID];
__device__ __align__(16) bf16 g_Ur0H[HID*HID], g_Ur0L[HID*HID];
__device__ __align__(16) bf16 g_Uf0H[HID*HID], g_Uf0L[HID*HID];
__device__ __align__(16) bf16 g_Uh0H[HID*HID], g_Uh0L[HID*HID];
__device__ __align__(16) bf16 g_Wh1H[HID*HID], g_Wh1L[HID*HID];
__device__ __align__(16) bf16 g_Uh1H[HID*HID], g_Uh1L[HID*HID];
__device__ __align__(16) bf16 g_WUr1H[HID*HID], g_WUr1L[HID*HID];
__device__ __align__(16) bf16 g_WUf1H[HID*HID], g_WUf1L[HID*HID];
__device__ __align__(16) bf16 g_Wr0H[HID*HID], g_Wr0L[HID*HID];
__device__ __align__(16) bf16 g_Wf0H[HID*HID], g_Wf0L[HID*HID];
__device__ __align__(16) bf16 g_Wh0H[HID*HID], g_Wh0L[HID*HID];

__device__ __forceinline__ float sigm(float x) { return 1.0f / (1.0f + expf(-x)); }
__device__ __forceinline__ void wsplit(bf16* H, bf16* L, size_t idx, float v) {
    const bf16 h = __float2bfloat16(v);
    H[idx] = h;
    L[idx] = __float2bfloat16(v - __bfloat162float(h));
}

// -------- release/acquire primitives (replace full threadfence in barriers) --------
__device__ __forceinline__ void atomAddRel(unsigned* p) {
    unsigned old;
    asm volatile("atom.add.release.gpu.u32 %0, [%1], 1;" : "=r"(old) : "l"(p) : "memory");
}
__device__ __forceinline__ unsigned ldAcq(unsigned* p) {
    unsigned v;
    asm volatile("ld.acquire.gpu.u32 %0, [%1];" : "=r"(v) : "l"(p) : "memory");
    return v;
}

// ================= mma.sync bf16x3 machinery =================
__device__ __forceinline__ uint32_t s2u(const void* p) {
    uint32_t a;
    asm("{ .reg .u64 t; cvta.to.shared.u64 t, %1; cvt.u32.u64 %0, t; }" : "=r"(a) : "l"(p));
    return a;
}
__device__ __forceinline__ void cpa16(uint32_t dst, const void* src) {
    asm volatile("cp.async.cg.shared.global [%0], [%1], 16;" :: "r"(dst), "l"(src) : "memory");
}
#define SW128(o) ((o) ^ (((o) >> 3) & 0x70))
#define STG 65536
#define REC_SMEM (2 * STG)
#define DEC_SMEM (3 * STG)

__device__ __forceinline__ void ldm4(uint32_t* r, uint32_t addr) {
    asm volatile("ldmatrix.sync.aligned.m8n8.x4.shared.b16 {%0,%1,%2,%3}, [%4];"
                 : "=r"(r[0]), "=r"(r[1]), "=r"(r[2]), "=r"(r[3]) : "r"(addr));
}
__device__ __forceinline__ void mma16816(float* d, const uint32_t* a, const uint32_t* b) {
    asm volatile(
        "mma.sync.aligned.m16n8k16.row.col.f32.bf16.bf16.f32 "
        "{%0,%1,%2,%3},{%4,%5,%6,%7},{%8,%9},{%0,%1,%2,%3};"
        : "+f"(d[0]), "+f"(d[1]), "+f"(d[2]), "+f"(d[3])
        : "r"(a[0]), "r"(a[1]), "r"(a[2]), "r"(a[3]), "r"(b[0]), "r"(b[1]));
}

__device__ __forceinline__ void ldchunk(uint32_t stg, const bf16* Ah, const bf16* Al,
                                        const bf16* Bh, const bf16* Bl)
{
    const int tid = threadIdx.x;
    const bf16* srcs[4] = { Ah, Al, Bh, Bl };
    #pragma unroll
    for (int arr = 0; arr < 4; arr++) {
        const uint32_t ab = stg + arr * 16384;
        #pragma unroll
        for (int i = 0; i < 4; i++) {
            const int g = tid + 256 * i;
            const int row = g >> 3, c = g & 7;
            cpa16(ab + SW128(row * 128 + c * 16), srcs[arr] + (size_t)row * HID + c * 8);
        }
    }
    asm volatile("cp.async.commit_group;" ::: "memory");
}

__device__ __forceinline__ void mma_stage(uint32_t stg, float (&acc)[4][4][4])
{
    const int lane = threadIdx.x & 31, wid = threadIdx.x >> 5;
    const int wm = wid >> 2, wn = wid & 3;
    const int rowa = wm * 64 + (lane & 7) + ((lane >> 3) & 1) * 8;
    const int cola_sel = (lane >> 4) * 16;
    const int rowb = wn * 32 + (lane & 7) + ((lane >> 4) & 1) * 8;
    const int colb_sel = ((lane >> 3) & 1) * 16;

    #pragma unroll
    for (int ks = 0; ks < 4; ks++) {
        uint32_t ah[4][4], al[4][4], bhp[2][4], blp[2][4];
        const int cola = ks * 32 + cola_sel;
        #pragma unroll
        for (int mt = 0; mt < 4; mt++) {
            const uint32_t ad = stg + SW128((rowa + mt * 16) * 128 + cola);
            ldm4(ah[mt], ad);
            ldm4(al[mt], ad + 16384);
        }
        const int colb = ks * 32 + colb_sel;
        #pragma unroll
        for (int p = 0; p < 2; p++) {
            const uint32_t bd = stg + 32768 + SW128((rowb + p * 16) * 128 + colb);
            ldm4(bhp[p], bd);
            ldm4(blp[p], bd + 16384);
        }
        #pragma unroll
        for (int mt = 0; mt < 4; mt++) {
            #pragma unroll
            for (int nt = 0; nt < 4; nt++) {
                const uint32_t* bh = &bhp[nt >> 1][(nt & 1) * 2];
                const uint32_t* bl = &blp[nt >> 1][(nt & 1) * 2];
                mma16816(acc[mt][nt], ah[mt], bh);
                mma16816(acc[mt][nt], ah[mt], bl);
                mma16816(acc[mt][nt], al[mt], bh);
            }
        }
    }
}

// Short-K (64 or 128) GEMM for the recurrence phases (proven 2-stage path).
__device__ __forceinline__ void mma_gemm128(const bf16* Ah, const bf16* Al,
                                            const bf16* Bh, const bf16* Bl,
                                            int nchunks, float (&acc)[4][4][4], uint32_t sb)
{
    ldchunk(sb, Ah, Al, Bh, Bl);
    if (nchunks == 2) {
        ldchunk(sb + STG, Ah + 64, Al + 64, Bh + 64, Bl + 64);
        asm volatile("cp.async.wait_group 1;" ::: "memory");
        __syncthreads();
        mma_stage(sb, acc);
        asm volatile("cp.async.wait_group 0;" ::: "memory");
        __syncthreads();
        mma_stage(sb + STG, acc);
    } else {
        asm volatile("cp.async.wait_group 0;" ::: "memory");
        __syncthreads();
        mma_stage(sb, acc);
    }
    __syncthreads();
}

// Full K=1024 GEMM (pre/decoder): 3-stage cp.async ring, ONE syncthreads/chunk.
__device__ __forceinline__ void mma_k1024(const bf16* Ah, const bf16* Al,
                                          const bf16* Bh, const bf16* Bl,
                                          float (&acc)[4][4][4], uint32_t sb)
{
    ldchunk(sb,        Ah,      Al,      Bh,      Bl);
    ldchunk(sb + STG,  Ah + 64, Al + 64, Bh + 64, Bl + 64);
    #pragma unroll 1
    for (int kc = 0; kc < 16; kc++) {
        if (kc < 15) asm volatile("cp.async.wait_group 1;" ::: "memory");
        else         asm volatile("cp.async.wait_group 0;" ::: "memory");
        // this sync both (a) publishes arrived stage kc to all warps and
        // (b) certifies all warps consumed stage kc-1, freeing buffer (kc+2)%3
        __syncthreads();
        if (kc + 2 < 16) {
            const int o = (kc + 2) * 64;
            ldchunk(sb + ((kc + 2) % 3) * STG, Ah + o, Al + o, Bh + o, Bl + o);
        }
        mma_stage(sb + (kc % 3) * STG, acc);
    }
}

// ================= persistent recurrence kernel =================
#define REC_CTAS 128

__device__ __forceinline__ void gbar(unsigned nbar) {
    __syncthreads();
    if (threadIdx.x == 0) {
        atomAddRel(&g_bar);
        const unsigned tgt = (unsigned)REC_CTAS * nbar;
        while (ldAcq(&g_bar) < tgt) __nanosleep(8);
    }
    __syncthreads();
}

// group mini-barrier: signal my producer tile, wait for my reduce tile's group
__device__ __forceinline__ void grpbar(int sig_slot, int wait_slot, unsigned tgt) {
    __syncthreads();
    if (threadIdx.x == 0) {
        atomAddRel(&g_cnt[sig_slot]);
        while (ldAcq(&g_cnt[wait_slot]) < tgt) __nanosleep(8);
    }
    __syncthreads();
}

__device__ __forceinline__ void stpart_mma(float (&acc)[4][4][4], int ks, int ntile, int Ntot) {
    const int lane = threadIdx.x & 31, wid = threadIdx.x >> 5;
    const int wm = wid >> 2, wn = wid & 3;
    #pragma unroll
    for (int mt = 0; mt < 4; mt++) {
        const int r = wm * 64 + mt * 16 + (lane >> 2);
        #pragma unroll
        for (int nt = 0; nt < 4; nt++) {
            const int c = ntile * 128 + wn * 32 + nt * 8 + (lane & 3) * 2;
            float* base = g_part + ((size_t)ks * M2 + r) * Ntot + c;
            *(float2*)base = make_float2(acc[mt][nt][0], acc[mt][nt][1]);
            *(float2*)(base + (size_t)8 * Ntot) = make_float2(acc[mt][nt][2], acc[mt][nt][3]);
        }
    }
}

__global__ __launch_bounds__(256)
void k_rec(const float* __restrict__ bur0, const float* __restrict__ buf0,
           const float* __restrict__ buh0)
{
    extern __shared__ __align__(128) char dsm[];
    const uint32_t sb = s2u(dsm);
    const int cta = blockIdx.x, tid = threadIdx.x;
    unsigned nbar = 0;

    for (int t = 0; t < T_STEPS; t++) {
        // ========== p0: [r|f]0 = ha @ [Ur0|Uf0].T (split-K 8, K=128) ==========
        {
            const int ntile = cta & 15, ks = cta >> 4, koff = ks * 128;
            const bf16* BH = (ntile < 8) ? g_Ur0H : g_Uf0H;
            const bf16* BL = (ntile < 8) ? g_Ur0L : g_Uf0L;
            const size_t wo = (size_t)((ntile & 7) * 128) * HID + koff;
            float acc[4][4][4] = {};
            mma_gemm128(g_haH + koff, g_haL + koff, BH + wo, BL + wo, 2, acc, sb);
            stpart_mma(acc, ks, ntile, 2048);
        }
        grpbar(cta & 15, cta >> 3, (unsigned)(t * 8 + 8));
        // ---- p0 reduce + sigmoid (slice n = cta*16) ----
        {
            const int m = tid >> 1, b = m & (BATCH - 1);
            const int n = cta * 16 + (tid & 1) * 8;
            float4 s0 = {0,0,0,0}, s1 = {0,0,0,0};
            #pragma unroll
            for (int ks = 0; ks < 8; ks++) {
                const float* p = g_part + ((size_t)ks * M2 + m) * 2048 + n;
                float4 v0 = __ldcg((const float4*)p), v1 = __ldcg((const float4*)(p + 4));
                s0.x += v0.x; s0.y += v0.y; s0.z += v0.z; s0.w += v0.w;
                s1.x += v1.x; s1.y += v1.y; s1.z += v1.z; s1.w += v1.w;
            }
            const int seg = n >> 10, nn = n & 1023;
            const float* bias = seg ? buf0 : bur0;
            float v[8] = {s0.x, s0.y, s0.z, s0.w, s1.x, s1.y, s1.z, s1.w};
            #pragma unroll
            for (int c = 0; c < 8; c++) {
                const float xadd = __ldg(g_xpre + ((size_t)t * BATCH + b) * (3 * HID) + n + c);
                const float g = sigm(v[c] + __ldg(bias + nn + c) + xadd);
                const int idx = m * HID + nn + c;
                if (seg == 0) {
                    const float rh = g * __ldcg(g_ha + idx);
                    wsplit(g_rhH, g_rhL, idx, rh);
                } else {
                    g_f[idx] = g;
                }
            }
        }
        gbar(++nbar);
        // ========== p1: hw0 = rh @ Uh0.T (split-K 16, K=64) ==========
        {
            const int ntile = cta & 7, ks = cta >> 3, koff = ks * 64;
            const size_t wo = (size_t)(ntile * 128) * HID + koff;
            float acc[4][4][4] = {};
            mma_gemm128(g_rhH + koff, g_rhL + koff, g_Uh0H + wo, g_Uh0L + wo, 1, acc, sb);
            stpart_mma(acc, ks, ntile, 1024);
        }
        grpbar(16 + (cta & 7), 16 + (cta >> 4), (unsigned)(t * 16 + 16));
        // ---- p1 reduce + tanh + h update (slice n = cta*8) ----
        {
            const int m = tid >> 1, b = m & (BATCH - 1);
            const int n = cta * 8 + (tid & 1) * 4;
            float4 s = {0,0,0,0};
            #pragma unroll
            for (int ks = 0; ks < 16; ks++) {
                float4 v = __ldcg((const float4*)(g_part + ((size_t)ks * M2 + m) * 1024 + n));
                s.x += v.x; s.y += v.y; s.z += v.z; s.w += v.w;
            }
            float v[4] = {s.x, s.y, s.z, s.w};
            #pragma unroll
            for (int c = 0; c < 4; c++) {
                const float xadd = __ldg(g_xpre + ((size_t)t * BATCH + b) * (3 * HID) + 2 * HID + n + c);
                const float hw = tanhf(v[c] + __ldg(buh0 + n + c) + xadd);
                const int idx = m * HID + n + c;
                const float h = __ldcg(g_ha + idx), f = __ldcg(g_f + idx);
                const float nh = h + f * (hw - h);
                g_hb[idx] = nh;
                wsplit(g_hbH, g_hbL, idx, nh);
            }
        }
        gbar(++nbar);
        // ========== p2: [r|f]1 = hb @ [WUr1|WUf1].T (split-K 8, K=128) ==========
        {
            const int ntile = cta & 15, ks = cta >> 4, koff = ks * 128;
            const bf16* BH = (ntile < 8) ? g_WUr1H : g_WUf1H;
            const bf16* BL = (ntile < 8) ? g_WUr1L : g_WUf1L;
            const size_t wo = (size_t)((ntile & 7) * 128) * HID + koff;
            float acc[4][4][4] = {};
            mma_gemm128(g_hbH + koff, g_hbL + koff, BH + wo, BL + wo, 2, acc, sb);
            stpart_mma(acc, ks, ntile, 2048);
        }
        grpbar(32 + (cta & 15), 32 + (cta >> 3), (unsigned)(t * 8 + 8));
        // ---- p2 reduce + sigmoid ----
        {
            const int m = tid >> 1;
            const int n = cta * 16 + (tid & 1) * 8;
            float4 s0 = {0,0,0,0}, s1 = {0,0,0,0};
            #pragma unroll
            for (int ks = 0; ks < 8; ks++) {
                const float* p = g_part + ((size_t)ks * M2 + m) * 2048 + n;
                float4 v0 = __ldcg((const float4*)p), v1 = __ldcg((const float4*)(p + 4));
                s0.x += v0.x; s0.y += v0.y; s0.z += v0.z; s0.w += v0.w;
                s1.x += v1.x; s1.y += v1.y; s1.z += v1.z; s1.w += v1.w;
            }
            const int seg = n >> 10, nn = n & 1023;
            float v[8] = {s0.x, s0.y, s0.z, s0.w, s1.x, s1.y, s1.z, s1.w};
            #pragma unroll
            for (int c = 0; c < 8; c++) {
                const int idx = m * HID + nn + c;
                if (seg == 0) {
                    const float r = sigm(v[c] + g_brc[nn + c]);
                    wsplit(g_rhH, g_rhL, idx, r * __ldcg(g_hb + idx));
                } else {
                    g_f[idx] = sigm(v[c] + g_bfc[nn + c]);
                }
            }
        }
        gbar(++nbar);
        // ========== p3: hw1 = hb @ Wh1.T + rh @ Uh1.T (virtual K=2048, split 16) ==========
        {
            const int ntile = cta & 7, ks = cta >> 3;
            float acc[4][4][4] = {};
            if (ks < 8) {
                const int koff = ks * 128;
                const size_t wo = (size_t)(ntile * 128) * HID + koff;
                mma_gemm128(g_hbH + koff, g_hbL + koff, g_Wh1H + wo, g_Wh1L + wo, 2, acc, sb);
            } else {
                const int koff = (ks - 8) * 128;
                const size_t wo = (size_t)(ntile * 128) * HID + koff;
                mma_gemm128(g_rhH + koff, g_rhL + koff, g_Uh1H + wo, g_Uh1L + wo, 2, acc, sb);
            }
            stpart_mma(acc, ks, ntile, 1024);
        }
        grpbar(48 + (cta & 7), 48 + (cta >> 4), (unsigned)(t * 16 + 16));
        // ---- p3 reduce + tanh + h update + h1 stash ----
        {
            const int m = tid >> 1;
            const int n = cta * 8 + (tid & 1) * 4;
            float4 s = {0,0,0,0};
            #pragma unroll
            for (int ks = 0; ks < 16; ks++) {
                float4 v = __ldcg((const float4*)(g_part + ((size_t)ks * M2 + m) * 1024 + n));
                s.x += v.x; s.y += v.y; s.z += v.z; s.w += v.w;
            }
            float v[4] = {s.x, s.y, s.z, s.w};
            #pragma unroll
            for (int c = 0; c < 4; c++) {
                const float hw = tanhf(v[c] + g_bhc[n + c]);
                const int idx = m * HID + n + c;
                const float h = __ldcg(g_hb + idx), f = __ldcg(g_f + idx);
                const float nh = h + f * (hw - h);
                g_ha[idx] = nh;
                wsplit(g_haH, g_haL, idx, nh);
                if (m >= BATCH) {
                    const size_t o = ((size_t)t * BATCH + (m - BATCH)) * HID + n + c;
                    wsplit(g_h1H, g_h1L, o, nh);
                }
            }
        }
        if (t != T_STEPS - 1) gbar(++nbar);
    }

    // drain + reset all coordination state for the next graph replay
    __threadfence();
    __syncthreads();
    if (tid == 0) atomicAdd(&g_bar2, 1u);
    if (cta == 0) {
        if (tid == 0) {
            while (*(volatile unsigned*)&g_bar2 < (unsigned)REC_CTAS) __nanosleep(8);
        }
        __syncthreads();
        if (tid < 64) g_cnt[tid] = 0;
        if (tid == 0) { g_bar = 0; g_bar2 = 0; }
        __threadfence();
    }
}

// ---------------- setup kernels ----------------
__global__ void k_hinit(const float* __restrict__ hidden) {
    int i = blockIdx.x * blockDim.x + threadIdx.x;
    if (i < M2 * HID) {
        const float v = hidden[i];
        g_ha[i] = v;
        wsplit(g_haH, g_haL, i, v);
    }
}
__global__ void k_hout(float* __restrict__ out) {
    int i = blockIdx.x * blockDim.x + threadIdx.x;
    if (i < M2 * HID) out[i] = g_ha[i];
}
__global__ void k_addb(const float* __restrict__ br1, const float* __restrict__ bur1,
                       const float* __restrict__ bf1, const float* __restrict__ buf1,
                       const float* __restrict__ bh1, const float* __restrict__ buh1) {
    int i = blockIdx.x * blockDim.x + threadIdx.x;
    if (i < HID) {
        g_brc[i] = br1[i] + bur1[i];
        g_bfc[i] = bf1[i] + buf1[i];
        g_bhc[i] = bh1[i] + buh1[i];
    }
}

__device__ __forceinline__ void split4(float4 v, bf16* H, bf16* L, size_t j) {
    const bf16 h0 = __float2bfloat16(v.x), h1 = __float2bfloat16(v.y);
    const bf16 h2 = __float2bfloat16(v.z), h3 = __float2bfloat16(v.w);
    ushort4 hv = { __bfloat16_as_ushort(h0), __bfloat16_as_ushort(h1),
                   __bfloat16_as_ushort(h2), __bfloat16_as_ushort(h3) };
    ((ushort4*)H)[j] = hv;
    ushort4 lv = { __bfloat16_as_ushort(__float2bfloat16(v.x - __bfloat162float(h0))),
                   __bfloat16_as_ushort(__float2bfloat16(v.y - __bfloat162float(h1))),
                   __bfloat16_as_ushort(__float2bfloat16(v.z - __bfloat162float(h2))),
                   __bfloat16_as_ushort(__float2bfloat16(v.w - __bfloat162float(h3))) };
    ((ushort4*)L)[j] = lv;
}

// One launch splits all 10 recurrence/pre weight matrices (grid.y selects).
__global__ void k_splitall(const float* __restrict__ Wr, const float* __restrict__ Wf,
                           const float* __restrict__ Wh, const float* __restrict__ Ur,
                           const float* __restrict__ Ufw, const float* __restrict__ Uh)
{
    const size_t HH = (size_t)HID * HID;
    const float *src, *src2 = nullptr;
    bf16 *H, *L;
    switch (blockIdx.y) {
        case 0: src = Ur;       H = g_Ur0H;  L = g_Ur0L;  break;
        case 1: src = Ufw;      H = g_Uf0H;  L = g_Uf0L;  break;
        case 2: src = Uh;       H = g_Uh0H;  L = g_Uh0L;  break;
        case 3: src = Wh + HH;  H = g_Wh1H;  L = g_Wh1L;  break;
        case 4: src = Uh + HH;  H = g_Uh1H;  L = g_Uh1L;  break;
        case 5: src = Wr;       H = g_Wr0H;  L = g_Wr0L;  break;
        case 6: src = Wf;       H = g_Wf0H;  L = g_Wf0L;  break;
        case 7: src = Wh;       H = g_Wh0H;  L = g_Wh0L;  break;
        case 8: src = Wr + HH;  src2 = Ur + HH;  H = g_WUr1H; L = g_WUr1L; break;
        default:src = Wf + HH;  src2 = Ufw + HH; H = g_WUf1H; L = g_WUf1L; break;
    }
    const size_t n4 = HH / 4;
    for (size_t j = (size_t)blockIdx.x * blockDim.x + threadIdx.x; j < n4;
         j += (size_t)gridDim.x * blockDim.x) {
        float4 v = __ldg((const float4*)src + j);
        if (src2) {
            float4 v2 = __ldg((const float4*)src2 + j);
            v.x += v2.x; v.y += v2.y; v.z += v2.z; v.w += v2.w;
        }
        split4(v, H, L, j);
    }
}

__global__ void k_splitW(const float* __restrict__ W) {
    const size_t n4 = (size_t)VOC * HID / 4;
    for (size_t j = (size_t)blockIdx.x * blockDim.x + threadIdx.x; j < n4;
         j += (size_t)gridDim.x * blockDim.x)
        split4(__ldg((const float4*)W + j), g_WdH, g_WdL, j);
}
__global__ void k_gather(const int* __restrict__ tokens, const float* __restrict__ emb) {
    const size_t n4 = (size_t)TB * HID / 4;
    for (size_t j = (size_t)blockIdx.x * blockDim.x + threadIdx.x; j < n4;
         j += (size_t)gridDim.x * blockDim.x) {
        const int row = (int)(j >> 8);
        const int c4  = (int)(j & 255);
        const int tok = __ldg(tokens + row);
        split4(__ldg((const float4*)(emb + (size_t)tok * HID) + c4), g_xeH, g_xeL, j);
    }
}

// ---------------- pre: xpre = xemb @ [Wr0|Wf0|Wh0].T + bias (bf16x3 mma) ----------------
__global__ __launch_bounds__(256)
void k_pre_mma(const float* __restrict__ b0, const float* __restrict__ b1,
               const float* __restrict__ b2)
{
    extern __shared__ __align__(128) char dsm[];
    const uint32_t sb = s2u(dsm);
    const int lane = threadIdx.x & 31, wid = threadIdx.x >> 5;
    const int wm = wid >> 2, wn = wid & 3;
    const int m0 = blockIdx.x * 128, n0g = blockIdx.y * 128;
    const int seg = n0g >> 10, nn0 = n0g & 1023;

    const bf16* BH = (seg == 0) ? g_Wr0H : (seg == 1) ? g_Wf0H : g_Wh0H;
    const bf16* BL = (seg == 0) ? g_Wr0L : (seg == 1) ? g_Wf0L : g_Wh0L;
    const float* bias = (seg == 0) ? b0 : (seg == 1) ? b1 : b2;

    float acc[4][4][4] = {};
    mma_k1024(g_xeH + (size_t)m0 * HID, g_xeL + (size_t)m0 * HID,
              BH + (size_t)nn0 * HID, BL + (size_t)nn0 * HID, acc, sb);

    #pragma unroll
    for (int mt = 0; mt < 4; mt++) {
        const int r = m0 + wm * 64 + mt * 16 + (lane >> 2);
        #pragma unroll
        for (int nt = 0; nt < 4; nt++) {
            const int cl = wn * 32 + nt * 8 + (lane & 3) * 2;
            const float2 bb = *(const float2*)(bias + nn0 + cl);
            float* d0 = g_xpre + (size_t)r * (3 * HID) + n0g + cl;
            *(float2*)d0 = make_float2(acc[mt][nt][0] + bb.x, acc[mt][nt][1] + bb.y);
            float* d1 = d0 + (size_t)8 * (3 * HID);
            *(float2*)d1 = make_float2(acc[mt][nt][2] + bb.x, acc[mt][nt][3] + bb.y);
        }
    }
}

// ---------------- decoder: logits = h1 @ Wdec.T + bdec (bf16x3 mma) ----------------
__global__ __launch_bounds__(256)
void k_dec_mma(const float* __restrict__ bdec, float* __restrict__ out)
{
    extern __shared__ __align__(128) char dsm[];
    const uint32_t sb = s2u(dsm);
    const int lane = threadIdx.x & 31, wid = threadIdx.x >> 5;
    const int wm = wid >> 2, wn = wid & 3;
    const int m0 = blockIdx.x * 128, n0 = blockIdx.y * 128;

    float acc[4][4][4] = {};
    mma_k1024(g_h1H + (size_t)m0 * HID, g_h1L + (size_t)m0 * HID,
              g_WdH + (size_t)n0 * HID, g_WdL + (size_t)n0 * HID, acc, sb);

    #pragma unroll
    for (int mt = 0; mt < 4; mt++) {
        const int r = m0 + wm * 64 + mt * 16 + (lane >> 2);
        #pragma unroll
        for (int nt = 0; nt < 4; nt++) {
            const int cc = n0 + wn * 32 + nt * 8 + (lane & 3) * 2;
            const float2 bb = *(const float2*)(bdec + cc);
            *(float2*)(out + (size_t)r * VOC + cc) =
                make_float2(acc[mt][nt][0] + bb.x, acc[mt][nt][1] + bb.y);
            *(float2*)(out + (size_t)(r + 8) * VOC + cc) =
                make_float2(acc[mt][nt][2] + bb.x, acc[mt][nt][3] + bb.y);
        }
    }
}

// ---------------- launch ----------------
extern "C" void kernel_launch(void* const* d_in, const int* in_sizes, int n_in,
                              void* d_out, int out_size)
{
    const int*   tokens = (const int*)  d_in[0];
    const float* hidden = (const float*)d_in[1];
    const float* emb    = (const float*)d_in[2];
    const float* Wr     = (const float*)d_in[3];
    const float* br     = (const float*)d_in[4];
    const float* Wf     = (const float*)d_in[5];
    const float* bf     = (const float*)d_in[6];
    const float* Wh     = (const float*)d_in[7];
    const float* bh     = (const float*)d_in[8];
    const float* Ur     = (const float*)d_in[9];
    const float* bur    = (const float*)d_in[10];
    const float* Ufw    = (const float*)d_in[11];
    const float* bufw   = (const float*)d_in[12];
    const float* Uh     = (const float*)d_in[13];
    const float* buh    = (const float*)d_in[14];
    const float* Wdec   = (const float*)d_in[15];
    const float* bdec   = (const float*)d_in[16];
    float* out = (float*)d_out;

    cudaFuncSetAttribute(k_rec,     cudaFuncAttributeMaxDynamicSharedMemorySize, REC_SMEM);
    cudaFuncSetAttribute(k_pre_mma, cudaFuncAttributeMaxDynamicSharedMemorySize, DEC_SMEM);
    cudaFuncSetAttribute(k_dec_mma, cudaFuncAttributeMaxDynamicSharedMemorySize, DEC_SMEM);

    k_hinit<<<(M2*HID + 1023) / 1024, 1024>>>(hidden);
    k_addb<<<4, 256>>>(br + HID, bur + HID, bf + HID, bufw + HID, bh + HID, buh + HID);

    k_splitall<<<dim3(128, 10), 256>>>(Wr, Wf, Wh, Ur, Ufw, Uh);
    k_splitW<<<2048, 256>>>(Wdec);
    k_gather<<<2048, 256>>>(tokens, emb);

    k_pre_mma<<<dim3(TB/128, 3*HID/128), 256, DEC_SMEM>>>(br, bf, bh);

    k_rec<<<REC_CTAS, 256, REC_SMEM>>>(bur, bufw, buh);

    k_dec_mma<<<dim3(TB/128, VOC/128), 256, DEC_SMEM>>>(bdec, out);

    const long long logits_elems = (long long)TB * VOC;
    if ((long long)out_size >= logits_elems + (long long)M2 * HID)
        k_hout<<<(M2*HID + 1023) / 1024, 1024>>>(out + logits_elems);
}